// round 3
// baseline (speedup 1.0000x reference)
#include <cuda_runtime.h>
#include <math.h>

#define BB   8
#define CIN  512
#define COUT 1024
#define PP   2048
#define NH   8
#define DH   128

// Scratch: projected Q/K/V (pre-BN) and folded BN affine params.
__device__ float g_y[3][BB][COUT][PP];     // ~201 MB, [proj][b][o][p]  proj: 0=Q,1=K,2=V
__device__ float g_scale[3][COUT];
__device__ float g_shift[3][COUT];

// ---------------------------------------------------------------------------
// Stage 1: y[proj][b][o][p] = sum_c W[o][c] * x[b][c][p]
// 128x128 tile, K-chunk 8, 256 threads, 8x8 microtile.
// ---------------------------------------------------------------------------
__global__ __launch_bounds__(256) void gemm_qkv_kernel(
    const float* __restrict__ x,
    const float* __restrict__ Wq,
    const float* __restrict__ Wk,
    const float* __restrict__ Wv)
{
    int z = blockIdx.z;
    int proj = z >> 3, b = z & 7;
    const float* W = (proj == 0) ? Wq : ((proj == 1) ? Wk : Wv);
    const float* X = x + (size_t)b * CIN * PP;
    float* Y = &g_y[proj][b][0][0];

    __shared__ float As[8][128];   // [k][o]
    __shared__ float Bs[8][128];   // [k][p]

    int tid = threadIdx.x;
    int tx = tid & 15, ty = tid >> 4;
    int o0 = blockIdx.y * 128;
    int p0 = blockIdx.x * 128;

    float acc[8][8];
#pragma unroll
    for (int i = 0; i < 8; i++)
#pragma unroll
        for (int j = 0; j < 8; j++) acc[i][j] = 0.f;

    int a_row = tid >> 1;           // 0..127
    int a_col = (tid & 1) * 4;      // 0 or 4
    int b_row = tid >> 5;           // 0..7
    int b_col = (tid & 31) * 4;     // 0..124

    for (int kk = 0; kk < CIN; kk += 8) {
        float4 av = *(const float4*)&W[(size_t)(o0 + a_row) * CIN + kk + a_col];
        As[a_col + 0][a_row] = av.x;
        As[a_col + 1][a_row] = av.y;
        As[a_col + 2][a_row] = av.z;
        As[a_col + 3][a_row] = av.w;
        float4 bv = *(const float4*)&X[(size_t)(kk + b_row) * PP + p0 + b_col];
        *(float4*)&Bs[b_row][b_col] = bv;
        __syncthreads();
#pragma unroll
        for (int k = 0; k < 8; k++) {
            float4 t0 = *(float4*)&As[k][ty * 4];
            float4 t1 = *(float4*)&As[k][64 + ty * 4];
            float4 u0 = *(float4*)&Bs[k][tx * 4];
            float4 u1 = *(float4*)&Bs[k][64 + tx * 4];
            float a[8] = {t0.x, t0.y, t0.z, t0.w, t1.x, t1.y, t1.z, t1.w};
            float bb[8] = {u0.x, u0.y, u0.z, u0.w, u1.x, u1.y, u1.z, u1.w};
#pragma unroll
            for (int i = 0; i < 8; i++)
#pragma unroll
                for (int j = 0; j < 8; j++) acc[i][j] += a[i] * bb[j];
        }
        __syncthreads();
    }
#pragma unroll
    for (int i = 0; i < 8; i++) {
        int o = o0 + ((i < 4) ? (ty * 4 + i) : (64 + ty * 4 + (i - 4)));
        float* yr = &Y[(size_t)o * PP + p0];
        *(float4*)&yr[tx * 4]      = make_float4(acc[i][0], acc[i][1], acc[i][2], acc[i][3]);
        *(float4*)&yr[64 + tx * 4] = make_float4(acc[i][4], acc[i][5], acc[i][6], acc[i][7]);
    }
}

// ---------------------------------------------------------------------------
// Stage 2: per-channel batch stats over (b, p) -> folded affine scale/shift.
// One block per (channel, proj).
// ---------------------------------------------------------------------------
__global__ __launch_bounds__(256) void stats_kernel(
    const float* __restrict__ gq, const float* __restrict__ bq,
    const float* __restrict__ gk, const float* __restrict__ bk,
    const float* __restrict__ gv, const float* __restrict__ bv)
{
    int o = blockIdx.x;
    int proj = blockIdx.y;
    const float* base = &g_y[proj][0][o][0];
    float s = 0.f, s2 = 0.f;
    for (int t = threadIdx.x; t < BB * PP; t += 256) {
        int b = t >> 11, p = t & 2047;
        float v = base[(size_t)b * COUT * PP + p];
        s += v; s2 += v * v;
    }
    __shared__ float red0[256];
    __shared__ float red1[256];
    red0[threadIdx.x] = s; red1[threadIdx.x] = s2;
    __syncthreads();
    for (int st = 128; st > 0; st >>= 1) {
        if (threadIdx.x < st) {
            red0[threadIdx.x] += red0[threadIdx.x + st];
            red1[threadIdx.x] += red1[threadIdx.x + st];
        }
        __syncthreads();
    }
    if (threadIdx.x == 0) {
        const float invn = 1.f / (BB * PP);
        float mean = red0[0] * invn;
        float var  = red1[0] * invn - mean * mean;
        const float* g  = (proj == 0) ? gq : ((proj == 1) ? gk : gv);
        const float* be = (proj == 0) ? bq : ((proj == 1) ? bk : bv);
        float sc = g[o] * rsqrtf(var + 1e-5f);
        g_scale[proj][o] = sc;
        g_shift[proj][o] = be[o] - mean * sc;
    }
}

// ---------------------------------------------------------------------------
// Stage 3: fused flash-style attention per (b, h, i-tile of 64).
//   S[i][j] = sum_c K[c][i] V[c][j] / sqrt(128);  P = online-softmax rows
//   O[c][i] += P[i][j] Q[c][j];  out = O / l
// BN+LeakyReLU applied on the fly at tile loads.
// ---------------------------------------------------------------------------
#define QS_STRIDE 132
#define PS_STRIDE 65
#define ATTN_SMEM ((128*64*2 + 64*QS_STRIDE + 64*PS_STRIDE + 128) * 4)

__global__ __launch_bounds__(256) void attn_kernel(float* __restrict__ out)
{
    extern __shared__ float sm[];
    float* Ks   = sm;                        // [128][64]  (c-major)
    float* Vs   = Ks + 128 * 64;             // [128][64]
    float* Qs   = Vs + 128 * 64;             // [64][QS_STRIDE]  (j-major)
    float* Ps   = Qs + 64 * QS_STRIDE;       // [64][PS_STRIDE]  Ps[j][i]
    float* frow = Ps + 64 * PS_STRIDE;       // [64]
    float* lrow = frow + 64;                 // [64]

    int tid = threadIdx.x;
    int bh = blockIdx.y;
    int b = bh >> 3, h = bh & 7;
    int i0 = blockIdx.x * 64;
    int ch0 = h * DH;

    const float* Qy = &g_y[0][b][ch0][0];
    const float* Ky = &g_y[1][b][ch0][0];
    const float* Vy = &g_y[2][b][ch0][0];

    // Load K tile (BN + LeakyReLU folded)
    for (int t = tid; t < 128 * 64; t += 256) {
        int c = t >> 6, ii = t & 63;
        float v = Ky[(size_t)c * PP + i0 + ii];
        v = v * g_scale[1][ch0 + c] + g_shift[1][ch0 + c];
        Ks[t] = (v >= 0.f) ? v : 0.1f * v;
    }

    int tx = tid & 15;   // mapping1: j block (4*tx)
    int ty = tid >> 4;   // mapping1: i block (4*ty)
    int it2 = tid & 15;  // mapping2: i block (4*it2)
    int ct  = tid >> 4;  // mapping2: c block (8*ct)

    float m[4], l[4];
#pragma unroll
    for (int r = 0; r < 4; r++) { m[r] = -1e30f; l[r] = 0.f; }

    float O[8][4];
#pragma unroll
    for (int a = 0; a < 8; a++)
#pragma unroll
        for (int r = 0; r < 4; r++) O[a][r] = 0.f;

    const float inv_sqrt_dh = 0.08838834764831845f;

    for (int j0 = 0; j0 < PP; j0 += 64) {
        __syncthreads();   // prev GEMM2 / K load complete before overwriting Vs,Qs
        for (int t = tid; t < 128 * 64; t += 256) {
            int c = t >> 6, jj = t & 63;
            float v = Vy[(size_t)c * PP + j0 + jj];
            v = v * g_scale[2][ch0 + c] + g_shift[2][ch0 + c];
            Vs[t] = (v >= 0.f) ? v : 0.1f * v;
            float q = Qy[(size_t)c * PP + j0 + jj];
            q = q * g_scale[0][ch0 + c] + g_shift[0][ch0 + c];
            Qs[jj * QS_STRIDE + c] = (q >= 0.f) ? q : 0.1f * q;
        }
        __syncthreads();

        // --- S = K_i^T V_j (64x64x128) ---
        float s[4][4];
#pragma unroll
        for (int r = 0; r < 4; r++)
#pragma unroll
            for (int q = 0; q < 4; q++) s[r][q] = 0.f;

#pragma unroll 4
        for (int c = 0; c < 128; c++) {
            float4 kv = *(float4*)&Ks[c * 64 + 4 * ty];
            float4 vv = *(float4*)&Vs[c * 64 + 4 * tx];
            s[0][0] += kv.x * vv.x; s[0][1] += kv.x * vv.y; s[0][2] += kv.x * vv.z; s[0][3] += kv.x * vv.w;
            s[1][0] += kv.y * vv.x; s[1][1] += kv.y * vv.y; s[1][2] += kv.y * vv.z; s[1][3] += kv.y * vv.w;
            s[2][0] += kv.z * vv.x; s[2][1] += kv.z * vv.y; s[2][2] += kv.z * vv.z; s[2][3] += kv.z * vv.w;
            s[3][0] += kv.w * vv.x; s[3][1] += kv.w * vv.y; s[3][2] += kv.w * vv.z; s[3][3] += kv.w * vv.w;
        }

        // --- online softmax over rows (16-lane groups share a row set) ---
#pragma unroll
        for (int r = 0; r < 4; r++) {
#pragma unroll
            for (int q = 0; q < 4; q++) s[r][q] *= inv_sqrt_dh;
            float rm = fmaxf(fmaxf(s[r][0], s[r][1]), fmaxf(s[r][2], s[r][3]));
            rm = fmaxf(rm, __shfl_xor_sync(0xffffffffu, rm, 1));
            rm = fmaxf(rm, __shfl_xor_sync(0xffffffffu, rm, 2));
            rm = fmaxf(rm, __shfl_xor_sync(0xffffffffu, rm, 4));
            rm = fmaxf(rm, __shfl_xor_sync(0xffffffffu, rm, 8));
            float mnew = fmaxf(m[r], rm);
            float f = __expf(m[r] - mnew);
            float rs = 0.f;
#pragma unroll
            for (int q = 0; q < 4; q++) {
                float pv = __expf(s[r][q] - mnew);
                Ps[(4 * tx + q) * PS_STRIDE + 4 * ty + r] = pv;
                rs += pv;
            }
            rs += __shfl_xor_sync(0xffffffffu, rs, 1);
            rs += __shfl_xor_sync(0xffffffffu, rs, 2);
            rs += __shfl_xor_sync(0xffffffffu, rs, 4);
            rs += __shfl_xor_sync(0xffffffffu, rs, 8);
            l[r] = l[r] * f + rs;
            m[r] = mnew;
            if (tx == 0) frow[4 * ty + r] = f;
        }
        __syncthreads();

        // --- O = O*f + Q_j * P^T  (128x64 x 64) ---
        float f2[4];
#pragma unroll
        for (int r = 0; r < 4; r++) f2[r] = frow[4 * it2 + r];
#pragma unroll
        for (int a = 0; a < 8; a++)
#pragma unroll
            for (int r = 0; r < 4; r++) O[a][r] *= f2[r];

#pragma unroll 2
        for (int j = 0; j < 64; j++) {
            float p4[4];
#pragma unroll
            for (int r = 0; r < 4; r++) p4[r] = Ps[j * PS_STRIDE + 4 * it2 + r];
            float4 qa = *(float4*)&Qs[j * QS_STRIDE + 8 * ct];
            float4 qb = *(float4*)&Qs[j * QS_STRIDE + 8 * ct + 4];
            float q8[8] = {qa.x, qa.y, qa.z, qa.w, qb.x, qb.y, qb.z, qb.w};
#pragma unroll
            for (int a = 0; a < 8; a++)
#pragma unroll
                for (int r = 0; r < 4; r++) O[a][r] += q8[a] * p4[r];
        }
    }

    // --- finalize: divide by l, write out[b][ch0+c][i0+i] ---
    if (tx == 0) {
#pragma unroll
        for (int r = 0; r < 4; r++) lrow[4 * ty + r] = l[r];
    }
    __syncthreads();
    float inv[4];
#pragma unroll
    for (int r = 0; r < 4; r++) inv[r] = 1.f / lrow[4 * it2 + r];
#pragma unroll
    for (int a = 0; a < 8; a++) {
        int ch = ch0 + 8 * ct + a;
        float* op = &out[((size_t)b * COUT + ch) * PP + i0 + 4 * it2];
        *(float4*)op = make_float4(O[a][0] * inv[0], O[a][1] * inv[1],
                                   O[a][2] * inv[2], O[a][3] * inv[3]);
    }
}

// ---------------------------------------------------------------------------
extern "C" void kernel_launch(void* const* d_in, const int* in_sizes, int n_in,
                              void* d_out, int out_size)
{
    const float* x  = (const float*)d_in[0];
    const float* Wq = (const float*)d_in[1];
    const float* gq = (const float*)d_in[2];
    const float* bq = (const float*)d_in[3];
    const float* Wk = (const float*)d_in[4];
    const float* gk = (const float*)d_in[5];
    const float* bk = (const float*)d_in[6];
    const float* Wv = (const float*)d_in[7];
    const float* gv = (const float*)d_in[8];
    const float* bv = (const float*)d_in[9];
    float* out = (float*)d_out;

    gemm_qkv_kernel<<<dim3(PP / 128, COUT / 128, 3 * BB), 256>>>(x, Wq, Wk, Wv);
    stats_kernel<<<dim3(COUT, 3), 256>>>(gq, bq, gk, bk, gv, bv);

    cudaFuncSetAttribute(attn_kernel, cudaFuncAttributeMaxDynamicSharedMemorySize, ATTN_SMEM);
    attn_kernel<<<dim3(PP / 64, BB * NH), 256, ATTN_SMEM>>>(out);
}

// round 4
// speedup vs baseline: 3.5021x; 3.5021x over previous
#include <cuda_runtime.h>
#include <cuda_bf16.h>
#include <math.h>

#define BB 8
#define CIN 512
#define COUT 1024
#define PP 2048
#define NH 8
#define DH 128

// ---------------- scratch (device globals; no allocations) ----------------
__device__ float    g_y[3][BB][COUT][PP];       // fp32 projections (pre-BN)
__device__ float    g_scale[3][COUT];
__device__ float    g_shift[3][COUT];
__device__ unsigned g_Whi[3][COUT][CIN/2];      // W split bf16 pairs along c
__device__ unsigned g_Wlo[3][COUT][CIN/2];
__device__ unsigned g_XThi[BB][PP][CIN/2];      // x^T split pairs along c
__device__ unsigned g_XTlo[BB][PP][CIN/2];
__device__ unsigned g_Qhi[BB][COUT][PP/2];      // Q (post-BN) pairs along p
__device__ unsigned g_Qlo[BB][COUT][PP/2];
__device__ unsigned g_KThi[BB][NH][PP][DH/2];   // K^T per head, pairs along c
__device__ unsigned g_KTlo[BB][NH][PP][DH/2];
__device__ unsigned g_VThi[BB][NH][PP][DH/2];   // V^T per head, pairs along c
__device__ unsigned g_VTlo[BB][NH][PP][DH/2];

// ---------------- helpers ----------------
__device__ __forceinline__ unsigned pack_bf16(float a, float b) {
    __nv_bfloat162 t = __floats2bfloat162_rn(a, b);   // .x = a (low 16 bits)
    return *(unsigned*)&t;
}
__device__ __forceinline__ void split2(float x0, float x1, unsigned& hi, unsigned& lo) {
    __nv_bfloat16 h0 = __float2bfloat16(x0);
    __nv_bfloat16 h1 = __float2bfloat16(x1);
    float r0 = x0 - __bfloat162float(h0);
    float r1 = x1 - __bfloat162float(h1);
    __nv_bfloat162 hp; hp.x = h0; hp.y = h1;
    hi = *(unsigned*)&hp;
    lo = pack_bf16(r0, r1);
}
__device__ __forceinline__ void mma16816(float* c,
    unsigned a0, unsigned a1, unsigned a2, unsigned a3, unsigned b0, unsigned b1)
{
    asm volatile(
        "mma.sync.aligned.m16n8k16.row.col.f32.bf16.bf16.f32 "
        "{%0,%1,%2,%3}, {%4,%5,%6,%7}, {%8,%9}, {%0,%1,%2,%3};\n"
        : "+f"(c[0]), "+f"(c[1]), "+f"(c[2]), "+f"(c[3])
        : "r"(a0), "r"(a1), "r"(a2), "r"(a3), "r"(b0), "r"(b1));
}

// ---------------- conv W -> split bf16 pairs ----------------
__global__ __launch_bounds__(256) void conv_w_kernel(
    const float* __restrict__ Wq, const float* __restrict__ Wk, const float* __restrict__ Wv)
{
    int idx = blockIdx.x * 256 + threadIdx.x;       // 3*1024*256 pairs
    int proj = idx >> 18;
    int rem = idx & 262143;
    const float* W = (proj == 0) ? Wq : ((proj == 1) ? Wk : Wv);
    float2 v = *(const float2*)(W + (size_t)rem * 2);
    unsigned hi, lo;
    split2(v.x, v.y, hi, lo);
    (&g_Whi[0][0][0])[(size_t)proj * 262144 + rem] = hi;
    (&g_Wlo[0][0][0])[(size_t)proj * 262144 + rem] = lo;
}

// ---------------- conv x -> x^T split pairs (transpose via smem) -----------
__global__ __launch_bounds__(256) void conv_x_kernel(const float* __restrict__ x)
{
    __shared__ float sm[64][65];
    int p0 = blockIdx.x * 64, c0 = blockIdx.y * 64, b = blockIdx.z;
    int tid = threadIdx.x;
    for (int t = tid; t < 64 * 64; t += 256) {
        int c = t >> 6, p = t & 63;
        sm[c][p] = x[((size_t)b * CIN + c0 + c) * PP + p0 + p];
    }
    __syncthreads();
    for (int t = tid; t < 64 * 32; t += 256) {
        int p = t >> 5, cp = t & 31;
        unsigned hi, lo;
        split2(sm[2 * cp][p], sm[2 * cp + 1][p], hi, lo);
        size_t o = ((size_t)b * PP + p0 + p) * 256 + (c0 >> 1) + cp;
        (&g_XThi[0][0][0])[o] = hi;
        (&g_XTlo[0][0][0])[o] = lo;
    }
}

// ---------------- Stage 1: tensor GEMM  y = W * x ----------------
#define G1_STR 20
__global__ __launch_bounds__(256) void gemm1_mma_kernel()
{
    __shared__ unsigned Ah[128 * G1_STR], Al[128 * G1_STR];
    __shared__ unsigned Bh[128 * G1_STR], Bl[128 * G1_STR];
    int z = blockIdx.z, proj = z >> 3, b = z & 7;
    int o0 = blockIdx.y * 128, p0 = blockIdx.x * 128;
    const unsigned* gWh = &g_Whi[proj][0][0];
    const unsigned* gWl = &g_Wlo[proj][0][0];
    const unsigned* gXh = &g_XThi[b][0][0];
    const unsigned* gXl = &g_XTlo[b][0][0];
    int tid = threadIdx.x, w = tid >> 5, lane = tid & 31;
    int g = lane >> 2, q = lane & 3;
    int wo = w >> 2, wp = w & 3;

    float acc[4][4][4];
#pragma unroll
    for (int i = 0; i < 4; i++)
#pragma unroll
        for (int j = 0; j < 4; j++)
#pragma unroll
            for (int e = 0; e < 4; e++) acc[i][j][e] = 0.f;

    for (int kk = 0; kk < 256; kk += 16) {      // cpair units (32 channels/chunk)
        __syncthreads();
        for (int t = tid; t < 2048; t += 256) {
            int r = t >> 4, cp = t & 15;
            Ah[r * G1_STR + cp] = gWh[(size_t)(o0 + r) * 256 + kk + cp];
            Al[r * G1_STR + cp] = gWl[(size_t)(o0 + r) * 256 + kk + cp];
            Bh[r * G1_STR + cp] = gXh[(size_t)(p0 + r) * 256 + kk + cp];
            Bl[r * G1_STR + cp] = gXl[(size_t)(p0 + r) * 256 + kk + cp];
        }
        __syncthreads();
#pragma unroll
        for (int ks = 0; ks < 2; ks++) {
            int k0 = 8 * ks + q;
            unsigned ah[4][4], al[4][4];
#pragma unroll
            for (int mf = 0; mf < 4; mf++) {
                int r = (wo * 64 + 16 * mf + g) * G1_STR + k0;
                ah[mf][0] = Ah[r];     ah[mf][1] = Ah[r + 8 * G1_STR];
                ah[mf][2] = Ah[r + 4]; ah[mf][3] = Ah[r + 8 * G1_STR + 4];
                al[mf][0] = Al[r];     al[mf][1] = Al[r + 8 * G1_STR];
                al[mf][2] = Al[r + 4]; al[mf][3] = Al[r + 8 * G1_STR + 4];
            }
#pragma unroll
            for (int nf = 0; nf < 4; nf++) {
                int r = (wp * 32 + 8 * nf + g) * G1_STR + k0;
                unsigned bh0 = Bh[r], bh1 = Bh[r + 4];
                unsigned bl0 = Bl[r], bl1 = Bl[r + 4];
#pragma unroll
                for (int mf = 0; mf < 4; mf++) {
                    mma16816(acc[mf][nf], ah[mf][0], ah[mf][1], ah[mf][2], ah[mf][3], bh0, bh1);
                    mma16816(acc[mf][nf], ah[mf][0], ah[mf][1], ah[mf][2], ah[mf][3], bl0, bl1);
                    mma16816(acc[mf][nf], al[mf][0], al[mf][1], al[mf][2], al[mf][3], bh0, bh1);
                }
            }
        }
    }
    float* Y = &g_y[proj][b][0][0];
#pragma unroll
    for (int mf = 0; mf < 4; mf++)
#pragma unroll
        for (int nf = 0; nf < 4; nf++) {
            int oo = o0 + wo * 64 + 16 * mf + g;
            int pp = p0 + wp * 32 + 8 * nf + 2 * q;
            float* r0 = Y + (size_t)oo * PP + pp;
            *(float2*)r0 = make_float2(acc[mf][nf][0], acc[mf][nf][1]);
            *(float2*)(r0 + 8 * PP) = make_float2(acc[mf][nf][2], acc[mf][nf][3]);
        }
}

// ---------------- Stage 2: batch stats -> folded affine ----------------
__global__ __launch_bounds__(256) void stats_kernel(
    const float* __restrict__ gq, const float* __restrict__ bq,
    const float* __restrict__ gk, const float* __restrict__ bk,
    const float* __restrict__ gv, const float* __restrict__ bv)
{
    int o = blockIdx.x, proj = blockIdx.y;
    const float* base = &g_y[proj][0][o][0];
    float s = 0.f, s2 = 0.f;
    for (int t = threadIdx.x; t < BB * PP; t += 256) {
        int b = t >> 11, p = t & 2047;
        float v = base[(size_t)b * COUT * PP + p];
        s += v; s2 += v * v;
    }
    __shared__ float red0[256], red1[256];
    red0[threadIdx.x] = s; red1[threadIdx.x] = s2;
    __syncthreads();
    for (int st = 128; st > 0; st >>= 1) {
        if (threadIdx.x < st) {
            red0[threadIdx.x] += red0[threadIdx.x + st];
            red1[threadIdx.x] += red1[threadIdx.x + st];
        }
        __syncthreads();
    }
    if (threadIdx.x == 0) {
        const float invn = 1.f / (BB * PP);
        float mean = red0[0] * invn;
        float var = red1[0] * invn - mean * mean;
        const float* gg = (proj == 0) ? gq : ((proj == 1) ? gk : gv);
        const float* be = (proj == 0) ? bq : ((proj == 1) ? bk : bv);
        float sc = gg[o] * rsqrtf(var + 1e-5f);
        g_scale[proj][o] = sc;
        g_shift[proj][o] = be[o] - mean * sc;
    }
}

// ---------------- Stage 3: fold BN+LeakyReLU, emit split operands ----------
__global__ __launch_bounds__(256) void fold_kernel()
{
    __shared__ float sm[64][65];
    int p0 = blockIdx.x * 64, c0 = blockIdx.y * 64;
    int z = blockIdx.z, proj = z >> 3, b = z & 7;
    int tid = threadIdx.x;
    for (int t = tid; t < 64 * 64; t += 256) {
        int c = t >> 6, p = t & 63;
        float v = g_y[proj][b][c0 + c][p0 + p];
        v = v * g_scale[proj][c0 + c] + g_shift[proj][c0 + c];
        sm[c][p] = (v >= 0.f) ? v : 0.1f * v;
    }
    __syncthreads();
    if (proj == 0) {
        for (int t = tid; t < 64 * 32; t += 256) {
            int c = t >> 5, jp = t & 31;
            unsigned hi, lo;
            split2(sm[c][2 * jp], sm[c][2 * jp + 1], hi, lo);
            size_t o = ((size_t)b * COUT + c0 + c) * 1024 + (p0 >> 1) + jp;
            (&g_Qhi[0][0][0])[o] = hi;
            (&g_Qlo[0][0][0])[o] = lo;
        }
    } else {
        int h = c0 >> 7, cpo = (c0 & 127) >> 1;
        unsigned* dh = (proj == 1) ? &g_KThi[0][0][0][0] : &g_VThi[0][0][0][0];
        unsigned* dl = (proj == 1) ? &g_KTlo[0][0][0][0] : &g_VTlo[0][0][0][0];
        for (int t = tid; t < 64 * 32; t += 256) {
            int p = t >> 5, cp = t & 31;
            unsigned hi, lo;
            split2(sm[2 * cp][p], sm[2 * cp + 1][p], hi, lo);
            size_t o = ((size_t)(b * NH + h) * PP + p0 + p) * 64 + cpo + cp;
            dh[o] = hi;
            dl[o] = lo;
        }
    }
}

// ---------------- Stage 4: fused tensor-core flash attention ----------------
#define KT_STR 68
#define V_STR  68
#define Q_STR  36
#define P_STR  36
#define ATTN_SMEM_U32 (128*KT_STR*2 + 64*V_STR*2 + 128*Q_STR*2 + 128*P_STR*2 + 256)
#define ATTN_SMEM (ATTN_SMEM_U32 * 4)

__global__ __launch_bounds__(256) void attn_mma_kernel(float* __restrict__ out)
{
    extern __shared__ unsigned sm[];
    unsigned* KTh = sm;
    unsigned* KTl = KTh + 128 * KT_STR;
    unsigned* Vh  = KTl + 128 * KT_STR;
    unsigned* Vl  = Vh + 64 * V_STR;
    unsigned* Qh  = Vl + 64 * V_STR;
    unsigned* Ql  = Qh + 128 * Q_STR;
    unsigned* Ph  = Ql + 128 * Q_STR;
    unsigned* Pl  = Ph + 128 * P_STR;
    float* frow = (float*)(Pl + 128 * P_STR);
    float* lrow = frow + 128;

    const int tid = threadIdx.x;
    const int w = tid >> 5, lane = tid & 31;
    const int g = lane >> 2, q = lane & 3;
    const int bh = blockIdx.y;
    const int b = bh >> 3, h = bh & 7;
    const int i0 = blockIdx.x * 128;

    const unsigned* gKh = &g_KThi[b][h][0][0];
    const unsigned* gKl = &g_KTlo[b][h][0][0];
    const unsigned* gVh = &g_VThi[b][h][0][0];
    const unsigned* gVl = &g_VTlo[b][h][0][0];
    const unsigned* gQh = &g_Qhi[b][h * 128][0];
    const unsigned* gQl = &g_Qlo[b][h * 128][0];

    for (int t = tid; t < 128 * 64; t += 256) {
        int r = t >> 6, cp = t & 63;
        KTh[r * KT_STR + cp] = gKh[(size_t)(i0 + r) * 64 + cp];
        KTl[r * KT_STR + cp] = gKl[(size_t)(i0 + r) * 64 + cp];
    }

    float m0 = -1e30f, m1 = -1e30f, l0 = 0.f, l1 = 0.f;
    float o[8][2][4];
#pragma unroll
    for (int mf = 0; mf < 8; mf++)
#pragma unroll
        for (int nf = 0; nf < 2; nf++)
#pragma unroll
            for (int e = 0; e < 4; e++) o[mf][nf][e] = 0.f;

    const int arow0 = (16 * w + g) * KT_STR;
    const int arow1 = arow0 + 8 * KT_STR;

    for (int j0 = 0; j0 < PP; j0 += 64) {
        __syncthreads();                 // previous iter done with V/Q tiles
        for (int t = tid; t < 64 * 64; t += 256) {
            int r = t >> 6, cp = t & 63;
            Vh[r * V_STR + cp] = gVh[(size_t)(j0 + r) * 64 + cp];
            Vl[r * V_STR + cp] = gVl[(size_t)(j0 + r) * 64 + cp];
        }
        for (int t = tid; t < 128 * 32; t += 256) {
            int r = t >> 5, jp = t & 31;
            Qh[r * Q_STR + jp] = gQh[(size_t)r * 1024 + (j0 >> 1) + jp];
            Ql[r * Q_STR + jp] = gQl[(size_t)r * 1024 + (j0 >> 1) + jp];
        }
        __syncthreads();

        // ---- S = K_i^T V_j : warp w owns rows [16w,16w+16), all 64 j ----
        float sacc[8][4];
#pragma unroll
        for (int nf = 0; nf < 8; nf++)
#pragma unroll
            for (int e = 0; e < 4; e++) sacc[nf][e] = 0.f;

#pragma unroll
        for (int ks = 0; ks < 8; ks++) {
            int k0 = 8 * ks + q;
            unsigned ah0 = KTh[arow0 + k0], ah1 = KTh[arow1 + k0];
            unsigned ah2 = KTh[arow0 + k0 + 4], ah3 = KTh[arow1 + k0 + 4];
            unsigned al0 = KTl[arow0 + k0], al1 = KTl[arow1 + k0];
            unsigned al2 = KTl[arow0 + k0 + 4], al3 = KTl[arow1 + k0 + 4];
#pragma unroll
            for (int nf = 0; nf < 8; nf++) {
                int br = (8 * nf + g) * V_STR + k0;
                unsigned bh0 = Vh[br], bh1 = Vh[br + 4];
                unsigned bl0 = Vl[br], bl1 = Vl[br + 4];
                mma16816(sacc[nf], ah0, ah1, ah2, ah3, bh0, bh1);
                mma16816(sacc[nf], ah0, ah1, ah2, ah3, bl0, bl1);
                mma16816(sacc[nf], al0, al1, al2, al3, bh0, bh1);
            }
        }

        // ---- online softmax (warp-local rows) ----
        const float scl = 0.08838834764831845f;
        float rm0 = -1e30f, rm1 = -1e30f;
#pragma unroll
        for (int nf = 0; nf < 8; nf++) {
            sacc[nf][0] *= scl; sacc[nf][1] *= scl;
            sacc[nf][2] *= scl; sacc[nf][3] *= scl;
            rm0 = fmaxf(rm0, fmaxf(sacc[nf][0], sacc[nf][1]));
            rm1 = fmaxf(rm1, fmaxf(sacc[nf][2], sacc[nf][3]));
        }
        rm0 = fmaxf(rm0, __shfl_xor_sync(0xffffffffu, rm0, 1));
        rm0 = fmaxf(rm0, __shfl_xor_sync(0xffffffffu, rm0, 2));
        rm1 = fmaxf(rm1, __shfl_xor_sync(0xffffffffu, rm1, 1));
        rm1 = fmaxf(rm1, __shfl_xor_sync(0xffffffffu, rm1, 2));
        float mn0 = fmaxf(m0, rm0), mn1 = fmaxf(m1, rm1);
        float f0 = __expf(m0 - mn0), f1 = __expf(m1 - mn1);
        float s0 = 0.f, s1 = 0.f;
        int pr0 = (16 * w + g) * P_STR, pr1 = pr0 + 8 * P_STR;
#pragma unroll
        for (int nf = 0; nf < 8; nf++) {
            float p00 = __expf(sacc[nf][0] - mn0);
            float p01 = __expf(sacc[nf][1] - mn0);
            float p10 = __expf(sacc[nf][2] - mn1);
            float p11 = __expf(sacc[nf][3] - mn1);
            s0 += p00 + p01; s1 += p10 + p11;
            int jp = 4 * nf + q;
            unsigned hi, lo;
            split2(p00, p01, hi, lo);
            Ph[pr0 + jp] = hi; Pl[pr0 + jp] = lo;
            split2(p10, p11, hi, lo);
            Ph[pr1 + jp] = hi; Pl[pr1 + jp] = lo;
        }
        s0 += __shfl_xor_sync(0xffffffffu, s0, 1);
        s0 += __shfl_xor_sync(0xffffffffu, s0, 2);
        s1 += __shfl_xor_sync(0xffffffffu, s1, 1);
        s1 += __shfl_xor_sync(0xffffffffu, s1, 2);
        l0 = l0 * f0 + s0; l1 = l1 * f1 + s1;
        m0 = mn0; m1 = mn1;
        if (q == 0) { frow[16 * w + g] = f0; frow[16 * w + g + 8] = f1; }
        __syncwarp();

        // ---- O rescale + O += Q * P^T (warp w owns cols [16w,16w+16)) ----
        float fA0 = frow[16 * w + 2 * q],     fB0 = frow[16 * w + 2 * q + 1];
        float fA1 = frow[16 * w + 8 + 2 * q], fB1 = frow[16 * w + 8 + 2 * q + 1];
#pragma unroll
        for (int mf = 0; mf < 8; mf++) {
            o[mf][0][0] *= fA0; o[mf][0][1] *= fB0; o[mf][0][2] *= fA0; o[mf][0][3] *= fB0;
            o[mf][1][0] *= fA1; o[mf][1][1] *= fB1; o[mf][1][2] *= fA1; o[mf][1][3] *= fB1;
        }
#pragma unroll
        for (int ks = 0; ks < 4; ks++) {
            int k0 = 8 * ks + q;
            int bn0 = (16 * w + g) * P_STR + k0;
            int bn1 = (16 * w + 8 + g) * P_STR + k0;
            unsigned p0h0 = Ph[bn0], p0h1 = Ph[bn0 + 4];
            unsigned p0l0 = Pl[bn0], p0l1 = Pl[bn0 + 4];
            unsigned p1h0 = Ph[bn1], p1h1 = Ph[bn1 + 4];
            unsigned p1l0 = Pl[bn1], p1l1 = Pl[bn1 + 4];
#pragma unroll
            for (int mf = 0; mf < 8; mf++) {
                int ar0 = (16 * mf + g) * Q_STR + k0;
                int ar1 = ar0 + 8 * Q_STR;
                unsigned qh0 = Qh[ar0], qh1 = Qh[ar1];
                unsigned qh2 = Qh[ar0 + 4], qh3 = Qh[ar1 + 4];
                unsigned ql0 = Ql[ar0], ql1 = Ql[ar1];
                unsigned ql2 = Ql[ar0 + 4], ql3 = Ql[ar1 + 4];
                mma16816(o[mf][0], qh0, qh1, qh2, qh3, p0h0, p0h1);
                mma16816(o[mf][0], ql0, ql1, ql2, ql3, p0h0, p0h1);
                mma16816(o[mf][0], qh0, qh1, qh2, qh3, p0l0, p0l1);
                mma16816(o[mf][1], qh0, qh1, qh2, qh3, p1h0, p1h1);
                mma16816(o[mf][1], ql0, ql1, ql2, ql3, p1h0, p1h1);
                mma16816(o[mf][1], qh0, qh1, qh2, qh3, p1l0, p1l1);
            }
        }
        __syncwarp();
    }

    // ---- finalize ----
    if (q == 0) { lrow[16 * w + g] = l0; lrow[16 * w + g + 8] = l1; }
    __syncwarp();
    float iA0 = 1.f / lrow[16 * w + 2 * q],     iB0 = 1.f / lrow[16 * w + 2 * q + 1];
    float iA1 = 1.f / lrow[16 * w + 8 + 2 * q], iB1 = 1.f / lrow[16 * w + 8 + 2 * q + 1];
#pragma unroll
    for (int mf = 0; mf < 8; mf++) {
        int c = h * 128 + 16 * mf + g;
        float* r0 = out + ((size_t)b * COUT + c) * PP + i0 + 16 * w;
        *(float2*)(r0 + 2 * q)     = make_float2(o[mf][0][0] * iA0, o[mf][0][1] * iB0);
        *(float2*)(r0 + 8 + 2 * q) = make_float2(o[mf][1][0] * iA1, o[mf][1][1] * iB1);
        float* r1 = r0 + 8 * PP;
        *(float2*)(r1 + 2 * q)     = make_float2(o[mf][0][2] * iA0, o[mf][0][3] * iB0);
        *(float2*)(r1 + 8 + 2 * q) = make_float2(o[mf][1][2] * iA1, o[mf][1][3] * iB1);
    }
}

// ---------------------------------------------------------------------------
extern "C" void kernel_launch(void* const* d_in, const int* in_sizes, int n_in,
                              void* d_out, int out_size)
{
    const float* x  = (const float*)d_in[0];
    const float* Wq = (const float*)d_in[1];
    const float* gq = (const float*)d_in[2];
    const float* bq = (const float*)d_in[3];
    const float* Wk = (const float*)d_in[4];
    const float* gk = (const float*)d_in[5];
    const float* bk = (const float*)d_in[6];
    const float* Wv = (const float*)d_in[7];
    const float* gv = (const float*)d_in[8];
    const float* bv = (const float*)d_in[9];
    float* out = (float*)d_out;

    conv_w_kernel<<<3 * COUT * (CIN / 2) / 256, 256>>>(Wq, Wk, Wv);
    conv_x_kernel<<<dim3(PP / 64, CIN / 64, BB), 256>>>(x);
    gemm1_mma_kernel<<<dim3(PP / 128, COUT / 128, 3 * BB), 256>>>();
    stats_kernel<<<dim3(COUT, 3), 256>>>(gq, bq, gk, bk, gv, bv);
    fold_kernel<<<dim3(PP / 64, COUT / 64, 3 * BB), 256>>>();

    cudaFuncSetAttribute(attn_mma_kernel, cudaFuncAttributeMaxDynamicSharedMemorySize, ATTN_SMEM);
    attn_mma_kernel<<<dim3(PP / 128, BB * NH), 256, ATTN_SMEM>>>(out);
}

// round 6
// speedup vs baseline: 4.9270x; 1.4069x over previous
#include <cuda_runtime.h>
#include <cuda_bf16.h>
#include <math.h>
#include <stdint.h>

#define BB 8
#define CIN 512
#define COUT 1024
#define PP 2048
#define NH 8
#define DH 128

// ---------------- scratch (device globals; no allocations) ----------------
__device__ float    g_y[3][BB][COUT][PP];       // fp32 projections (pre-BN)
__device__ float    g_scale[3][COUT];
__device__ float    g_shift[3][COUT];
__device__ unsigned g_Whi[3][COUT][CIN/2];      // W split bf16 pairs along c
__device__ unsigned g_Wlo[3][COUT][CIN/2];
__device__ unsigned g_XThi[BB][PP][CIN/2];      // x^T split pairs along c
__device__ unsigned g_XTlo[BB][PP][CIN/2];
__device__ unsigned g_Qhi[BB][COUT][PP/2];      // Q (post-BN) pairs along p
__device__ unsigned g_Qlo[BB][COUT][PP/2];
__device__ unsigned g_KThi[BB][NH][PP][DH/2];   // K^T per head, pairs along c
__device__ unsigned g_KTlo[BB][NH][PP][DH/2];
__device__ unsigned g_VThi[BB][NH][PP][DH/2];   // V^T per head, pairs along c
__device__ unsigned g_VTlo[BB][NH][PP][DH/2];

// ---------------- helpers ----------------
__device__ __forceinline__ unsigned pack_bf16(float a, float b) {
    __nv_bfloat162 t = __floats2bfloat162_rn(a, b);
    return *(unsigned*)&t;
}
__device__ __forceinline__ void split2(float x0, float x1, unsigned& hi, unsigned& lo) {
    __nv_bfloat16 h0 = __float2bfloat16(x0);
    __nv_bfloat16 h1 = __float2bfloat16(x1);
    float r0 = x0 - __bfloat162float(h0);
    float r1 = x1 - __bfloat162float(h1);
    __nv_bfloat162 hp; hp.x = h0; hp.y = h1;
    hi = *(unsigned*)&hp;
    lo = pack_bf16(r0, r1);
}
__device__ __forceinline__ void mma16816(float* c,
    unsigned a0, unsigned a1, unsigned a2, unsigned a3, unsigned b0, unsigned b1)
{
    asm volatile(
        "mma.sync.aligned.m16n8k16.row.col.f32.bf16.bf16.f32 "
        "{%0,%1,%2,%3}, {%4,%5,%6,%7}, {%8,%9}, {%0,%1,%2,%3};\n"
        : "+f"(c[0]), "+f"(c[1]), "+f"(c[2]), "+f"(c[3])
        : "r"(a0), "r"(a1), "r"(a2), "r"(a3), "r"(b0), "r"(b1));
}

#define CP16(d, s) asm volatile("cp.async.cg.shared.global [%0], [%1], 16;" :: "r"(d), "l"(s) : "memory")
#define CP_COMMIT() asm volatile("cp.async.commit_group;" ::: "memory")
#define CP_WAIT(n)  asm volatile("cp.async.wait_group %0;" :: "n"(n) : "memory")
#define LDSM4(r0, r1, r2, r3, a) \
    asm volatile("ldmatrix.sync.aligned.m8n8.x4.shared.b16 {%0,%1,%2,%3}, [%4];" \
        : "=r"(r0), "=r"(r1), "=r"(r2), "=r"(r3) : "r"(a))

// ---------------- conv W -> split bf16 pairs ----------------
__global__ __launch_bounds__(256) void conv_w_kernel(
    const float* __restrict__ Wq, const float* __restrict__ Wk, const float* __restrict__ Wv)
{
    int idx = blockIdx.x * 256 + threadIdx.x;
    int proj = idx >> 18;
    int rem = idx & 262143;
    const float* W = (proj == 0) ? Wq : ((proj == 1) ? Wk : Wv);
    float2 v = *(const float2*)(W + (size_t)rem * 2);
    unsigned hi, lo;
    split2(v.x, v.y, hi, lo);
    (&g_Whi[0][0][0])[(size_t)proj * 262144 + rem] = hi;
    (&g_Wlo[0][0][0])[(size_t)proj * 262144 + rem] = lo;
}

// ---------------- conv x -> x^T split pairs ----------------
__global__ __launch_bounds__(256) void conv_x_kernel(const float* __restrict__ x)
{
    __shared__ float sm[64][65];
    int p0 = blockIdx.x * 64, c0 = blockIdx.y * 64, b = blockIdx.z;
    int tid = threadIdx.x;
    for (int t = tid; t < 64 * 64; t += 256) {
        int c = t >> 6, p = t & 63;
        sm[c][p] = x[((size_t)b * CIN + c0 + c) * PP + p0 + p];
    }
    __syncthreads();
    for (int t = tid; t < 64 * 32; t += 256) {
        int p = t >> 5, cp = t & 31;
        unsigned hi, lo;
        split2(sm[2 * cp][p], sm[2 * cp + 1][p], hi, lo);
        size_t o = ((size_t)b * PP + p0 + p) * 256 + (c0 >> 1) + cp;
        (&g_XThi[0][0][0])[o] = hi;
        (&g_XTlo[0][0][0])[o] = lo;
    }
}

// ---------------- Stage 1: mma.sync GEMM  y = W * x ----------------
#define G1_STR 20
__global__ __launch_bounds__(256) void gemm1_mma_kernel()
{
    __shared__ unsigned Ah[128 * G1_STR], Al[128 * G1_STR];
    __shared__ unsigned Bh[128 * G1_STR], Bl[128 * G1_STR];
    int z = blockIdx.z, proj = z >> 3, b = z & 7;
    int o0 = blockIdx.y * 128, p0 = blockIdx.x * 128;
    const unsigned* gWh = &g_Whi[proj][0][0];
    const unsigned* gWl = &g_Wlo[proj][0][0];
    const unsigned* gXh = &g_XThi[b][0][0];
    const unsigned* gXl = &g_XTlo[b][0][0];
    int tid = threadIdx.x, w = tid >> 5, lane = tid & 31;
    int g = lane >> 2, q = lane & 3;
    int wo = w >> 2, wp = w & 3;

    float acc[4][4][4];
#pragma unroll
    for (int i = 0; i < 4; i++)
#pragma unroll
        for (int j = 0; j < 4; j++)
#pragma unroll
            for (int e = 0; e < 4; e++) acc[i][j][e] = 0.f;

    for (int kk = 0; kk < 256; kk += 16) {
        __syncthreads();
        for (int t = tid; t < 2048; t += 256) {
            int r = t >> 4, cp = t & 15;
            Ah[r * G1_STR + cp] = gWh[(size_t)(o0 + r) * 256 + kk + cp];
            Al[r * G1_STR + cp] = gWl[(size_t)(o0 + r) * 256 + kk + cp];
            Bh[r * G1_STR + cp] = gXh[(size_t)(p0 + r) * 256 + kk + cp];
            Bl[r * G1_STR + cp] = gXl[(size_t)(p0 + r) * 256 + kk + cp];
        }
        __syncthreads();
#pragma unroll
        for (int ks = 0; ks < 2; ks++) {
            int k0 = 8 * ks + q;
            unsigned ah[4][4], al[4][4];
#pragma unroll
            for (int mf = 0; mf < 4; mf++) {
                int r = (wo * 64 + 16 * mf + g) * G1_STR + k0;
                ah[mf][0] = Ah[r];     ah[mf][1] = Ah[r + 8 * G1_STR];
                ah[mf][2] = Ah[r + 4]; ah[mf][3] = Ah[r + 8 * G1_STR + 4];
                al[mf][0] = Al[r];     al[mf][1] = Al[r + 8 * G1_STR];
                al[mf][2] = Al[r + 4]; al[mf][3] = Al[r + 8 * G1_STR + 4];
            }
#pragma unroll
            for (int nf = 0; nf < 4; nf++) {
                int r = (wp * 32 + 8 * nf + g) * G1_STR + k0;
                unsigned bh0 = Bh[r], bh1 = Bh[r + 4];
                unsigned bl0 = Bl[r], bl1 = Bl[r + 4];
#pragma unroll
                for (int mf = 0; mf < 4; mf++) {
                    mma16816(acc[mf][nf], ah[mf][0], ah[mf][1], ah[mf][2], ah[mf][3], bh0, bh1);
                    mma16816(acc[mf][nf], ah[mf][0], ah[mf][1], ah[mf][2], ah[mf][3], bl0, bl1);
                    mma16816(acc[mf][nf], al[mf][0], al[mf][1], al[mf][2], al[mf][3], bh0, bh1);
                }
            }
        }
    }
    float* Y = &g_y[proj][b][0][0];
#pragma unroll
    for (int mf = 0; mf < 4; mf++)
#pragma unroll
        for (int nf = 0; nf < 4; nf++) {
            int oo = o0 + wo * 64 + 16 * mf + g;
            int pp = p0 + wp * 32 + 8 * nf + 2 * q;
            float* r0 = Y + (size_t)oo * PP + pp;
            *(float2*)r0 = make_float2(acc[mf][nf][0], acc[mf][nf][1]);
            *(float2*)(r0 + 8 * PP) = make_float2(acc[mf][nf][2], acc[mf][nf][3]);
        }
}

// ---------------- Stage 2: batch stats -> folded affine ----------------
__global__ __launch_bounds__(256) void stats_kernel(
    const float* __restrict__ gq, const float* __restrict__ bq,
    const float* __restrict__ gk, const float* __restrict__ bk,
    const float* __restrict__ gv, const float* __restrict__ bv)
{
    int o = blockIdx.x, proj = blockIdx.y;
    const float* base = &g_y[proj][0][o][0];
    float s = 0.f, s2 = 0.f;
    for (int t = threadIdx.x; t < BB * PP; t += 256) {
        int b = t >> 11, p = t & 2047;
        float v = base[(size_t)b * COUT * PP + p];
        s += v; s2 += v * v;
    }
    __shared__ float red0[256], red1[256];
    red0[threadIdx.x] = s; red1[threadIdx.x] = s2;
    __syncthreads();
    for (int st = 128; st > 0; st >>= 1) {
        if (threadIdx.x < st) {
            red0[threadIdx.x] += red0[threadIdx.x + st];
            red1[threadIdx.x] += red1[threadIdx.x + st];
        }
        __syncthreads();
    }
    if (threadIdx.x == 0) {
        const float invn = 1.f / (BB * PP);
        float mean = red0[0] * invn;
        float var = red1[0] * invn - mean * mean;
        const float* gg = (proj == 0) ? gq : ((proj == 1) ? gk : gv);
        const float* be = (proj == 0) ? bq : ((proj == 1) ? bk : bv);
        float sc = gg[o] * rsqrtf(var + 1e-5f);
        g_scale[proj][o] = sc;
        g_shift[proj][o] = be[o] - mean * sc;
    }
}

// ---------------- Stage 3: fold BN+LeakyReLU, emit split operands ----------
__global__ __launch_bounds__(256) void fold_kernel()
{
    __shared__ float sm[64][65];
    int p0 = blockIdx.x * 64, c0 = blockIdx.y * 64;
    int z = blockIdx.z, proj = z >> 3, b = z & 7;
    int tid = threadIdx.x;
    for (int t = tid; t < 64 * 64; t += 256) {
        int c = t >> 6, p = t & 63;
        float v = g_y[proj][b][c0 + c][p0 + p];
        v = v * g_scale[proj][c0 + c] + g_shift[proj][c0 + c];
        sm[c][p] = (v >= 0.f) ? v : 0.1f * v;
    }
    __syncthreads();
    if (proj == 0) {
        for (int t = tid; t < 64 * 32; t += 256) {
            int c = t >> 5, jp = t & 31;
            unsigned hi, lo;
            split2(sm[c][2 * jp], sm[c][2 * jp + 1], hi, lo);
            size_t o = ((size_t)b * COUT + c0 + c) * 1024 + (p0 >> 1) + jp;
            (&g_Qhi[0][0][0])[o] = hi;
            (&g_Qlo[0][0][0])[o] = lo;
        }
    } else {
        int h = c0 >> 7, cpo = (c0 & 127) >> 1;
        unsigned* dh = (proj == 1) ? &g_KThi[0][0][0][0] : &g_VThi[0][0][0][0];
        unsigned* dl = (proj == 1) ? &g_KTlo[0][0][0][0] : &g_VTlo[0][0][0][0];
        for (int t = tid; t < 64 * 32; t += 256) {
            int p = t >> 5, cp = t & 31;
            unsigned hi, lo;
            split2(sm[2 * cp][p], sm[2 * cp + 1][p], hi, lo);
            size_t o = ((size_t)(b * NH + h) * PP + p0 + p) * 64 + cpo + cp;
            dh[o] = hi;
            dl[o] = lo;
        }
    }
}

// ---------------- Stage 4: mma.sync flash attention v2 ----------------
// smem layout (u32 offsets):
//  KH 0 (128x68)  KL 8704
//  V  17408: buf{0,1} x 8704, each = Vh(64x68=4352) + Vl(4352)
//  QH 34816 (128x36)  QL 39424
//  PH 44032 (128x36)  PL 48640
//  LR 53248 (128 floats)
#define OFF_KH 0
#define OFF_KL 8704
#define OFF_V  17408
#define OFF_QH 34816
#define OFF_QL 39424
#define OFF_PH 44032
#define OFF_PL 48640
#define OFF_LR 53248
#define ATTN2_SMEM ((53248 + 128) * 4)

__global__ __launch_bounds__(256) void attn2_kernel(float* __restrict__ out)
{
    extern __shared__ unsigned sm[];
    uint32_t smb = (uint32_t)__cvta_generic_to_shared(sm);
    const int tid = threadIdx.x;
    const int w = tid >> 5, lane = tid & 31;
    const int g = lane >> 2, q = lane & 3;
    const int tt = lane >> 3, rr = lane & 7;
    const int bh = blockIdx.y, b = bh >> 3, h = bh & 7;
    const int i0 = blockIdx.x * 128;

    const unsigned* gKh = &g_KThi[b][h][0][0];
    const unsigned* gKl = &g_KTlo[b][h][0][0];
    const unsigned* gVh = &g_VThi[b][h][0][0];
    const unsigned* gVl = &g_VTlo[b][h][0][0];
    const unsigned* gQh = &g_Qhi[b][h * 128][0];
    const unsigned* gQl = &g_Qlo[b][h * 128][0];

    // K tile + V buffer 0 via cp.async
    for (int t = tid; t < 2048; t += 256) {
        int r = t >> 4, f4 = (t & 15) * 4;
        uint32_t d = smb + 4 * (OFF_KH + r * 68 + f4);
        size_t so = (size_t)(i0 + r) * 64 + f4;
        CP16(d, gKh + so);
        CP16(d + 4 * 8704, gKl + so);
    }
    for (int t = tid; t < 1024; t += 256) {
        int r = t >> 4, f4 = (t & 15) * 4;
        uint32_t d = smb + 4 * (OFF_V + r * 68 + f4);
        size_t so = (size_t)r * 64 + f4;
        CP16(d, gVh + so);
        CP16(d + 4 * 4352, gVl + so);
    }
    CP_COMMIT();

    float oacc[8][2][4];
#pragma unroll
    for (int mf = 0; mf < 8; mf++)
#pragma unroll
        for (int nf = 0; nf < 2; nf++)
#pragma unroll
            for (int e = 0; e < 4; e++) oacc[mf][nf][e] = 0.f;
    float l0 = 0.f, l1 = 0.f;

    const int aRow = 16 * w + (tt & 1) * 8 + rr;   // S-A / O-B ldmatrix row
    const int aCol = (tt >> 1) * 4;                // u32 column within 16-k chunk
    const int bRow0 = (tt & 1) * 8 + rr;
    const float scl = 0.08838834764831845f;        // 1/sqrt(128)

    for (int jt = 0; jt < 32; jt++) {
        const int j0 = jt * 64, buf = jt & 1;

        // issue Q tile for this iter (consumed in O phase)
        for (int t = tid; t < 1024; t += 256) {
            int r = t >> 3, f4 = (t & 7) * 4;
            uint32_t d = smb + 4 * (OFF_QH + r * 36 + f4);
            size_t so = (size_t)r * 1024 + (j0 >> 1) + f4;
            CP16(d, gQh + so);
            CP16(d + 4 * 4608, gQl + so);
        }
        CP_COMMIT();
        CP_WAIT(1);          // V[buf] (and K on iter 0) ready; Q still in flight
        __syncthreads();

        // prefetch next V tile
        if (jt < 31) {
            int jn = j0 + 64, nbuf = buf ^ 1;
            for (int t = tid; t < 1024; t += 256) {
                int r = t >> 4, f4 = (t & 15) * 4;
                uint32_t d = smb + 4 * (OFF_V + nbuf * 8704 + r * 68 + f4);
                size_t so = (size_t)(jn + r) * 64 + f4;
                CP16(d, gVh + so);
                CP16(d + 4 * 4352, gVl + so);
            }
        }
        CP_COMMIT();

        // ---- S = K_i^T V_j : warp w owns rows 16w..16w+15, n=64 ----
        float sacc[8][4];
#pragma unroll
        for (int nf = 0; nf < 8; nf++)
#pragma unroll
            for (int e = 0; e < 4; e++) sacc[nf][e] = 0.f;

        const uint32_t aBaseH = smb + 4 * (OFF_KH + aRow * 68 + aCol);
        const uint32_t vBase = smb + 4 * (OFF_V + buf * 8704 + bRow0 * 68 + aCol);
#pragma unroll
        for (int ks = 0; ks < 8; ks++) {
            uint32_t ah0, ah1, ah2, ah3, al0, al1, al2, al3;
            LDSM4(ah0, ah1, ah2, ah3, aBaseH + 32 * ks);
            LDSM4(al0, al1, al2, al3, aBaseH + 4 * 8704 + 32 * ks);
#pragma unroll
            for (int nb = 0; nb < 4; nb++) {
                uint32_t vh0, vh1, vh2, vh3, vl0, vl1, vl2, vl3;
                uint32_t vb = vBase + 4 * (nb * 16 * 68) + 32 * ks;
                LDSM4(vh0, vh1, vh2, vh3, vb);
                LDSM4(vl0, vl1, vl2, vl3, vb + 4 * 4352);
                // frag0 = (r0,r2) n=nb*16..+7 ; frag1 = (r1,r3) n=+8
                mma16816(sacc[2 * nb],     ah0, ah1, ah2, ah3, vh0, vh2);
                mma16816(sacc[2 * nb],     al0, al1, al2, al3, vh0, vh2);
                mma16816(sacc[2 * nb],     ah0, ah1, ah2, ah3, vl0, vl2);
                mma16816(sacc[2 * nb + 1], ah0, ah1, ah2, ah3, vh1, vh3);
                mma16816(sacc[2 * nb + 1], al0, al1, al2, al3, vh1, vh3);
                mma16816(sacc[2 * nb + 1], ah0, ah1, ah2, ah3, vl1, vl3);
            }
        }

        // ---- softmax, no max-subtraction (BN-bounded S) ----
#pragma unroll
        for (int nf = 0; nf < 8; nf++) {
            float e0 = __expf(scl * sacc[nf][0]);
            float e1 = __expf(scl * sacc[nf][1]);
            float e2 = __expf(scl * sacc[nf][2]);
            float e3 = __expf(scl * sacc[nf][3]);
            l0 += e0 + e1;
            l1 += e2 + e3;
            unsigned hi, lo;
            int jp = 4 * nf + q;
            split2(e0, e1, hi, lo);
            sm[OFF_PH + (16 * w + g) * 36 + jp] = hi;
            sm[OFF_PL + (16 * w + g) * 36 + jp] = lo;
            split2(e2, e3, hi, lo);
            sm[OFF_PH + (16 * w + 8 + g) * 36 + jp] = hi;
            sm[OFF_PL + (16 * w + 8 + g) * 36 + jp] = lo;
        }
        CP_WAIT(1);          // Q ready; next-V still in flight
        __syncthreads();     // P visible to all warps

        // ---- O += Q_j P^T : warp w owns i-cols 16w..16w+15, m=128 ----
        const uint32_t pBase = smb + 4 * (OFF_PH + aRow * 36 + aCol);
        const uint32_t qBase = smb + 4 * (OFF_QH + bRow0 * 36 + aCol);
#pragma unroll
        for (int ks = 0; ks < 4; ks++) {
            uint32_t ph0, ph1, ph2, ph3, pl0, pl1, pl2, pl3;
            LDSM4(ph0, ph1, ph2, ph3, pBase + 32 * ks);
            LDSM4(pl0, pl1, pl2, pl3, pBase + 4 * 4608 + 32 * ks);
#pragma unroll
            for (int mf = 0; mf < 8; mf++) {
                uint32_t qh0, qh1, qh2, qh3, ql0, ql1, ql2, ql3;
                uint32_t qa = qBase + 4 * (16 * mf * 36) + 32 * ks;
                LDSM4(qh0, qh1, qh2, qh3, qa);
                LDSM4(ql0, ql1, ql2, ql3, qa + 4 * 4608);
                mma16816(oacc[mf][0], qh0, qh1, qh2, qh3, ph0, ph2);
                mma16816(oacc[mf][0], ql0, ql1, ql2, ql3, ph0, ph2);
                mma16816(oacc[mf][0], qh0, qh1, qh2, qh3, pl0, pl2);
                mma16816(oacc[mf][1], qh0, qh1, qh2, qh3, ph1, ph3);
                mma16816(oacc[mf][1], ql0, ql1, ql2, ql3, ph1, ph3);
                mma16816(oacc[mf][1], qh0, qh1, qh2, qh3, pl1, pl3);
            }
        }
        __syncthreads();     // all warps done with Q/P before next overwrite
    }

    // ---- finalize: reduce l, scale O, write out ----
    l0 += __shfl_xor_sync(0xffffffffu, l0, 1);
    l0 += __shfl_xor_sync(0xffffffffu, l0, 2);
    l1 += __shfl_xor_sync(0xffffffffu, l1, 1);
    l1 += __shfl_xor_sync(0xffffffffu, l1, 2);
    float* lrow = (float*)&sm[OFF_LR];
    if (q == 0) {
        lrow[16 * w + g] = 1.f / l0;
        lrow[16 * w + 8 + g] = 1.f / l1;
    }
    __syncthreads();
#pragma unroll
    for (int nf = 0; nf < 2; nf++) {
        int ic = 16 * w + 8 * nf + 2 * q;
        float il0 = lrow[ic], il1 = lrow[ic + 1];
#pragma unroll
        for (int mf = 0; mf < 8; mf++) {
            int c = h * 128 + 16 * mf + g;
            float* p0 = out + ((size_t)b * COUT + c) * PP + i0 + ic;
            p0[0] = oacc[mf][nf][0] * il0;
            p0[1] = oacc[mf][nf][1] * il1;
            float* p1 = p0 + 8 * PP;
            p1[0] = oacc[mf][nf][2] * il0;
            p1[1] = oacc[mf][nf][3] * il1;
        }
    }
}

// ---------------------------------------------------------------------------
extern "C" void kernel_launch(void* const* d_in, const int* in_sizes, int n_in,
                              void* d_out, int out_size)
{
    const float* x  = (const float*)d_in[0];
    const float* Wq = (const float*)d_in[1];
    const float* gq = (const float*)d_in[2];
    const float* bq = (const float*)d_in[3];
    const float* Wk = (const float*)d_in[4];
    const float* gk = (const float*)d_in[5];
    const float* bk = (const float*)d_in[6];
    const float* Wv = (const float*)d_in[7];
    const float* gv = (const float*)d_in[8];
    const float* bv = (const float*)d_in[9];
    float* out = (float*)d_out;

    conv_w_kernel<<<3 * COUT * (CIN / 2) / 256, 256>>>(Wq, Wk, Wv);
    conv_x_kernel<<<dim3(PP / 64, CIN / 64, BB), 256>>>(x);
    gemm1_mma_kernel<<<dim3(PP / 128, COUT / 128, 3 * BB), 256>>>();
    stats_kernel<<<dim3(COUT, 3), 256>>>(gq, bq, gk, bk, gv, bv);
    fold_kernel<<<dim3(PP / 64, COUT / 64, 3 * BB), 256>>>();

    cudaFuncSetAttribute(attn2_kernel, cudaFuncAttributeMaxDynamicSharedMemorySize, ATTN2_SMEM);
    attn2_kernel<<<dim3(PP / 128, BB * NH), 256, ATTN2_SMEM>>>(out);
}

// round 7
// speedup vs baseline: 5.9940x; 1.2166x over previous
#include <cuda_runtime.h>
#include <cuda_bf16.h>
#include <math.h>
#include <stdint.h>

#define BB 8
#define CIN 512
#define COUT 1024
#define PP 2048
#define NH 8
#define DH 128

// ---------------- scratch (device globals; no allocations) ----------------
__device__ float    g_y[3][BB][COUT][PP];       // fp32 projections (pre-BN)
__device__ float    g_scale[3][COUT];
__device__ float    g_shift[3][COUT];
__device__ unsigned g_Whi[3][COUT][CIN/2];      // W split bf16 pairs along c
__device__ unsigned g_Wlo[3][COUT][CIN/2];
__device__ unsigned g_XThi[BB][PP][CIN/2];      // x^T split pairs along c
__device__ unsigned g_XTlo[BB][PP][CIN/2];
__device__ unsigned g_Qhi[BB][COUT][PP/2];      // Q (post-BN) pairs along p
__device__ unsigned g_Qlo[BB][COUT][PP/2];
__device__ unsigned g_KThi[BB][NH][PP][DH/2];   // K^T per head, pairs along c
__device__ unsigned g_KTlo[BB][NH][PP][DH/2];
__device__ unsigned g_VThi[BB][NH][PP][DH/2];   // V^T per head, pairs along c
__device__ unsigned g_VTlo[BB][NH][PP][DH/2];

// ---------------- helpers ----------------
__device__ __forceinline__ unsigned pack_bf16(float a, float b) {
    __nv_bfloat162 t = __floats2bfloat162_rn(a, b);
    return *(unsigned*)&t;
}
__device__ __forceinline__ void split2(float x0, float x1, unsigned& hi, unsigned& lo) {
    __nv_bfloat16 h0 = __float2bfloat16(x0);
    __nv_bfloat16 h1 = __float2bfloat16(x1);
    float r0 = x0 - __bfloat162float(h0);
    float r1 = x1 - __bfloat162float(h1);
    __nv_bfloat162 hp; hp.x = h0; hp.y = h1;
    hi = *(unsigned*)&hp;
    lo = pack_bf16(r0, r1);
}
__device__ __forceinline__ void mma16816(float* c,
    unsigned a0, unsigned a1, unsigned a2, unsigned a3, unsigned b0, unsigned b1)
{
    asm volatile(
        "mma.sync.aligned.m16n8k16.row.col.f32.bf16.bf16.f32 "
        "{%0,%1,%2,%3}, {%4,%5,%6,%7}, {%8,%9}, {%0,%1,%2,%3};\n"
        : "+f"(c[0]), "+f"(c[1]), "+f"(c[2]), "+f"(c[3])
        : "r"(a0), "r"(a1), "r"(a2), "r"(a3), "r"(b0), "r"(b1));
}

#define CP16(d, s) asm volatile("cp.async.cg.shared.global [%0], [%1], 16;" :: "r"(d), "l"(s) : "memory")
#define CP_COMMIT() asm volatile("cp.async.commit_group;" ::: "memory")
#define CP_WAIT(n)  asm volatile("cp.async.wait_group %0;" :: "n"(n) : "memory")
#define LDSM4(r0, r1, r2, r3, a) \
    asm volatile("ldmatrix.sync.aligned.m8n8.x4.shared.b16 {%0,%1,%2,%3}, [%4];" \
        : "=r"(r0), "=r"(r1), "=r"(r2), "=r"(r3) : "r"(a))

// ---------------- conv W -> split bf16 pairs ----------------
__global__ __launch_bounds__(256) void conv_w_kernel(
    const float* __restrict__ Wq, const float* __restrict__ Wk, const float* __restrict__ Wv)
{
    int idx = blockIdx.x * 256 + threadIdx.x;
    int proj = idx >> 18;
    int rem = idx & 262143;
    const float* W = (proj == 0) ? Wq : ((proj == 1) ? Wk : Wv);
    float2 v = *(const float2*)(W + (size_t)rem * 2);
    unsigned hi, lo;
    split2(v.x, v.y, hi, lo);
    (&g_Whi[0][0][0])[(size_t)proj * 262144 + rem] = hi;
    (&g_Wlo[0][0][0])[(size_t)proj * 262144 + rem] = lo;
}

// ---------------- conv x -> x^T split pairs ----------------
__global__ __launch_bounds__(256) void conv_x_kernel(const float* __restrict__ x)
{
    __shared__ float sm[64][65];
    int p0 = blockIdx.x * 64, c0 = blockIdx.y * 64, b = blockIdx.z;
    int tid = threadIdx.x;
    for (int t = tid; t < 64 * 64; t += 256) {
        int c = t >> 6, p = t & 63;
        sm[c][p] = x[((size_t)b * CIN + c0 + c) * PP + p0 + p];
    }
    __syncthreads();
    for (int t = tid; t < 64 * 32; t += 256) {
        int p = t >> 5, cp = t & 31;
        unsigned hi, lo;
        split2(sm[2 * cp][p], sm[2 * cp + 1][p], hi, lo);
        size_t o = ((size_t)b * PP + p0 + p) * 256 + (c0 >> 1) + cp;
        (&g_XThi[0][0][0])[o] = hi;
        (&g_XTlo[0][0][0])[o] = lo;
    }
}

// ---------------- Stage 1 v2: cp.async + ldmatrix GEMM  y = W * x ---------
// smem per stage (u32): Ah 128x20=2560, Al 2560, Bh 2560, Bl 2560 => 10240
// 2 stages = 20480 u32 = 80KB dynamic
#define G2_STR 20
#define G2_STAGE 10240
#define G2_SMEM (2 * G2_STAGE * 4)

__global__ __launch_bounds__(256, 2) void gemm1b_kernel()
{
    extern __shared__ unsigned su[];
    uint32_t smb = (uint32_t)__cvta_generic_to_shared(su);
    int z = blockIdx.z, proj = z >> 3, b = z & 7;
    int o0 = blockIdx.y * 128, p0 = blockIdx.x * 128;
    const unsigned* gWh = &g_Whi[proj][0][0];
    const unsigned* gWl = &g_Wlo[proj][0][0];
    const unsigned* gXh = &g_XThi[b][0][0];
    const unsigned* gXl = &g_XTlo[b][0][0];
    const int tid = threadIdx.x, w = tid >> 5, lane = tid & 31;
    const int g = lane >> 2, q = lane & 3;
    const int tt = lane >> 3, rr = lane & 7;
    const int wo = w >> 2, wp = w & 3;

    float acc[4][4][4];
#pragma unroll
    for (int i = 0; i < 4; i++)
#pragma unroll
        for (int j = 0; j < 4; j++)
#pragma unroll
            for (int e = 0; e < 4; e++) acc[i][j][e] = 0.f;

    // stage loader: chunk c covers kpair [16c, 16c+16)
#define G2_LOAD(c) do { \
        int _s = (c) & 1, _kk = (c) * 16; \
        uint32_t _sb = smb + 4 * (_s * G2_STAGE); \
        for (int t = tid; t < 512; t += 256) { \
            int r = t >> 2, f4 = (t & 3) * 4; \
            uint32_t d = _sb + 4 * (r * G2_STR + f4); \
            size_t wo_ = (size_t)(o0 + r) * 256 + _kk + f4; \
            size_t xo_ = (size_t)(p0 + r) * 256 + _kk + f4; \
            CP16(d,            gWh + wo_); \
            CP16(d + 4 * 2560, gWl + wo_); \
            CP16(d + 4 * 5120, gXh + xo_); \
            CP16(d + 4 * 7680, gXl + xo_); \
        } \
    } while (0)

    G2_LOAD(0);
    CP_COMMIT();

    const int fragRow = (tt & 1) * 8 + rr;     // ldmatrix row-within-16
    const int fragCol = (tt >> 1) * 4;         // u32 col (k8 offset for lanes 16+)

    for (int c = 0; c < 16; c++) {
        if (c < 15) {
            G2_LOAD(c + 1);
            CP_COMMIT();
            CP_WAIT(1);
        } else {
            CP_WAIT(0);
        }
        __syncthreads();

        const int s = c & 1;
        const uint32_t aB = smb + 4 * (s * G2_STAGE + (wo * 64 + fragRow) * G2_STR + fragCol);
        const uint32_t bB = smb + 4 * (s * G2_STAGE + 5120 + (wp * 32 + fragRow) * G2_STR + fragCol);
#pragma unroll
        for (int ks = 0; ks < 2; ks++) {
            uint32_t a[4][4];
            uint32_t bh[2][4], bl[2][4];
#pragma unroll
            for (int nb = 0; nb < 2; nb++) {
                uint32_t ba = bB + 4 * (16 * nb * G2_STR + 8 * ks);
                LDSM4(bh[nb][0], bh[nb][1], bh[nb][2], bh[nb][3], ba);
                LDSM4(bl[nb][0], bl[nb][1], bl[nb][2], bl[nb][3], ba + 4 * 2560);
            }
            // A-hi fragments
#pragma unroll
            for (int mf = 0; mf < 4; mf++) {
                uint32_t aa = aB + 4 * (16 * mf * G2_STR + 8 * ks);
                LDSM4(a[mf][0], a[mf][1], a[mf][2], a[mf][3], aa);
            }
            // Ah*Bh + Ah*Bl
#pragma unroll
            for (int nb = 0; nb < 2; nb++)
#pragma unroll
                for (int mf = 0; mf < 4; mf++) {
                    mma16816(acc[mf][2 * nb],     a[mf][0], a[mf][1], a[mf][2], a[mf][3], bh[nb][0], bh[nb][2]);
                    mma16816(acc[mf][2 * nb],     a[mf][0], a[mf][1], a[mf][2], a[mf][3], bl[nb][0], bl[nb][2]);
                    mma16816(acc[mf][2 * nb + 1], a[mf][0], a[mf][1], a[mf][2], a[mf][3], bh[nb][1], bh[nb][3]);
                    mma16816(acc[mf][2 * nb + 1], a[mf][0], a[mf][1], a[mf][2], a[mf][3], bl[nb][1], bl[nb][3]);
                }
            // A-lo fragments (reuse regs), Al*Bh
#pragma unroll
            for (int mf = 0; mf < 4; mf++) {
                uint32_t aa = aB + 4 * (2560 + 16 * mf * G2_STR + 8 * ks);
                LDSM4(a[mf][0], a[mf][1], a[mf][2], a[mf][3], aa);
            }
#pragma unroll
            for (int nb = 0; nb < 2; nb++)
#pragma unroll
                for (int mf = 0; mf < 4; mf++) {
                    mma16816(acc[mf][2 * nb],     a[mf][0], a[mf][1], a[mf][2], a[mf][3], bh[nb][0], bh[nb][2]);
                    mma16816(acc[mf][2 * nb + 1], a[mf][0], a[mf][1], a[mf][2], a[mf][3], bh[nb][1], bh[nb][3]);
                }
        }
        __syncthreads();
    }

    float* Y = &g_y[proj][b][0][0];
#pragma unroll
    for (int mf = 0; mf < 4; mf++)
#pragma unroll
        for (int nf = 0; nf < 4; nf++) {
            int oo = o0 + wo * 64 + 16 * mf + g;
            int pp = p0 + wp * 32 + 8 * nf + 2 * q;
            float* r0 = Y + (size_t)oo * PP + pp;
            *(float2*)r0 = make_float2(acc[mf][nf][0], acc[mf][nf][1]);
            *(float2*)(r0 + 8 * PP) = make_float2(acc[mf][nf][2], acc[mf][nf][3]);
        }
}

// ---------------- Stage 2: batch stats -> folded affine ----------------
__global__ __launch_bounds__(256) void stats_kernel(
    const float* __restrict__ gq, const float* __restrict__ bq,
    const float* __restrict__ gk, const float* __restrict__ bk,
    const float* __restrict__ gv, const float* __restrict__ bv)
{
    int o = blockIdx.x, proj = blockIdx.y;
    const float* base = &g_y[proj][0][o][0];
    float s = 0.f, s2 = 0.f;
    for (int t = threadIdx.x; t < BB * PP / 4; t += 256) {
        int b = t >> 9, p4 = (t & 511) * 4;
        float4 v = *(const float4*)&base[(size_t)b * COUT * PP + p4];
        s += v.x + v.y + v.z + v.w;
        s2 += v.x * v.x + v.y * v.y + v.z * v.z + v.w * v.w;
    }
    __shared__ float red0[256], red1[256];
    red0[threadIdx.x] = s; red1[threadIdx.x] = s2;
    __syncthreads();
    for (int st = 128; st > 0; st >>= 1) {
        if (threadIdx.x < st) {
            red0[threadIdx.x] += red0[threadIdx.x + st];
            red1[threadIdx.x] += red1[threadIdx.x + st];
        }
        __syncthreads();
    }
    if (threadIdx.x == 0) {
        const float invn = 1.f / (BB * PP);
        float mean = red0[0] * invn;
        float var = red1[0] * invn - mean * mean;
        const float* gg = (proj == 0) ? gq : ((proj == 1) ? gk : gv);
        const float* be = (proj == 0) ? bq : ((proj == 1) ? bk : bv);
        float sc = gg[o] * rsqrtf(var + 1e-5f);
        g_scale[proj][o] = sc;
        g_shift[proj][o] = be[o] - mean * sc;
    }
}

// ---------------- Stage 3: fold BN+LeakyReLU, emit split operands ----------
__global__ __launch_bounds__(256) void fold_kernel()
{
    __shared__ float sm[64][65];
    int p0 = blockIdx.x * 64, c0 = blockIdx.y * 64;
    int z = blockIdx.z, proj = z >> 3, b = z & 7;
    int tid = threadIdx.x;
    for (int t = tid; t < 64 * 64; t += 256) {
        int c = t >> 6, p = t & 63;
        float v = g_y[proj][b][c0 + c][p0 + p];
        v = v * g_scale[proj][c0 + c] + g_shift[proj][c0 + c];
        sm[c][p] = (v >= 0.f) ? v : 0.1f * v;
    }
    __syncthreads();
    if (proj == 0) {
        for (int t = tid; t < 64 * 32; t += 256) {
            int c = t >> 5, jp = t & 31;
            unsigned hi, lo;
            split2(sm[c][2 * jp], sm[c][2 * jp + 1], hi, lo);
            size_t o = ((size_t)b * COUT + c0 + c) * 1024 + (p0 >> 1) + jp;
            (&g_Qhi[0][0][0])[o] = hi;
            (&g_Qlo[0][0][0])[o] = lo;
        }
    } else {
        int h = c0 >> 7, cpo = (c0 & 127) >> 1;
        unsigned* dh = (proj == 1) ? &g_KThi[0][0][0][0] : &g_VThi[0][0][0][0];
        unsigned* dl = (proj == 1) ? &g_KTlo[0][0][0][0] : &g_VTlo[0][0][0][0];
        for (int t = tid; t < 64 * 32; t += 256) {
            int p = t >> 5, cp = t & 31;
            unsigned hi, lo;
            split2(sm[2 * cp][p], sm[2 * cp + 1][p], hi, lo);
            size_t o = ((size_t)(b * NH + h) * PP + p0 + p) * 64 + cpo + cp;
            dh[o] = hi;
            dl[o] = lo;
        }
    }
}

// ---------------- Stage 4: mma.sync flash attention v2 ----------------
#define OFF_KH 0
#define OFF_KL 8704
#define OFF_V  17408
#define OFF_QH 34816
#define OFF_QL 39424
#define OFF_PH 44032
#define OFF_PL 48640
#define OFF_LR 53248
#define ATTN2_SMEM ((53248 + 128) * 4)

__global__ __launch_bounds__(256) void attn2_kernel(float* __restrict__ out)
{
    extern __shared__ unsigned sm[];
    uint32_t smb = (uint32_t)__cvta_generic_to_shared(sm);
    const int tid = threadIdx.x;
    const int w = tid >> 5, lane = tid & 31;
    const int g = lane >> 2, q = lane & 3;
    const int tt = lane >> 3, rr = lane & 7;
    const int bh = blockIdx.y, b = bh >> 3, h = bh & 7;
    const int i0 = blockIdx.x * 128;

    const unsigned* gKh = &g_KThi[b][h][0][0];
    const unsigned* gKl = &g_KTlo[b][h][0][0];
    const unsigned* gVh = &g_VThi[b][h][0][0];
    const unsigned* gVl = &g_VTlo[b][h][0][0];
    const unsigned* gQh = &g_Qhi[b][h * 128][0];
    const unsigned* gQl = &g_Qlo[b][h * 128][0];

    for (int t = tid; t < 2048; t += 256) {
        int r = t >> 4, f4 = (t & 15) * 4;
        uint32_t d = smb + 4 * (OFF_KH + r * 68 + f4);
        size_t so = (size_t)(i0 + r) * 64 + f4;
        CP16(d, gKh + so);
        CP16(d + 4 * 8704, gKl + so);
    }
    for (int t = tid; t < 1024; t += 256) {
        int r = t >> 4, f4 = (t & 15) * 4;
        uint32_t d = smb + 4 * (OFF_V + r * 68 + f4);
        size_t so = (size_t)r * 64 + f4;
        CP16(d, gVh + so);
        CP16(d + 4 * 4352, gVl + so);
    }
    CP_COMMIT();

    float oacc[8][2][4];
#pragma unroll
    for (int mf = 0; mf < 8; mf++)
#pragma unroll
        for (int nf = 0; nf < 2; nf++)
#pragma unroll
            for (int e = 0; e < 4; e++) oacc[mf][nf][e] = 0.f;
    float l0 = 0.f, l1 = 0.f;

    const int aRow = 16 * w + (tt & 1) * 8 + rr;
    const int aCol = (tt >> 1) * 4;
    const int bRow0 = (tt & 1) * 8 + rr;
    const float scl = 0.08838834764831845f;

    for (int jt = 0; jt < 32; jt++) {
        const int j0 = jt * 64, buf = jt & 1;

        for (int t = tid; t < 1024; t += 256) {
            int r = t >> 3, f4 = (t & 7) * 4;
            uint32_t d = smb + 4 * (OFF_QH + r * 36 + f4);
            size_t so = (size_t)r * 1024 + (j0 >> 1) + f4;
            CP16(d, gQh + so);
            CP16(d + 4 * 4608, gQl + so);
        }
        CP_COMMIT();
        CP_WAIT(1);
        __syncthreads();

        if (jt < 31) {
            int jn = j0 + 64, nbuf = buf ^ 1;
            for (int t = tid; t < 1024; t += 256) {
                int r = t >> 4, f4 = (t & 15) * 4;
                uint32_t d = smb + 4 * (OFF_V + nbuf * 8704 + r * 68 + f4);
                size_t so = (size_t)(jn + r) * 64 + f4;
                CP16(d, gVh + so);
                CP16(d + 4 * 4352, gVl + so);
            }
        }
        CP_COMMIT();

        float sacc[8][4];
#pragma unroll
        for (int nf = 0; nf < 8; nf++)
#pragma unroll
            for (int e = 0; e < 4; e++) sacc[nf][e] = 0.f;

        const uint32_t aBaseH = smb + 4 * (OFF_KH + aRow * 68 + aCol);
        const uint32_t vBase = smb + 4 * (OFF_V + buf * 8704 + bRow0 * 68 + aCol);
#pragma unroll
        for (int ks = 0; ks < 8; ks++) {
            uint32_t ah0, ah1, ah2, ah3, al0, al1, al2, al3;
            LDSM4(ah0, ah1, ah2, ah3, aBaseH + 32 * ks);
            LDSM4(al0, al1, al2, al3, aBaseH + 4 * 8704 + 32 * ks);
#pragma unroll
            for (int nb = 0; nb < 4; nb++) {
                uint32_t vh0, vh1, vh2, vh3, vl0, vl1, vl2, vl3;
                uint32_t vb = vBase + 4 * (nb * 16 * 68) + 32 * ks;
                LDSM4(vh0, vh1, vh2, vh3, vb);
                LDSM4(vl0, vl1, vl2, vl3, vb + 4 * 4352);
                mma16816(sacc[2 * nb],     ah0, ah1, ah2, ah3, vh0, vh2);
                mma16816(sacc[2 * nb],     al0, al1, al2, al3, vh0, vh2);
                mma16816(sacc[2 * nb],     ah0, ah1, ah2, ah3, vl0, vl2);
                mma16816(sacc[2 * nb + 1], ah0, ah1, ah2, ah3, vh1, vh3);
                mma16816(sacc[2 * nb + 1], al0, al1, al2, al3, vh1, vh3);
                mma16816(sacc[2 * nb + 1], ah0, ah1, ah2, ah3, vl1, vl3);
            }
        }

#pragma unroll
        for (int nf = 0; nf < 8; nf++) {
            float e0 = __expf(scl * sacc[nf][0]);
            float e1 = __expf(scl * sacc[nf][1]);
            float e2 = __expf(scl * sacc[nf][2]);
            float e3 = __expf(scl * sacc[nf][3]);
            l0 += e0 + e1;
            l1 += e2 + e3;
            unsigned hi, lo;
            int jp = 4 * nf + q;
            split2(e0, e1, hi, lo);
            sm[OFF_PH + (16 * w + g) * 36 + jp] = hi;
            sm[OFF_PL + (16 * w + g) * 36 + jp] = lo;
            split2(e2, e3, hi, lo);
            sm[OFF_PH + (16 * w + 8 + g) * 36 + jp] = hi;
            sm[OFF_PL + (16 * w + 8 + g) * 36 + jp] = lo;
        }
        CP_WAIT(1);
        __syncthreads();

        const uint32_t pBase = smb + 4 * (OFF_PH + aRow * 36 + aCol);
        const uint32_t qBase = smb + 4 * (OFF_QH + bRow0 * 36 + aCol);
#pragma unroll
        for (int ks = 0; ks < 4; ks++) {
            uint32_t ph0, ph1, ph2, ph3, pl0, pl1, pl2, pl3;
            LDSM4(ph0, ph1, ph2, ph3, pBase + 32 * ks);
            LDSM4(pl0, pl1, pl2, pl3, pBase + 4 * 4608 + 32 * ks);
#pragma unroll
            for (int mf = 0; mf < 8; mf++) {
                uint32_t qh0, qh1, qh2, qh3, ql0, ql1, ql2, ql3;
                uint32_t qa = qBase + 4 * (16 * mf * 36) + 32 * ks;
                LDSM4(qh0, qh1, qh2, qh3, qa);
                LDSM4(ql0, ql1, ql2, ql3, qa + 4 * 4608);
                mma16816(oacc[mf][0], qh0, qh1, qh2, qh3, ph0, ph2);
                mma16816(oacc[mf][0], ql0, ql1, ql2, ql3, ph0, ph2);
                mma16816(oacc[mf][0], qh0, qh1, qh2, qh3, pl0, pl2);
                mma16816(oacc[mf][1], qh0, qh1, qh2, qh3, ph1, ph3);
                mma16816(oacc[mf][1], ql0, ql1, ql2, ql3, ph1, ph3);
                mma16816(oacc[mf][1], qh0, qh1, qh2, qh3, pl1, pl3);
            }
        }
        __syncthreads();
    }

    l0 += __shfl_xor_sync(0xffffffffu, l0, 1);
    l0 += __shfl_xor_sync(0xffffffffu, l0, 2);
    l1 += __shfl_xor_sync(0xffffffffu, l1, 1);
    l1 += __shfl_xor_sync(0xffffffffu, l1, 2);
    float* lrow = (float*)&sm[OFF_LR];
    if (q == 0) {
        lrow[16 * w + g] = 1.f / l0;
        lrow[16 * w + 8 + g] = 1.f / l1;
    }
    __syncthreads();
#pragma unroll
    for (int nf = 0; nf < 2; nf++) {
        int ic = 16 * w + 8 * nf + 2 * q;
        float il0 = lrow[ic], il1 = lrow[ic + 1];
#pragma unroll
        for (int mf = 0; mf < 8; mf++) {
            int c = h * 128 + 16 * mf + g;
            float* p0 = out + ((size_t)b * COUT + c) * PP + i0 + ic;
            p0[0] = oacc[mf][nf][0] * il0;
            p0[1] = oacc[mf][nf][1] * il1;
            float* p1 = p0 + 8 * PP;
            p1[0] = oacc[mf][nf][2] * il0;
            p1[1] = oacc[mf][nf][3] * il1;
        }
    }
}

// ---------------------------------------------------------------------------
extern "C" void kernel_launch(void* const* d_in, const int* in_sizes, int n_in,
                              void* d_out, int out_size)
{
    const float* x  = (const float*)d_in[0];
    const float* Wq = (const float*)d_in[1];
    const float* gq = (const float*)d_in[2];
    const float* bq = (const float*)d_in[3];
    const float* Wk = (const float*)d_in[4];
    const float* gk = (const float*)d_in[5];
    const float* bk = (const float*)d_in[6];
    const float* Wv = (const float*)d_in[7];
    const float* gv = (const float*)d_in[8];
    const float* bv = (const float*)d_in[9];
    float* out = (float*)d_out;

    conv_w_kernel<<<3 * COUT * (CIN / 2) / 256, 256>>>(Wq, Wk, Wv);
    conv_x_kernel<<<dim3(PP / 64, CIN / 64, BB), 256>>>(x);

    cudaFuncSetAttribute(gemm1b_kernel, cudaFuncAttributeMaxDynamicSharedMemorySize, G2_SMEM);
    gemm1b_kernel<<<dim3(PP / 128, COUT / 128, 3 * BB), 256, G2_SMEM>>>();

    stats_kernel<<<dim3(COUT, 3), 256>>>(gq, bq, gk, bk, gv, bv);
    fold_kernel<<<dim3(PP / 64, COUT / 64, 3 * BB), 256>>>();

    cudaFuncSetAttribute(attn2_kernel, cudaFuncAttributeMaxDynamicSharedMemorySize, ATTN2_SMEM);
    attn2_kernel<<<dim3(PP / 128, BB * NH), 256, ATTN2_SMEM>>>(out);
}

// round 8
// speedup vs baseline: 6.0343x; 1.0067x over previous
#include <cuda_runtime.h>
#include <cuda_bf16.h>
#include <math.h>
#include <stdint.h>

#define BB 8
#define CIN 512
#define COUT 1024
#define PP 2048
#define NH 8
#define DH 128

// ---------------- scratch (device globals; no allocations) ----------------
__device__ float    g_y[3][BB][COUT][PP];       // fp32 projections (pre-BN)
__device__ float    g_scale[3][COUT];
__device__ float    g_shift[3][COUT];
__device__ unsigned g_Whi[3][COUT][CIN/2];      // W split bf16 pairs along c
__device__ unsigned g_Wlo[3][COUT][CIN/2];
__device__ unsigned g_XThi[BB][PP][CIN/2];      // x^T split pairs along c
__device__ unsigned g_XTlo[BB][PP][CIN/2];
__device__ unsigned g_Qhi[BB][COUT][PP/2];      // Q (post-BN) pairs along p
__device__ unsigned g_Qlo[BB][COUT][PP/2];
__device__ unsigned g_KThi[BB][NH][PP][DH/2];   // K^T per head (pre-scaled), pairs along c
__device__ unsigned g_KTlo[BB][NH][PP][DH/2];
__device__ unsigned g_VThi[BB][NH][PP][DH/2];   // V^T per head, pairs along c
__device__ unsigned g_VTlo[BB][NH][PP][DH/2];

// log2(e) / sqrt(128): folded into K so softmax is a bare ex2
#define K_ALPHA 0.12751743f

// ---------------- helpers ----------------
// fast split: hi = truncate-to-bf16 (packed via PRMT), lo = rn-bf16(x - hi)
__device__ __forceinline__ void split2(float x0, float x1, unsigned& hi, unsigned& lo) {
    unsigned u0 = __float_as_uint(x0), u1 = __float_as_uint(x1);
    hi = __byte_perm(u0, u1, 0x7632);
    float h0 = __uint_as_float(u0 & 0xffff0000u);
    float h1 = __uint_as_float(u1 & 0xffff0000u);
    float l0 = x0 - h0, l1 = x1 - h1;
    asm("cvt.rn.bf16x2.f32 %0, %1, %2;" : "=r"(lo) : "f"(l1), "f"(l0));
}
__device__ __forceinline__ float fex2(float x) {
    float y;
    asm("ex2.approx.ftz.f32 %0, %1;" : "=f"(y) : "f"(x));
    return y;
}
__device__ __forceinline__ void mma16816(float* c,
    unsigned a0, unsigned a1, unsigned a2, unsigned a3, unsigned b0, unsigned b1)
{
    asm volatile(
        "mma.sync.aligned.m16n8k16.row.col.f32.bf16.bf16.f32 "
        "{%0,%1,%2,%3}, {%4,%5,%6,%7}, {%8,%9}, {%0,%1,%2,%3};\n"
        : "+f"(c[0]), "+f"(c[1]), "+f"(c[2]), "+f"(c[3])
        : "r"(a0), "r"(a1), "r"(a2), "r"(a3), "r"(b0), "r"(b1));
}

#define CP16(d, s) asm volatile("cp.async.cg.shared.global [%0], [%1], 16;" :: "r"(d), "l"(s) : "memory")
#define CP_COMMIT() asm volatile("cp.async.commit_group;" ::: "memory")
#define CP_WAIT(n)  asm volatile("cp.async.wait_group %0;" :: "n"(n) : "memory")
#define LDSM4(r0, r1, r2, r3, a) \
    asm volatile("ldmatrix.sync.aligned.m8n8.x4.shared.b16 {%0,%1,%2,%3}, [%4];" \
        : "=r"(r0), "=r"(r1), "=r"(r2), "=r"(r3) : "r"(a))

// ---------------- conv W -> split bf16 pairs ----------------
__global__ __launch_bounds__(256) void conv_w_kernel(
    const float* __restrict__ Wq, const float* __restrict__ Wk, const float* __restrict__ Wv)
{
    int idx = blockIdx.x * 256 + threadIdx.x;
    int proj = idx >> 18;
    int rem = idx & 262143;
    const float* W = (proj == 0) ? Wq : ((proj == 1) ? Wk : Wv);
    float2 v = *(const float2*)(W + (size_t)rem * 2);
    unsigned hi, lo;
    split2(v.x, v.y, hi, lo);
    (&g_Whi[0][0][0])[(size_t)proj * 262144 + rem] = hi;
    (&g_Wlo[0][0][0])[(size_t)proj * 262144 + rem] = lo;
}

// ---------------- conv x -> x^T split pairs ----------------
__global__ __launch_bounds__(256) void conv_x_kernel(const float* __restrict__ x)
{
    __shared__ float sm[64][65];
    int p0 = blockIdx.x * 64, c0 = blockIdx.y * 64, b = blockIdx.z;
    int tid = threadIdx.x;
    for (int t = tid; t < 64 * 64; t += 256) {
        int c = t >> 6, p = t & 63;
        sm[c][p] = x[((size_t)b * CIN + c0 + c) * PP + p0 + p];
    }
    __syncthreads();
    for (int t = tid; t < 64 * 32; t += 256) {
        int p = t >> 5, cp = t & 31;
        unsigned hi, lo;
        split2(sm[2 * cp][p], sm[2 * cp + 1][p], hi, lo);
        size_t o = ((size_t)b * PP + p0 + p) * 256 + (c0 >> 1) + cp;
        (&g_XThi[0][0][0])[o] = hi;
        (&g_XTlo[0][0][0])[o] = lo;
    }
}

// ---------------- Stage 1: cp.async + ldmatrix GEMM  y = W * x ---------
#define G2_STR 20
#define G2_STAGE 10240
#define G2_SMEM (2 * G2_STAGE * 4)

__global__ __launch_bounds__(256, 2) void gemm1b_kernel()
{
    extern __shared__ unsigned su[];
    uint32_t smb = (uint32_t)__cvta_generic_to_shared(su);
    int z = blockIdx.z, proj = z >> 3, b = z & 7;
    int o0 = blockIdx.y * 128, p0 = blockIdx.x * 128;
    const unsigned* gWh = &g_Whi[proj][0][0];
    const unsigned* gWl = &g_Wlo[proj][0][0];
    const unsigned* gXh = &g_XThi[b][0][0];
    const unsigned* gXl = &g_XTlo[b][0][0];
    const int tid = threadIdx.x, w = tid >> 5, lane = tid & 31;
    const int g = lane >> 2, q = lane & 3;
    const int tt = lane >> 3, rr = lane & 7;
    const int wo = w >> 2, wp = w & 3;

    float acc[4][4][4];
#pragma unroll
    for (int i = 0; i < 4; i++)
#pragma unroll
        for (int j = 0; j < 4; j++)
#pragma unroll
            for (int e = 0; e < 4; e++) acc[i][j][e] = 0.f;

#define G2_LOAD(c) do { \
        int _s = (c) & 1, _kk = (c) * 16; \
        uint32_t _sb = smb + 4 * (_s * G2_STAGE); \
        for (int t = tid; t < 512; t += 256) { \
            int r = t >> 2, f4 = (t & 3) * 4; \
            uint32_t d = _sb + 4 * (r * G2_STR + f4); \
            size_t wo_ = (size_t)(o0 + r) * 256 + _kk + f4; \
            size_t xo_ = (size_t)(p0 + r) * 256 + _kk + f4; \
            CP16(d,            gWh + wo_); \
            CP16(d + 4 * 2560, gWl + wo_); \
            CP16(d + 4 * 5120, gXh + xo_); \
            CP16(d + 4 * 7680, gXl + xo_); \
        } \
    } while (0)

    G2_LOAD(0);
    CP_COMMIT();

    const int fragRow = (tt & 1) * 8 + rr;
    const int fragCol = (tt >> 1) * 4;

    for (int c = 0; c < 16; c++) {
        if (c < 15) {
            G2_LOAD(c + 1);
            CP_COMMIT();
            CP_WAIT(1);
        } else {
            CP_WAIT(0);
        }
        __syncthreads();

        const int s = c & 1;
        const uint32_t aB = smb + 4 * (s * G2_STAGE + (wo * 64 + fragRow) * G2_STR + fragCol);
        const uint32_t bB = smb + 4 * (s * G2_STAGE + 5120 + (wp * 32 + fragRow) * G2_STR + fragCol);
#pragma unroll
        for (int ks = 0; ks < 2; ks++) {
            uint32_t a[4][4];
            uint32_t bh[2][4], bl[2][4];
#pragma unroll
            for (int nb = 0; nb < 2; nb++) {
                uint32_t ba = bB + 4 * (16 * nb * G2_STR + 8 * ks);
                LDSM4(bh[nb][0], bh[nb][1], bh[nb][2], bh[nb][3], ba);
                LDSM4(bl[nb][0], bl[nb][1], bl[nb][2], bl[nb][3], ba + 4 * 2560);
            }
#pragma unroll
            for (int mf = 0; mf < 4; mf++) {
                uint32_t aa = aB + 4 * (16 * mf * G2_STR + 8 * ks);
                LDSM4(a[mf][0], a[mf][1], a[mf][2], a[mf][3], aa);
            }
#pragma unroll
            for (int nb = 0; nb < 2; nb++)
#pragma unroll
                for (int mf = 0; mf < 4; mf++) {
                    mma16816(acc[mf][2 * nb],     a[mf][0], a[mf][1], a[mf][2], a[mf][3], bh[nb][0], bh[nb][2]);
                    mma16816(acc[mf][2 * nb],     a[mf][0], a[mf][1], a[mf][2], a[mf][3], bl[nb][0], bl[nb][2]);
                    mma16816(acc[mf][2 * nb + 1], a[mf][0], a[mf][1], a[mf][2], a[mf][3], bh[nb][1], bh[nb][3]);
                    mma16816(acc[mf][2 * nb + 1], a[mf][0], a[mf][1], a[mf][2], a[mf][3], bl[nb][1], bl[nb][3]);
                }
#pragma unroll
            for (int mf = 0; mf < 4; mf++) {
                uint32_t aa = aB + 4 * (2560 + 16 * mf * G2_STR + 8 * ks);
                LDSM4(a[mf][0], a[mf][1], a[mf][2], a[mf][3], aa);
            }
#pragma unroll
            for (int nb = 0; nb < 2; nb++)
#pragma unroll
                for (int mf = 0; mf < 4; mf++) {
                    mma16816(acc[mf][2 * nb],     a[mf][0], a[mf][1], a[mf][2], a[mf][3], bh[nb][0], bh[nb][2]);
                    mma16816(acc[mf][2 * nb + 1], a[mf][0], a[mf][1], a[mf][2], a[mf][3], bh[nb][1], bh[nb][3]);
                }
        }
        __syncthreads();
    }

    float* Y = &g_y[proj][b][0][0];
#pragma unroll
    for (int mf = 0; mf < 4; mf++)
#pragma unroll
        for (int nf = 0; nf < 4; nf++) {
            int oo = o0 + wo * 64 + 16 * mf + g;
            int pp = p0 + wp * 32 + 8 * nf + 2 * q;
            float* r0 = Y + (size_t)oo * PP + pp;
            *(float2*)r0 = make_float2(acc[mf][nf][0], acc[mf][nf][1]);
            *(float2*)(r0 + 8 * PP) = make_float2(acc[mf][nf][2], acc[mf][nf][3]);
        }
}

// ---------------- Stage 2: batch stats -> folded affine ----------------
__global__ __launch_bounds__(256) void stats_kernel(
    const float* __restrict__ gq, const float* __restrict__ bq,
    const float* __restrict__ gk, const float* __restrict__ bk,
    const float* __restrict__ gv, const float* __restrict__ bv)
{
    int o = blockIdx.x, proj = blockIdx.y;
    const float* base = &g_y[proj][0][o][0];
    float s = 0.f, s2 = 0.f;
    for (int t = threadIdx.x; t < BB * PP / 4; t += 256) {
        int b = t >> 9, p4 = (t & 511) * 4;
        float4 v = *(const float4*)&base[(size_t)b * COUT * PP + p4];
        s += v.x + v.y + v.z + v.w;
        s2 += v.x * v.x + v.y * v.y + v.z * v.z + v.w * v.w;
    }
    __shared__ float red0[256], red1[256];
    red0[threadIdx.x] = s; red1[threadIdx.x] = s2;
    __syncthreads();
    for (int st = 128; st > 0; st >>= 1) {
        if (threadIdx.x < st) {
            red0[threadIdx.x] += red0[threadIdx.x + st];
            red1[threadIdx.x] += red1[threadIdx.x + st];
        }
        __syncthreads();
    }
    if (threadIdx.x == 0) {
        const float invn = 1.f / (BB * PP);
        float mean = red0[0] * invn;
        float var = red1[0] * invn - mean * mean;
        const float* gg = (proj == 0) ? gq : ((proj == 1) ? gk : gv);
        const float* be = (proj == 0) ? bq : ((proj == 1) ? bk : bv);
        float sc = gg[o] * rsqrtf(var + 1e-5f);
        g_scale[proj][o] = sc;
        g_shift[proj][o] = be[o] - mean * sc;
    }
}

// ---------------- Stage 3: fold BN+LeakyReLU, emit split operands ----------
__global__ __launch_bounds__(256) void fold_kernel()
{
    __shared__ float sm[64][65];
    int p0 = blockIdx.x * 64, c0 = blockIdx.y * 64;
    int z = blockIdx.z, proj = z >> 3, b = z & 7;
    int tid = threadIdx.x;
    const float post = (proj == 1) ? K_ALPHA : 1.f;   // fold softmax scale into K
    for (int t = tid; t < 64 * 64; t += 256) {
        int c = t >> 6, p = t & 63;
        float v = g_y[proj][b][c0 + c][p0 + p];
        v = v * g_scale[proj][c0 + c] + g_shift[proj][c0 + c];
        v = (v >= 0.f) ? v : 0.1f * v;
        sm[c][p] = v * post;
    }
    __syncthreads();
    if (proj == 0) {
        for (int t = tid; t < 64 * 32; t += 256) {
            int c = t >> 5, jp = t & 31;
            unsigned hi, lo;
            split2(sm[c][2 * jp], sm[c][2 * jp + 1], hi, lo);
            size_t o = ((size_t)b * COUT + c0 + c) * 1024 + (p0 >> 1) + jp;
            (&g_Qhi[0][0][0])[o] = hi;
            (&g_Qlo[0][0][0])[o] = lo;
        }
    } else {
        int h = c0 >> 7, cpo = (c0 & 127) >> 1;
        unsigned* dh = (proj == 1) ? &g_KThi[0][0][0][0] : &g_VThi[0][0][0][0];
        unsigned* dl = (proj == 1) ? &g_KTlo[0][0][0][0] : &g_VTlo[0][0][0][0];
        for (int t = tid; t < 64 * 32; t += 256) {
            int p = t >> 5, cp = t & 31;
            unsigned hi, lo;
            split2(sm[2 * cp][p], sm[2 * cp + 1][p], hi, lo);
            size_t o = ((size_t)(b * NH + h) * PP + p0 + p) * 64 + cpo + cp;
            dh[o] = hi;
            dl[o] = lo;
        }
    }
}

// ---------------- Stage 4: mma.sync flash attention v3 ----------------
// smem (u32): KH 0 (128x68), KL 8704, V 17408 (Vh 4352 + Vl 4352, single buf),
// Q 26112 (2 bufs x 9216; QL at +4608), PH 44544, PL 49152, LR 53760.
#define OFF_KH 0
#define OFF_KL 8704
#define OFF_V  17408
#define OFF_Q  26112
#define OFF_PH 44544
#define OFF_PL 49152
#define OFF_LR 53760
#define ATTN3_SMEM ((53760 + 128) * 4)

__global__ __launch_bounds__(256) void attn3_kernel(float* __restrict__ out)
{
    extern __shared__ unsigned sm[];
    uint32_t smb = (uint32_t)__cvta_generic_to_shared(sm);
    const int tid = threadIdx.x;
    const int w = tid >> 5, lane = tid & 31;
    const int g = lane >> 2, q = lane & 3;
    const int tt = lane >> 3, rr = lane & 7;
    const int bh = blockIdx.y, b = bh >> 3, h = bh & 7;
    const int i0 = blockIdx.x * 128;

    const unsigned* gKh = &g_KThi[b][h][0][0];
    const unsigned* gKl = &g_KTlo[b][h][0][0];
    const unsigned* gVh = &g_VThi[b][h][0][0];
    const unsigned* gVl = &g_VTlo[b][h][0][0];
    const unsigned* gQh = &g_Qhi[b][h * 128][0];
    const unsigned* gQl = &g_Qlo[b][h * 128][0];

    // prologue: K, V(0), Q(0)->buf0  (one commit group)
    for (int t = tid; t < 2048; t += 256) {
        int r = t >> 4, f4 = (t & 15) * 4;
        uint32_t d = smb + 4 * (OFF_KH + r * 68 + f4);
        size_t so = (size_t)(i0 + r) * 64 + f4;
        CP16(d, gKh + so);
        CP16(d + 4 * 8704, gKl + so);
    }
    for (int t = tid; t < 1024; t += 256) {
        int r = t >> 4, f4 = (t & 15) * 4;
        uint32_t d = smb + 4 * (OFF_V + r * 68 + f4);
        size_t so = (size_t)r * 64 + f4;
        CP16(d, gVh + so);
        CP16(d + 4 * 4352, gVl + so);
    }
    for (int t = tid; t < 1024; t += 256) {
        int r = t >> 3, f4 = (t & 7) * 4;
        uint32_t d = smb + 4 * (OFF_Q + r * 36 + f4);
        size_t so = (size_t)r * 1024 + f4;
        CP16(d, gQh + so);
        CP16(d + 4 * 4608, gQl + so);
    }
    CP_COMMIT();

    float oacc[8][2][4];
#pragma unroll
    for (int mf = 0; mf < 8; mf++)
#pragma unroll
        for (int nf = 0; nf < 2; nf++)
#pragma unroll
            for (int e = 0; e < 4; e++) oacc[mf][nf][e] = 0.f;
    float l0 = 0.f, l1 = 0.f;

    const int aRow = 16 * w + (tt & 1) * 8 + rr;
    const int aCol = (tt >> 1) * 4;
    const int bRow0 = (tt & 1) * 8 + rr;

    for (int jt = 0; jt < 32; jt++) {
        const int qb = jt & 1;
        CP_WAIT(0);
        __syncthreads();                       // V(jt), Q(jt) resident

        // ---- S = K_i^T V_j (K pre-scaled by log2e/sqrt(dh)) ----
        float sacc[8][4];
#pragma unroll
        for (int nf = 0; nf < 8; nf++)
#pragma unroll
            for (int e = 0; e < 4; e++) sacc[nf][e] = 0.f;

        const uint32_t aBaseH = smb + 4 * (OFF_KH + aRow * 68 + aCol);
        const uint32_t vBase = smb + 4 * (OFF_V + bRow0 * 68 + aCol);
#pragma unroll
        for (int ks = 0; ks < 8; ks++) {
            uint32_t ah0, ah1, ah2, ah3, al0, al1, al2, al3;
            LDSM4(ah0, ah1, ah2, ah3, aBaseH + 32 * ks);
            LDSM4(al0, al1, al2, al3, aBaseH + 4 * 8704 + 32 * ks);
#pragma unroll
            for (int nb = 0; nb < 4; nb++) {
                uint32_t vh0, vh1, vh2, vh3, vl0, vl1, vl2, vl3;
                uint32_t vb = vBase + 4 * (nb * 16 * 68) + 32 * ks;
                LDSM4(vh0, vh1, vh2, vh3, vb);
                LDSM4(vl0, vl1, vl2, vl3, vb + 4 * 4352);
                mma16816(sacc[2 * nb],     ah0, ah1, ah2, ah3, vh0, vh2);
                mma16816(sacc[2 * nb],     al0, al1, al2, al3, vh0, vh2);
                mma16816(sacc[2 * nb],     ah0, ah1, ah2, ah3, vl0, vl2);
                mma16816(sacc[2 * nb + 1], ah0, ah1, ah2, ah3, vh1, vh3);
                mma16816(sacc[2 * nb + 1], al0, al1, al2, al3, vh1, vh3);
                mma16816(sacc[2 * nb + 1], ah0, ah1, ah2, ah3, vl1, vl3);
            }
        }
        __syncthreads();                       // all warps done reading V

        // prefetch V(jt+1) (single buf) + Q(jt+1) (alt buf), one group
        if (jt < 31) {
            const int jn = (jt + 1) * 64;
            for (int t = tid; t < 1024; t += 256) {
                int r = t >> 4, f4 = (t & 15) * 4;
                uint32_t d = smb + 4 * (OFF_V + r * 68 + f4);
                size_t so = (size_t)(jn + r) * 64 + f4;
                CP16(d, gVh + so);
                CP16(d + 4 * 4352, gVl + so);
            }
            for (int t = tid; t < 1024; t += 256) {
                int r = t >> 3, f4 = (t & 7) * 4;
                uint32_t d = smb + 4 * (OFF_Q + (qb ^ 1) * 9216 + r * 36 + f4);
                size_t so = (size_t)r * 1024 + (jn >> 1) + f4;
                CP16(d, gQh + so);
                CP16(d + 4 * 4608, gQl + so);
            }
            CP_COMMIT();
        }

        // ---- softmax: P = exp2(sacc) ; warp-local rows ----
#pragma unroll
        for (int nf = 0; nf < 8; nf++) {
            float e0 = fex2(sacc[nf][0]);
            float e1 = fex2(sacc[nf][1]);
            float e2 = fex2(sacc[nf][2]);
            float e3 = fex2(sacc[nf][3]);
            l0 += e0 + e1;
            l1 += e2 + e3;
            unsigned hi, lo;
            int jp = 4 * nf + q;
            split2(e0, e1, hi, lo);
            sm[OFF_PH + (16 * w + g) * 36 + jp] = hi;
            sm[OFF_PL + (16 * w + g) * 36 + jp] = lo;
            split2(e2, e3, hi, lo);
            sm[OFF_PH + (16 * w + 8 + g) * 36 + jp] = hi;
            sm[OFF_PL + (16 * w + 8 + g) * 36 + jp] = lo;
        }
        __syncwarp();                          // P is warp-local: no block sync

        // ---- O += Q_j P^T ----
        const uint32_t pBase = smb + 4 * (OFF_PH + aRow * 36 + aCol);
        const uint32_t qBase = smb + 4 * (OFF_Q + qb * 9216 + bRow0 * 36 + aCol);
#pragma unroll
        for (int ks = 0; ks < 4; ks++) {
            uint32_t ph0, ph1, ph2, ph3, pl0, pl1, pl2, pl3;
            LDSM4(ph0, ph1, ph2, ph3, pBase + 32 * ks);
            LDSM4(pl0, pl1, pl2, pl3, pBase + 4 * 4608 + 32 * ks);
#pragma unroll
            for (int mf = 0; mf < 8; mf++) {
                uint32_t qh0, qh1, qh2, qh3, ql0, ql1, ql2, ql3;
                uint32_t qa = qBase + 4 * (16 * mf * 36) + 32 * ks;
                LDSM4(qh0, qh1, qh2, qh3, qa);
                LDSM4(ql0, ql1, ql2, ql3, qa + 4 * 4608);
                mma16816(oacc[mf][0], qh0, qh1, qh2, qh3, ph0, ph2);
                mma16816(oacc[mf][0], ql0, ql1, ql2, ql3, ph0, ph2);
                mma16816(oacc[mf][0], qh0, qh1, qh2, qh3, pl0, pl2);
                mma16816(oacc[mf][1], qh0, qh1, qh2, qh3, ph1, ph3);
                mma16816(oacc[mf][1], ql0, ql1, ql2, ql3, ph1, ph3);
                mma16816(oacc[mf][1], qh0, qh1, qh2, qh3, pl1, pl3);
            }
        }
        // no end-of-iter barrier: next top sync + CP_WAIT(0) protects buffers
    }

    l0 += __shfl_xor_sync(0xffffffffu, l0, 1);
    l0 += __shfl_xor_sync(0xffffffffu, l0, 2);
    l1 += __shfl_xor_sync(0xffffffffu, l1, 1);
    l1 += __shfl_xor_sync(0xffffffffu, l1, 2);
    float* lrow = (float*)&sm[OFF_LR];
    if (q == 0) {
        lrow[16 * w + g] = 1.f / l0;
        lrow[16 * w + 8 + g] = 1.f / l1;
    }
    __syncthreads();
#pragma unroll
    for (int nf = 0; nf < 2; nf++) {
        int ic = 16 * w + 8 * nf + 2 * q;
        float il0 = lrow[ic], il1 = lrow[ic + 1];
#pragma unroll
        for (int mf = 0; mf < 8; mf++) {
            int c = h * 128 + 16 * mf + g;
            float* p0 = out + ((size_t)b * COUT + c) * PP + i0 + ic;
            *(float2*)p0 = make_float2(oacc[mf][nf][0] * il0, oacc[mf][nf][1] * il1);
            float* p1 = p0 + 8 * PP;
            *(float2*)p1 = make_float2(oacc[mf][nf][2] * il0, oacc[mf][nf][3] * il1);
        }
    }
}

// ---------------------------------------------------------------------------
extern "C" void kernel_launch(void* const* d_in, const int* in_sizes, int n_in,
                              void* d_out, int out_size)
{
    const float* x  = (const float*)d_in[0];
    const float* Wq = (const float*)d_in[1];
    const float* gq = (const float*)d_in[2];
    const float* bq = (const float*)d_in[3];
    const float* Wk = (const float*)d_in[4];
    const float* gk = (const float*)d_in[5];
    const float* bk = (const float*)d_in[6];
    const float* Wv = (const float*)d_in[7];
    const float* gv = (const float*)d_in[8];
    const float* bv = (const float*)d_in[9];
    float* out = (float*)d_out;

    conv_w_kernel<<<3 * COUT * (CIN / 2) / 256, 256>>>(Wq, Wk, Wv);
    conv_x_kernel<<<dim3(PP / 64, CIN / 64, BB), 256>>>(x);

    cudaFuncSetAttribute(gemm1b_kernel, cudaFuncAttributeMaxDynamicSharedMemorySize, G2_SMEM);
    gemm1b_kernel<<<dim3(PP / 128, COUT / 128, 3 * BB), 256, G2_SMEM>>>();

    stats_kernel<<<dim3(COUT, 3), 256>>>(gq, bq, gk, bk, gv, bv);
    fold_kernel<<<dim3(PP / 64, COUT / 64, 3 * BB), 256>>>();

    cudaFuncSetAttribute(attn3_kernel, cudaFuncAttributeMaxDynamicSharedMemorySize, ATTN3_SMEM);
    attn3_kernel<<<dim3(PP / 128, BB * NH), 256, ATTN3_SMEM>>>(out);
}

// round 9
// speedup vs baseline: 6.2363x; 1.0335x over previous
#include <cuda_runtime.h>
#include <cuda_bf16.h>
#include <math.h>
#include <stdint.h>

#define BB 8
#define CIN 512
#define COUT 1024
#define PP 2048
#define NH 8
#define DH 128

// ---------------- scratch (device globals; no allocations) ----------------
__device__ float    g_y[3][BB][COUT][PP];       // fp32 projections (pre-BN)
__device__ float    g_scale[3][COUT];
__device__ float    g_shift[3][COUT];
__device__ unsigned g_Whi[3][COUT][CIN/2];      // W split bf16 pairs along c
__device__ unsigned g_Wlo[3][COUT][CIN/2];
__device__ unsigned g_XThi[BB][PP][CIN/2];      // x^T split pairs along c
__device__ unsigned g_XTlo[BB][PP][CIN/2];
__device__ unsigned g_Qhi[BB][COUT][PP/2];      // Q (post-BN) pairs along p
__device__ unsigned g_Qlo[BB][COUT][PP/2];
__device__ unsigned g_KThi[BB][NH][PP][DH/2];   // K^T per head (pre-scaled), pairs along c
__device__ unsigned g_KTlo[BB][NH][PP][DH/2];
__device__ unsigned g_VThi[BB][NH][PP][DH/2];   // V^T per head, pairs along c
__device__ unsigned g_VTlo[BB][NH][PP][DH/2];

// log2(e) / sqrt(128): folded into K so softmax is a bare ex2
#define K_ALPHA 0.12751743f

// ---------------- helpers ----------------
__device__ __forceinline__ void split2(float x0, float x1, unsigned& hi, unsigned& lo) {
    unsigned u0 = __float_as_uint(x0), u1 = __float_as_uint(x1);
    hi = __byte_perm(u0, u1, 0x7632);
    float h0 = __uint_as_float(u0 & 0xffff0000u);
    float h1 = __uint_as_float(u1 & 0xffff0000u);
    float l0 = x0 - h0, l1 = x1 - h1;
    asm("cvt.rn.bf16x2.f32 %0, %1, %2;" : "=r"(lo) : "f"(l1), "f"(l0));
}
__device__ __forceinline__ float fex2(float x) {
    float y;
    asm("ex2.approx.ftz.f32 %0, %1;" : "=f"(y) : "f"(x));
    return y;
}
__device__ __forceinline__ void mma16816(float* c,
    unsigned a0, unsigned a1, unsigned a2, unsigned a3, unsigned b0, unsigned b1)
{
    asm volatile(
        "mma.sync.aligned.m16n8k16.row.col.f32.bf16.bf16.f32 "
        "{%0,%1,%2,%3}, {%4,%5,%6,%7}, {%8,%9}, {%0,%1,%2,%3};\n"
        : "+f"(c[0]), "+f"(c[1]), "+f"(c[2]), "+f"(c[3])
        : "r"(a0), "r"(a1), "r"(a2), "r"(a3), "r"(b0), "r"(b1));
}

#define CP16(d, s) asm volatile("cp.async.cg.shared.global [%0], [%1], 16;" :: "r"(d), "l"(s) : "memory")
#define CP_COMMIT() asm volatile("cp.async.commit_group;" ::: "memory")
#define CP_WAIT(n)  asm volatile("cp.async.wait_group %0;" :: "n"(n) : "memory")
#define LDSM4(r0, r1, r2, r3, a) \
    asm volatile("ldmatrix.sync.aligned.m8n8.x4.shared.b16 {%0,%1,%2,%3}, [%4];" \
        : "=r"(r0), "=r"(r1), "=r"(r2), "=r"(r3) : "r"(a))

// ---------------- conv W -> split bf16 pairs ----------------
__global__ __launch_bounds__(256) void conv_w_kernel(
    const float* __restrict__ Wq, const float* __restrict__ Wk, const float* __restrict__ Wv)
{
    int idx = blockIdx.x * 256 + threadIdx.x;
    int proj = idx >> 18;
    int rem = idx & 262143;
    const float* W = (proj == 0) ? Wq : ((proj == 1) ? Wk : Wv);
    float2 v = *(const float2*)(W + (size_t)rem * 2);
    unsigned hi, lo;
    split2(v.x, v.y, hi, lo);
    (&g_Whi[0][0][0])[(size_t)proj * 262144 + rem] = hi;
    (&g_Wlo[0][0][0])[(size_t)proj * 262144 + rem] = lo;
}

// ---------------- conv x -> x^T split pairs ----------------
__global__ __launch_bounds__(256) void conv_x_kernel(const float* __restrict__ x)
{
    __shared__ float sm[64][65];
    int p0 = blockIdx.x * 64, c0 = blockIdx.y * 64, b = blockIdx.z;
    int tid = threadIdx.x;
    for (int t = tid; t < 64 * 64; t += 256) {
        int c = t >> 6, p = t & 63;
        sm[c][p] = x[((size_t)b * CIN + c0 + c) * PP + p0 + p];
    }
    __syncthreads();
    for (int t = tid; t < 64 * 32; t += 256) {
        int p = t >> 5, cp = t & 31;
        unsigned hi, lo;
        split2(sm[2 * cp][p], sm[2 * cp + 1][p], hi, lo);
        size_t o = ((size_t)b * PP + p0 + p) * 256 + (c0 >> 1) + cp;
        (&g_XThi[0][0][0])[o] = hi;
        (&g_XTlo[0][0][0])[o] = lo;
    }
}

// ---------------- Stage 1: cp.async + ldmatrix GEMM  y = W * x ---------
#define G2_STR 20
#define G2_STAGE 10240
#define G2_SMEM (2 * G2_STAGE * 4)

__global__ __launch_bounds__(256, 2) void gemm1b_kernel()
{
    extern __shared__ unsigned su[];
    uint32_t smb = (uint32_t)__cvta_generic_to_shared(su);
    int z = blockIdx.z, proj = z >> 3, b = z & 7;
    int o0 = blockIdx.y * 128, p0 = blockIdx.x * 128;
    const unsigned* gWh = &g_Whi[proj][0][0];
    const unsigned* gWl = &g_Wlo[proj][0][0];
    const unsigned* gXh = &g_XThi[b][0][0];
    const unsigned* gXl = &g_XTlo[b][0][0];
    const int tid = threadIdx.x, w = tid >> 5, lane = tid & 31;
    const int g = lane >> 2, q = lane & 3;
    const int tt = lane >> 3, rr = lane & 7;
    const int wo = w >> 2, wp = w & 3;

    float acc[4][4][4];
#pragma unroll
    for (int i = 0; i < 4; i++)
#pragma unroll
        for (int j = 0; j < 4; j++)
#pragma unroll
            for (int e = 0; e < 4; e++) acc[i][j][e] = 0.f;

#define G2_LOAD(c) do { \
        int _s = (c) & 1, _kk = (c) * 16; \
        uint32_t _sb = smb + 4 * (_s * G2_STAGE); \
        for (int t = tid; t < 512; t += 256) { \
            int r = t >> 2, f4 = (t & 3) * 4; \
            uint32_t d = _sb + 4 * (r * G2_STR + f4); \
            size_t wo_ = (size_t)(o0 + r) * 256 + _kk + f4; \
            size_t xo_ = (size_t)(p0 + r) * 256 + _kk + f4; \
            CP16(d,            gWh + wo_); \
            CP16(d + 4 * 2560, gWl + wo_); \
            CP16(d + 4 * 5120, gXh + xo_); \
            CP16(d + 4 * 7680, gXl + xo_); \
        } \
    } while (0)

    G2_LOAD(0);
    CP_COMMIT();

    const int fragRow = (tt & 1) * 8 + rr;
    const int fragCol = (tt >> 1) * 4;

    for (int c = 0; c < 16; c++) {
        if (c < 15) {
            G2_LOAD(c + 1);
            CP_COMMIT();
            CP_WAIT(1);
        } else {
            CP_WAIT(0);
        }
        __syncthreads();

        const int s = c & 1;
        const uint32_t aB = smb + 4 * (s * G2_STAGE + (wo * 64 + fragRow) * G2_STR + fragCol);
        const uint32_t bB = smb + 4 * (s * G2_STAGE + 5120 + (wp * 32 + fragRow) * G2_STR + fragCol);
#pragma unroll
        for (int ks = 0; ks < 2; ks++) {
            uint32_t a[4][4];
            uint32_t bh[2][4], bl[2][4];
#pragma unroll
            for (int nb = 0; nb < 2; nb++) {
                uint32_t ba = bB + 4 * (16 * nb * G2_STR + 8 * ks);
                LDSM4(bh[nb][0], bh[nb][1], bh[nb][2], bh[nb][3], ba);
                LDSM4(bl[nb][0], bl[nb][1], bl[nb][2], bl[nb][3], ba + 4 * 2560);
            }
#pragma unroll
            for (int mf = 0; mf < 4; mf++) {
                uint32_t aa = aB + 4 * (16 * mf * G2_STR + 8 * ks);
                LDSM4(a[mf][0], a[mf][1], a[mf][2], a[mf][3], aa);
            }
#pragma unroll
            for (int nb = 0; nb < 2; nb++)
#pragma unroll
                for (int mf = 0; mf < 4; mf++) {
                    mma16816(acc[mf][2 * nb],     a[mf][0], a[mf][1], a[mf][2], a[mf][3], bh[nb][0], bh[nb][2]);
                    mma16816(acc[mf][2 * nb],     a[mf][0], a[mf][1], a[mf][2], a[mf][3], bl[nb][0], bl[nb][2]);
                    mma16816(acc[mf][2 * nb + 1], a[mf][0], a[mf][1], a[mf][2], a[mf][3], bh[nb][1], bh[nb][3]);
                    mma16816(acc[mf][2 * nb + 1], a[mf][0], a[mf][1], a[mf][2], a[mf][3], bl[nb][1], bl[nb][3]);
                }
#pragma unroll
            for (int mf = 0; mf < 4; mf++) {
                uint32_t aa = aB + 4 * (2560 + 16 * mf * G2_STR + 8 * ks);
                LDSM4(a[mf][0], a[mf][1], a[mf][2], a[mf][3], aa);
            }
#pragma unroll
            for (int nb = 0; nb < 2; nb++)
#pragma unroll
                for (int mf = 0; mf < 4; mf++) {
                    mma16816(acc[mf][2 * nb],     a[mf][0], a[mf][1], a[mf][2], a[mf][3], bh[nb][0], bh[nb][2]);
                    mma16816(acc[mf][2 * nb + 1], a[mf][0], a[mf][1], a[mf][2], a[mf][3], bh[nb][1], bh[nb][3]);
                }
        }
        __syncthreads();
    }

    float* Y = &g_y[proj][b][0][0];
#pragma unroll
    for (int mf = 0; mf < 4; mf++)
#pragma unroll
        for (int nf = 0; nf < 4; nf++) {
            int oo = o0 + wo * 64 + 16 * mf + g;
            int pp = p0 + wp * 32 + 8 * nf + 2 * q;
            float* r0 = Y + (size_t)oo * PP + pp;
            *(float2*)r0 = make_float2(acc[mf][nf][0], acc[mf][nf][1]);
            *(float2*)(r0 + 8 * PP) = make_float2(acc[mf][nf][2], acc[mf][nf][3]);
        }
}

// ---------------- Stage 2: batch stats -> folded affine ----------------
__global__ __launch_bounds__(256) void stats_kernel(
    const float* __restrict__ gq, const float* __restrict__ bq,
    const float* __restrict__ gk, const float* __restrict__ bk,
    const float* __restrict__ gv, const float* __restrict__ bv)
{
    int o = blockIdx.x, proj = blockIdx.y;
    const float* base = &g_y[proj][0][o][0];
    float s = 0.f, s2 = 0.f;
    for (int t = threadIdx.x; t < BB * PP / 4; t += 256) {
        int b = t >> 9, p4 = (t & 511) * 4;
        float4 v = *(const float4*)&base[(size_t)b * COUT * PP + p4];
        s += v.x + v.y + v.z + v.w;
        s2 += v.x * v.x + v.y * v.y + v.z * v.z + v.w * v.w;
    }
    __shared__ float red0[256], red1[256];
    red0[threadIdx.x] = s; red1[threadIdx.x] = s2;
    __syncthreads();
    for (int st = 128; st > 0; st >>= 1) {
        if (threadIdx.x < st) {
            red0[threadIdx.x] += red0[threadIdx.x + st];
            red1[threadIdx.x] += red1[threadIdx.x + st];
        }
        __syncthreads();
    }
    if (threadIdx.x == 0) {
        const float invn = 1.f / (BB * PP);
        float mean = red0[0] * invn;
        float var = red1[0] * invn - mean * mean;
        const float* gg = (proj == 0) ? gq : ((proj == 1) ? gk : gv);
        const float* be = (proj == 0) ? bq : ((proj == 1) ? bk : bv);
        float sc = gg[o] * rsqrtf(var + 1e-5f);
        g_scale[proj][o] = sc;
        g_shift[proj][o] = be[o] - mean * sc;
    }
}

// ---------------- Stage 3: fold BN+LeakyReLU, emit split operands ----------
__global__ __launch_bounds__(256) void fold_kernel()
{
    __shared__ float sm[64][65];
    int p0 = blockIdx.x * 64, c0 = blockIdx.y * 64;
    int z = blockIdx.z, proj = z >> 3, b = z & 7;
    int tid = threadIdx.x;
    const float post = (proj == 1) ? K_ALPHA : 1.f;
    for (int t = tid; t < 64 * 64; t += 256) {
        int c = t >> 6, p = t & 63;
        float v = g_y[proj][b][c0 + c][p0 + p];
        v = v * g_scale[proj][c0 + c] + g_shift[proj][c0 + c];
        v = (v >= 0.f) ? v : 0.1f * v;
        sm[c][p] = v * post;
    }
    __syncthreads();
    if (proj == 0) {
        for (int t = tid; t < 64 * 32; t += 256) {
            int c = t >> 5, jp = t & 31;
            unsigned hi, lo;
            split2(sm[c][2 * jp], sm[c][2 * jp + 1], hi, lo);
            size_t o = ((size_t)b * COUT + c0 + c) * 1024 + (p0 >> 1) + jp;
            (&g_Qhi[0][0][0])[o] = hi;
            (&g_Qlo[0][0][0])[o] = lo;
        }
    } else {
        int h = c0 >> 7, cpo = (c0 & 127) >> 1;
        unsigned* dh = (proj == 1) ? &g_KThi[0][0][0][0] : &g_VThi[0][0][0][0];
        unsigned* dl = (proj == 1) ? &g_KTlo[0][0][0][0] : &g_VTlo[0][0][0][0];
        for (int t = tid; t < 64 * 32; t += 256) {
            int p = t >> 5, cp = t & 31;
            unsigned hi, lo;
            split2(sm[2 * cp][p], sm[2 * cp + 1][p], hi, lo);
            size_t o = ((size_t)(b * NH + h) * PP + p0 + p) * 64 + cpo + cp;
            dh[o] = hi;
            dl[o] = lo;
        }
    }
}

// ---------------- Stage 4: mma.sync flash attention v4 ----------------
// K A-fragments live in registers (loaded once via staging through V region).
// smem (u32): V 0 (2 bufs x 8704: Vh 4352 + Vl 4352)  [prologue: Khi@0, Klo@8704]
//             Q 17408 (2 bufs x 9216; QL at +4608)
//             PH 35840 (4608), PL 40448 (4608), LR 45056 (128)
#define OFF_V  0
#define OFF_Q  17408
#define OFF_PH 35840
#define OFF_PL 40448
#define OFF_LR 45056
#define ATTN4_SMEM ((45056 + 128) * 4)

__global__ __launch_bounds__(256) void attn4_kernel(float* __restrict__ out)
{
    extern __shared__ unsigned sm[];
    uint32_t smb = (uint32_t)__cvta_generic_to_shared(sm);
    const int tid = threadIdx.x;
    const int w = tid >> 5, lane = tid & 31;
    const int g = lane >> 2, q = lane & 3;
    const int tt = lane >> 3, rr = lane & 7;
    const int bh = blockIdx.y, b = bh >> 3, h = bh & 7;
    const int i0 = blockIdx.x * 128;

    const unsigned* gKh = &g_KThi[b][h][0][0];
    const unsigned* gKl = &g_KTlo[b][h][0][0];
    const unsigned* gVh = &g_VThi[b][h][0][0];
    const unsigned* gVl = &g_VTlo[b][h][0][0];
    const unsigned* gQh = &g_Qhi[b][h * 128][0];
    const unsigned* gQl = &g_Qlo[b][h * 128][0];

    const int aRow = 16 * w + (tt & 1) * 8 + rr;
    const int aCol = (tt >> 1) * 4;
    const int bRow0 = (tt & 1) * 8 + rr;

    // ---- prologue: stage K through V region, extract A-fragments to regs ----
    for (int t = tid; t < 2048; t += 256) {
        int r = t >> 4, f4 = (t & 15) * 4;
        uint32_t d = smb + 4 * (OFF_V + r * 68 + f4);
        size_t so = (size_t)(i0 + r) * 64 + f4;
        CP16(d, gKh + so);
        CP16(d + 4 * 8704, gKl + so);
    }
    CP_COMMIT();
    CP_WAIT(0);
    __syncthreads();

    unsigned kh[8][4], kl[8][4];
    {
        const uint32_t kB = smb + 4 * (OFF_V + aRow * 68 + aCol);
#pragma unroll
        for (int ks = 0; ks < 8; ks++) {
            LDSM4(kh[ks][0], kh[ks][1], kh[ks][2], kh[ks][3], kB + 32 * ks);
            LDSM4(kl[ks][0], kl[ks][1], kl[ks][2], kl[ks][3], kB + 4 * 8704 + 32 * ks);
        }
    }
    __syncthreads();

    // V(0) -> buf0, Q(0) -> qbuf0
    for (int t = tid; t < 1024; t += 256) {
        int r = t >> 4, f4 = (t & 15) * 4;
        uint32_t d = smb + 4 * (OFF_V + r * 68 + f4);
        size_t so = (size_t)r * 64 + f4;
        CP16(d, gVh + so);
        CP16(d + 4 * 4352, gVl + so);
    }
    for (int t = tid; t < 1024; t += 256) {
        int r = t >> 3, f4 = (t & 7) * 4;
        uint32_t d = smb + 4 * (OFF_Q + r * 36 + f4);
        size_t so = (size_t)r * 1024 + f4;
        CP16(d, gQh + so);
        CP16(d + 4 * 4608, gQl + so);
    }
    CP_COMMIT();

    float oacc[8][2][4];
#pragma unroll
    for (int mf = 0; mf < 8; mf++)
#pragma unroll
        for (int nf = 0; nf < 2; nf++)
#pragma unroll
            for (int e = 0; e < 4; e++) oacc[mf][nf][e] = 0.f;
    float l0 = 0.f, l1 = 0.f;

    for (int jt = 0; jt < 32; jt++) {
        const int qb = jt & 1;
        CP_WAIT(0);
        __syncthreads();                 // V(jt), Q(jt) resident everywhere

        // prefetch V(jt+1)/Q(jt+1) into alternate buffers immediately:
        // safe (barrier above proves all warps finished iter jt-1)
        if (jt < 31) {
            const int jn = (jt + 1) * 64;
            for (int t = tid; t < 1024; t += 256) {
                int r = t >> 4, f4 = (t & 15) * 4;
                uint32_t d = smb + 4 * (OFF_V + (qb ^ 1) * 8704 + r * 68 + f4);
                size_t so = (size_t)(jn + r) * 64 + f4;
                CP16(d, gVh + so);
                CP16(d + 4 * 4352, gVl + so);
            }
            for (int t = tid; t < 1024; t += 256) {
                int r = t >> 3, f4 = (t & 7) * 4;
                uint32_t d = smb + 4 * (OFF_Q + (qb ^ 1) * 9216 + r * 36 + f4);
                size_t so = (size_t)r * 1024 + (jn >> 1) + f4;
                CP16(d, gQh + so);
                CP16(d + 4 * 4608, gQl + so);
            }
            CP_COMMIT();
        }

        // ---- S = K_i^T V_j (K fragments in registers) ----
        float sacc[8][4];
#pragma unroll
        for (int nf = 0; nf < 8; nf++)
#pragma unroll
            for (int e = 0; e < 4; e++) sacc[nf][e] = 0.f;

        const uint32_t vBase = smb + 4 * (OFF_V + qb * 8704 + bRow0 * 68 + aCol);
#pragma unroll
        for (int ks = 0; ks < 8; ks++) {
#pragma unroll
            for (int nb = 0; nb < 4; nb++) {
                uint32_t vh0, vh1, vh2, vh3, vl0, vl1, vl2, vl3;
                uint32_t vb = vBase + 4 * (nb * 16 * 68) + 32 * ks;
                LDSM4(vh0, vh1, vh2, vh3, vb);
                LDSM4(vl0, vl1, vl2, vl3, vb + 4 * 4352);
                mma16816(sacc[2 * nb],     kh[ks][0], kh[ks][1], kh[ks][2], kh[ks][3], vh0, vh2);
                mma16816(sacc[2 * nb],     kl[ks][0], kl[ks][1], kl[ks][2], kl[ks][3], vh0, vh2);
                mma16816(sacc[2 * nb],     kh[ks][0], kh[ks][1], kh[ks][2], kh[ks][3], vl0, vl2);
                mma16816(sacc[2 * nb + 1], kh[ks][0], kh[ks][1], kh[ks][2], kh[ks][3], vh1, vh3);
                mma16816(sacc[2 * nb + 1], kl[ks][0], kl[ks][1], kl[ks][2], kl[ks][3], vh1, vh3);
                mma16816(sacc[2 * nb + 1], kh[ks][0], kh[ks][1], kh[ks][2], kh[ks][3], vl1, vl3);
            }
        }

        // ---- softmax: P = exp2(sacc); warp-local rows ----
#pragma unroll
        for (int nf = 0; nf < 8; nf++) {
            float e0 = fex2(sacc[nf][0]);
            float e1 = fex2(sacc[nf][1]);
            float e2 = fex2(sacc[nf][2]);
            float e3 = fex2(sacc[nf][3]);
            l0 += e0 + e1;
            l1 += e2 + e3;
            unsigned hi, lo;
            int jp = 4 * nf + q;
            split2(e0, e1, hi, lo);
            sm[OFF_PH + (16 * w + g) * 36 + jp] = hi;
            sm[OFF_PL + (16 * w + g) * 36 + jp] = lo;
            split2(e2, e3, hi, lo);
            sm[OFF_PH + (16 * w + 8 + g) * 36 + jp] = hi;
            sm[OFF_PL + (16 * w + 8 + g) * 36 + jp] = lo;
        }
        __syncwarp();

        // ---- O += Q_j P^T ----
        const uint32_t pBase = smb + 4 * (OFF_PH + aRow * 36 + aCol);
        const uint32_t qBase = smb + 4 * (OFF_Q + qb * 9216 + bRow0 * 36 + aCol);
#pragma unroll
        for (int ks = 0; ks < 4; ks++) {
            uint32_t ph0, ph1, ph2, ph3, pl0, pl1, pl2, pl3;
            LDSM4(ph0, ph1, ph2, ph3, pBase + 32 * ks);
            LDSM4(pl0, pl1, pl2, pl3, pBase + 4 * 4608 + 32 * ks);
#pragma unroll
            for (int mf = 0; mf < 8; mf++) {
                uint32_t qh0, qh1, qh2, qh3, ql0, ql1, ql2, ql3;
                uint32_t qa = qBase + 4 * (16 * mf * 36) + 32 * ks;
                LDSM4(qh0, qh1, qh2, qh3, qa);
                LDSM4(ql0, ql1, ql2, ql3, qa + 4 * 4608);
                mma16816(oacc[mf][0], qh0, qh1, qh2, qh3, ph0, ph2);
                mma16816(oacc[mf][0], ql0, ql1, ql2, ql3, ph0, ph2);
                mma16816(oacc[mf][0], qh0, qh1, qh2, qh3, pl0, pl2);
                mma16816(oacc[mf][1], qh0, qh1, qh2, qh3, ph1, ph3);
                mma16816(oacc[mf][1], ql0, ql1, ql2, ql3, ph1, ph3);
                mma16816(oacc[mf][1], qh0, qh1, qh2, qh3, pl1, pl3);
            }
        }
    }

    l0 += __shfl_xor_sync(0xffffffffu, l0, 1);
    l0 += __shfl_xor_sync(0xffffffffu, l0, 2);
    l1 += __shfl_xor_sync(0xffffffffu, l1, 1);
    l1 += __shfl_xor_sync(0xffffffffu, l1, 2);
    float* lrow = (float*)&sm[OFF_LR];
    if (q == 0) {
        lrow[16 * w + g] = 1.f / l0;
        lrow[16 * w + 8 + g] = 1.f / l1;
    }
    __syncthreads();
#pragma unroll
    for (int nf = 0; nf < 2; nf++) {
        int ic = 16 * w + 8 * nf + 2 * q;
        float il0 = lrow[ic], il1 = lrow[ic + 1];
#pragma unroll
        for (int mf = 0; mf < 8; mf++) {
            int c = h * 128 + 16 * mf + g;
            float* p0 = out + ((size_t)b * COUT + c) * PP + i0 + ic;
            *(float2*)p0 = make_float2(oacc[mf][nf][0] * il0, oacc[mf][nf][1] * il1);
            float* p1 = p0 + 8 * PP;
            *(float2*)p1 = make_float2(oacc[mf][nf][2] * il0, oacc[mf][nf][3] * il1);
        }
    }
}

// ---------------------------------------------------------------------------
extern "C" void kernel_launch(void* const* d_in, const int* in_sizes, int n_in,
                              void* d_out, int out_size)
{
    const float* x  = (const float*)d_in[0];
    const float* Wq = (const float*)d_in[1];
    const float* gq = (const float*)d_in[2];
    const float* bq = (const float*)d_in[3];
    const float* Wk = (const float*)d_in[4];
    const float* gk = (const float*)d_in[5];
    const float* bk = (const float*)d_in[6];
    const float* Wv = (const float*)d_in[7];
    const float* gv = (const float*)d_in[8];
    const float* bv = (const float*)d_in[9];
    float* out = (float*)d_out;

    conv_w_kernel<<<3 * COUT * (CIN / 2) / 256, 256>>>(Wq, Wk, Wv);
    conv_x_kernel<<<dim3(PP / 64, CIN / 64, BB), 256>>>(x);

    cudaFuncSetAttribute(gemm1b_kernel, cudaFuncAttributeMaxDynamicSharedMemorySize, G2_SMEM);
    gemm1b_kernel<<<dim3(PP / 128, COUT / 128, 3 * BB), 256, G2_SMEM>>>();

    stats_kernel<<<dim3(COUT, 3), 256>>>(gq, bq, gk, bk, gv, bv);
    fold_kernel<<<dim3(PP / 64, COUT / 64, 3 * BB), 256>>>();

    cudaFuncSetAttribute(attn4_kernel, cudaFuncAttributeMaxDynamicSharedMemorySize, ATTN4_SMEM);
    attn4_kernel<<<dim3(PP / 128, BB * NH), 256, ATTN4_SMEM>>>(out);
}

// round 10
// speedup vs baseline: 8.4160x; 1.3495x over previous
#include <cuda_runtime.h>
#include <cuda_fp16.h>
#include <math.h>
#include <stdint.h>

#define BB 8
#define CIN 512
#define COUT 1024
#define PP 2048
#define NH 8
#define DH 128

// ---------------- scratch (device globals; no allocations) ----------------
__device__ float    g_y[3][BB][COUT][PP];       // fp32 projections (pre-BN)
__device__ float    g_scale[3][COUT];
__device__ float    g_shift[3][COUT];
__device__ unsigned g_Wh[3][COUT][CIN/2];       // W split fp16 pairs along c (A-op)
__device__ unsigned g_Wl[3][COUT][CIN/2];
__device__ unsigned g_XT[BB][PP][CIN/2];        // x^T rounded fp16 pairs (B-op)
__device__ unsigned g_Qh[BB][COUT][PP/2];       // Q split fp16 pairs along p (A-op)
__device__ unsigned g_Ql[BB][COUT][PP/2];
__device__ unsigned g_KTh[BB][NH][PP][DH/2];    // K^T split (pre-scaled) (A-op)
__device__ unsigned g_KTl[BB][NH][PP][DH/2];
__device__ unsigned g_VT[BB][NH][PP][DH/2];     // V^T rounded fp16 (B-op)

// log2(e) / sqrt(128): folded into K so softmax is a bare ex2
#define K_ALPHA 0.12751743f

// ---------------- helpers ----------------
__device__ __forceinline__ unsigned pack2h(float x0, float x1) {
    unsigned h;
    asm("cvt.rn.f16x2.f32 %0, %1, %2;" : "=r"(h) : "f"(x1), "f"(x0));
    return h;
}
__device__ __forceinline__ void split2h(float x0, float x1, unsigned& hi, unsigned& lo) {
    unsigned h = pack2h(x0, x1);
    __half2 hh = *(__half2*)&h;
    float l0 = x0 - __half2float(__low2half(hh));
    float l1 = x1 - __half2float(__high2half(hh));
    hi = h;
    lo = pack2h(l0, l1);
}
__device__ __forceinline__ float fex2(float x) {
    float y;
    asm("ex2.approx.ftz.f32 %0, %1;" : "=f"(y) : "f"(x));
    return y;
}
__device__ __forceinline__ void mma16816(float* c,
    unsigned a0, unsigned a1, unsigned a2, unsigned a3, unsigned b0, unsigned b1)
{
    asm volatile(
        "mma.sync.aligned.m16n8k16.row.col.f32.f16.f16.f32 "
        "{%0,%1,%2,%3}, {%4,%5,%6,%7}, {%8,%9}, {%0,%1,%2,%3};\n"
        : "+f"(c[0]), "+f"(c[1]), "+f"(c[2]), "+f"(c[3])
        : "r"(a0), "r"(a1), "r"(a2), "r"(a3), "r"(b0), "r"(b1));
}

#define CP16(d, s) asm volatile("cp.async.cg.shared.global [%0], [%1], 16;" :: "r"(d), "l"(s) : "memory")
#define CP_COMMIT() asm volatile("cp.async.commit_group;" ::: "memory")
#define CP_WAIT(n)  asm volatile("cp.async.wait_group %0;" :: "n"(n) : "memory")
#define LDSM4(r0, r1, r2, r3, a) \
    asm volatile("ldmatrix.sync.aligned.m8n8.x4.shared.b16 {%0,%1,%2,%3}, [%4];" \
        : "=r"(r0), "=r"(r1), "=r"(r2), "=r"(r3) : "r"(a))

// ---------------- conv W -> split fp16 pairs ----------------
__global__ __launch_bounds__(256) void conv_w_kernel(
    const float* __restrict__ Wq, const float* __restrict__ Wk, const float* __restrict__ Wv)
{
    int idx = blockIdx.x * 256 + threadIdx.x;
    int proj = idx >> 18;
    int rem = idx & 262143;
    const float* W = (proj == 0) ? Wq : ((proj == 1) ? Wk : Wv);
    float2 v = *(const float2*)(W + (size_t)rem * 2);
    unsigned hi, lo;
    split2h(v.x, v.y, hi, lo);
    (&g_Wh[0][0][0])[(size_t)proj * 262144 + rem] = hi;
    (&g_Wl[0][0][0])[(size_t)proj * 262144 + rem] = lo;
}

// ---------------- conv x -> x^T rounded fp16 pairs ----------------
__global__ __launch_bounds__(256) void conv_x_kernel(const float* __restrict__ x)
{
    __shared__ float sm[64][65];
    int p0 = blockIdx.x * 64, c0 = blockIdx.y * 64, b = blockIdx.z;
    int tid = threadIdx.x;
    for (int t = tid; t < 64 * 64; t += 256) {
        int c = t >> 6, p = t & 63;
        sm[c][p] = x[((size_t)b * CIN + c0 + c) * PP + p0 + p];
    }
    __syncthreads();
    for (int t = tid; t < 64 * 32; t += 256) {
        int p = t >> 5, cp = t & 31;
        size_t o = ((size_t)b * PP + p0 + p) * 256 + (c0 >> 1) + cp;
        (&g_XT[0][0][0])[o] = pack2h(sm[2 * cp][p], sm[2 * cp + 1][p]);
    }
}

// ---------------- Stage 1: cp.async + ldmatrix GEMM  y = W * x ---------
// smem per stage (u32): Ah 128x20=2560, Al 2560, B 2560 => 7680; 2 stages
#define G2_STR 20
#define G2_STAGE 7680
#define G2_SMEM (2 * G2_STAGE * 4)

__global__ __launch_bounds__(256, 2) void gemm1b_kernel()
{
    extern __shared__ unsigned su[];
    uint32_t smb = (uint32_t)__cvta_generic_to_shared(su);
    int z = blockIdx.z, proj = z >> 3, b = z & 7;
    int o0 = blockIdx.y * 128, p0 = blockIdx.x * 128;
    const unsigned* gWh = &g_Wh[proj][0][0];
    const unsigned* gWl = &g_Wl[proj][0][0];
    const unsigned* gX  = &g_XT[b][0][0];
    const int tid = threadIdx.x, w = tid >> 5, lane = tid & 31;
    const int g = lane >> 2, q = lane & 3;
    const int tt = lane >> 3, rr = lane & 7;
    const int wo = w >> 2, wp = w & 3;

    float acc[4][4][4];
#pragma unroll
    for (int i = 0; i < 4; i++)
#pragma unroll
        for (int j = 0; j < 4; j++)
#pragma unroll
            for (int e = 0; e < 4; e++) acc[i][j][e] = 0.f;

#define G2_LOAD(c) do { \
        int _s = (c) & 1, _kk = (c) * 16; \
        uint32_t _sb = smb + 4 * (_s * G2_STAGE); \
        for (int t = tid; t < 512; t += 256) { \
            int r = t >> 2, f4 = (t & 3) * 4; \
            uint32_t d = _sb + 4 * (r * G2_STR + f4); \
            size_t wo_ = (size_t)(o0 + r) * 256 + _kk + f4; \
            size_t xo_ = (size_t)(p0 + r) * 256 + _kk + f4; \
            CP16(d,            gWh + wo_); \
            CP16(d + 4 * 2560, gWl + wo_); \
            CP16(d + 4 * 5120, gX + xo_); \
        } \
    } while (0)

    G2_LOAD(0);
    CP_COMMIT();

    const int fragRow = (tt & 1) * 8 + rr;
    const int fragCol = (tt >> 1) * 4;

    for (int c = 0; c < 16; c++) {
        if (c < 15) {
            G2_LOAD(c + 1);
            CP_COMMIT();
            CP_WAIT(1);
        } else {
            CP_WAIT(0);
        }
        __syncthreads();

        const int s = c & 1;
        const uint32_t aB = smb + 4 * (s * G2_STAGE + (wo * 64 + fragRow) * G2_STR + fragCol);
        const uint32_t bB = smb + 4 * (s * G2_STAGE + 5120 + (wp * 32 + fragRow) * G2_STR + fragCol);
#pragma unroll
        for (int ks = 0; ks < 2; ks++) {
            uint32_t ah[4][4], al[4][4];
            uint32_t bh[2][4];
#pragma unroll
            for (int nb = 0; nb < 2; nb++) {
                uint32_t ba = bB + 4 * (16 * nb * G2_STR + 8 * ks);
                LDSM4(bh[nb][0], bh[nb][1], bh[nb][2], bh[nb][3], ba);
            }
#pragma unroll
            for (int mf = 0; mf < 4; mf++) {
                uint32_t aa = aB + 4 * (16 * mf * G2_STR + 8 * ks);
                LDSM4(ah[mf][0], ah[mf][1], ah[mf][2], ah[mf][3], aa);
                LDSM4(al[mf][0], al[mf][1], al[mf][2], al[mf][3], aa + 4 * 2560);
            }
#pragma unroll
            for (int nb = 0; nb < 2; nb++)
#pragma unroll
                for (int mf = 0; mf < 4; mf++) {
                    mma16816(acc[mf][2 * nb],     ah[mf][0], ah[mf][1], ah[mf][2], ah[mf][3], bh[nb][0], bh[nb][2]);
                    mma16816(acc[mf][2 * nb],     al[mf][0], al[mf][1], al[mf][2], al[mf][3], bh[nb][0], bh[nb][2]);
                    mma16816(acc[mf][2 * nb + 1], ah[mf][0], ah[mf][1], ah[mf][2], ah[mf][3], bh[nb][1], bh[nb][3]);
                    mma16816(acc[mf][2 * nb + 1], al[mf][0], al[mf][1], al[mf][2], al[mf][3], bh[nb][1], bh[nb][3]);
                }
        }
        __syncthreads();
    }

    float* Y = &g_y[proj][b][0][0];
#pragma unroll
    for (int mf = 0; mf < 4; mf++)
#pragma unroll
        for (int nf = 0; nf < 4; nf++) {
            int oo = o0 + wo * 64 + 16 * mf + g;
            int pp = p0 + wp * 32 + 8 * nf + 2 * q;
            float* r0 = Y + (size_t)oo * PP + pp;
            *(float2*)r0 = make_float2(acc[mf][nf][0], acc[mf][nf][1]);
            *(float2*)(r0 + 8 * PP) = make_float2(acc[mf][nf][2], acc[mf][nf][3]);
        }
}

// ---------------- Stage 2: batch stats -> folded affine ----------------
__global__ __launch_bounds__(256) void stats_kernel(
    const float* __restrict__ gq, const float* __restrict__ bq,
    const float* __restrict__ gk, const float* __restrict__ bk,
    const float* __restrict__ gv, const float* __restrict__ bv)
{
    int o = blockIdx.x, proj = blockIdx.y;
    const float* base = &g_y[proj][0][o][0];
    float s = 0.f, s2 = 0.f;
    for (int t = threadIdx.x; t < BB * PP / 4; t += 256) {
        int b = t >> 9, p4 = (t & 511) * 4;
        float4 v = *(const float4*)&base[(size_t)b * COUT * PP + p4];
        s += v.x + v.y + v.z + v.w;
        s2 += v.x * v.x + v.y * v.y + v.z * v.z + v.w * v.w;
    }
    __shared__ float red0[256], red1[256];
    red0[threadIdx.x] = s; red1[threadIdx.x] = s2;
    __syncthreads();
    for (int st = 128; st > 0; st >>= 1) {
        if (threadIdx.x < st) {
            red0[threadIdx.x] += red0[threadIdx.x + st];
            red1[threadIdx.x] += red1[threadIdx.x + st];
        }
        __syncthreads();
    }
    if (threadIdx.x == 0) {
        const float invn = 1.f / (BB * PP);
        float mean = red0[0] * invn;
        float var = red1[0] * invn - mean * mean;
        const float* gg = (proj == 0) ? gq : ((proj == 1) ? gk : gv);
        const float* be = (proj == 0) ? bq : ((proj == 1) ? bk : bv);
        float sc = gg[o] * rsqrtf(var + 1e-5f);
        g_scale[proj][o] = sc;
        g_shift[proj][o] = be[o] - mean * sc;
    }
}

// ---------------- Stage 3: fold BN+LeakyReLU, emit fp16 operands ----------
__global__ __launch_bounds__(256) void fold_kernel()
{
    __shared__ float sm[64][65];
    int p0 = blockIdx.x * 64, c0 = blockIdx.y * 64;
    int z = blockIdx.z, proj = z >> 3, b = z & 7;
    int tid = threadIdx.x;
    const float post = (proj == 1) ? K_ALPHA : 1.f;
    for (int t = tid; t < 64 * 64; t += 256) {
        int c = t >> 6, p = t & 63;
        float v = g_y[proj][b][c0 + c][p0 + p];
        v = v * g_scale[proj][c0 + c] + g_shift[proj][c0 + c];
        v = (v >= 0.f) ? v : 0.1f * v;
        sm[c][p] = v * post;
    }
    __syncthreads();
    if (proj == 0) {
        // Q: A-operand of O GEMM -> split
        for (int t = tid; t < 64 * 32; t += 256) {
            int c = t >> 5, jp = t & 31;
            unsigned hi, lo;
            split2h(sm[c][2 * jp], sm[c][2 * jp + 1], hi, lo);
            size_t o = ((size_t)b * COUT + c0 + c) * 1024 + (p0 >> 1) + jp;
            (&g_Qh[0][0][0])[o] = hi;
            (&g_Ql[0][0][0])[o] = lo;
        }
    } else if (proj == 1) {
        // K: A-operand of S GEMM -> split
        int h = c0 >> 7, cpo = (c0 & 127) >> 1;
        for (int t = tid; t < 64 * 32; t += 256) {
            int p = t >> 5, cp = t & 31;
            unsigned hi, lo;
            split2h(sm[2 * cp][p], sm[2 * cp + 1][p], hi, lo);
            size_t o = ((size_t)(b * NH + h) * PP + p0 + p) * 64 + cpo + cp;
            (&g_KTh[0][0][0][0])[o] = hi;
            (&g_KTl[0][0][0][0])[o] = lo;
        }
    } else {
        // V: B-operand of S GEMM -> single rounded
        int h = c0 >> 7, cpo = (c0 & 127) >> 1;
        for (int t = tid; t < 64 * 32; t += 256) {
            int p = t >> 5, cp = t & 31;
            size_t o = ((size_t)(b * NH + h) * PP + p0 + p) * 64 + cpo + cp;
            (&g_VT[0][0][0][0])[o] = pack2h(sm[2 * cp][p], sm[2 * cp + 1][p]);
        }
    }
}

// ---------------- Stage 4: fp16 2-term flash attention ----------------
// smem (u32): V 0 (2 bufs x 4352)      [prologue stages Kh@0 (8704), Kl@8704]
//             Q 8704 (2 bufs x 9216: Qh 4608 + Ql 4608)
//             PH 27136 (4608), LR 31744 (128)
#define OFF_V  0
#define OFF_Q  8704
#define OFF_PH 27136
#define OFF_LR 31744
#define ATTN5_SMEM ((31744 + 128) * 4)

__global__ __launch_bounds__(256) void attn5_kernel(float* __restrict__ out)
{
    extern __shared__ unsigned sm[];
    uint32_t smb = (uint32_t)__cvta_generic_to_shared(sm);
    const int tid = threadIdx.x;
    const int w = tid >> 5, lane = tid & 31;
    const int g = lane >> 2, q = lane & 3;
    const int tt = lane >> 3, rr = lane & 7;
    const int bh = blockIdx.y, b = bh >> 3, h = bh & 7;
    const int i0 = blockIdx.x * 128;

    const unsigned* gKh = &g_KTh[b][h][0][0];
    const unsigned* gKl = &g_KTl[b][h][0][0];
    const unsigned* gV  = &g_VT[b][h][0][0];
    const unsigned* gQh = &g_Qh[b][h * 128][0];
    const unsigned* gQl = &g_Ql[b][h * 128][0];

    const int aRow = 16 * w + (tt & 1) * 8 + rr;
    const int aCol = (tt >> 1) * 4;
    const int bRow0 = (tt & 1) * 8 + rr;

    // ---- prologue: stage K, extract A-fragments to registers ----
    for (int t = tid; t < 2048; t += 256) {
        int r = t >> 4, f4 = (t & 15) * 4;
        uint32_t d = smb + 4 * (r * 68 + f4);
        size_t so = (size_t)(i0 + r) * 64 + f4;
        CP16(d, gKh + so);
        CP16(d + 4 * 8704, gKl + so);
    }
    CP_COMMIT();
    CP_WAIT(0);
    __syncthreads();

    unsigned kh[8][4], kl[8][4];
    {
        const uint32_t kB = smb + 4 * (aRow * 68 + aCol);
#pragma unroll
        for (int ks = 0; ks < 8; ks++) {
            LDSM4(kh[ks][0], kh[ks][1], kh[ks][2], kh[ks][3], kB + 32 * ks);
            LDSM4(kl[ks][0], kl[ks][1], kl[ks][2], kl[ks][3], kB + 4 * 8704 + 32 * ks);
        }
    }
    __syncthreads();

    // V(0), Q(0)
    for (int t = tid; t < 1024; t += 256) {
        int r = t >> 4, f4 = (t & 15) * 4;
        CP16(smb + 4 * (OFF_V + r * 68 + f4), gV + (size_t)r * 64 + f4);
    }
    for (int t = tid; t < 1024; t += 256) {
        int r = t >> 3, f4 = (t & 7) * 4;
        uint32_t d = smb + 4 * (OFF_Q + r * 36 + f4);
        size_t so = (size_t)r * 1024 + f4;
        CP16(d, gQh + so);
        CP16(d + 4 * 4608, gQl + so);
    }
    CP_COMMIT();

    float oacc[8][2][4];
#pragma unroll
    for (int mf = 0; mf < 8; mf++)
#pragma unroll
        for (int nf = 0; nf < 2; nf++)
#pragma unroll
            for (int e = 0; e < 4; e++) oacc[mf][nf][e] = 0.f;
    float l0 = 0.f, l1 = 0.f;

    for (int jt = 0; jt < 32; jt++) {
        const int qb = jt & 1;
        CP_WAIT(0);
        __syncthreads();                 // V(jt), Q(jt) resident

        // prefetch next tiles into alternate buffers immediately
        if (jt < 31) {
            const int jn = (jt + 1) * 64;
            for (int t = tid; t < 1024; t += 256) {
                int r = t >> 4, f4 = (t & 15) * 4;
                CP16(smb + 4 * (OFF_V + (qb ^ 1) * 4352 + r * 68 + f4),
                     gV + (size_t)(jn + r) * 64 + f4);
            }
            for (int t = tid; t < 1024; t += 256) {
                int r = t >> 3, f4 = (t & 7) * 4;
                uint32_t d = smb + 4 * (OFF_Q + (qb ^ 1) * 9216 + r * 36 + f4);
                size_t so = (size_t)r * 1024 + (jn >> 1) + f4;
                CP16(d, gQh + so);
                CP16(d + 4 * 4608, gQl + so);
            }
            CP_COMMIT();
        }

        // ---- S = K_i^T V_j (2-term: Kh·V + Kl·V) ----
        float sacc[8][4];
#pragma unroll
        for (int nf = 0; nf < 8; nf++)
#pragma unroll
            for (int e = 0; e < 4; e++) sacc[nf][e] = 0.f;

        const uint32_t vBase = smb + 4 * (OFF_V + qb * 4352 + bRow0 * 68 + aCol);
#pragma unroll
        for (int ks = 0; ks < 8; ks++) {
#pragma unroll
            for (int nb = 0; nb < 4; nb++) {
                uint32_t vh0, vh1, vh2, vh3;
                LDSM4(vh0, vh1, vh2, vh3, vBase + 4 * (nb * 16 * 68) + 32 * ks);
                mma16816(sacc[2 * nb],     kh[ks][0], kh[ks][1], kh[ks][2], kh[ks][3], vh0, vh2);
                mma16816(sacc[2 * nb],     kl[ks][0], kl[ks][1], kl[ks][2], kl[ks][3], vh0, vh2);
                mma16816(sacc[2 * nb + 1], kh[ks][0], kh[ks][1], kh[ks][2], kh[ks][3], vh1, vh3);
                mma16816(sacc[2 * nb + 1], kl[ks][0], kl[ks][1], kl[ks][2], kl[ks][3], vh1, vh3);
            }
        }

        // ---- softmax: P = exp2(sacc), rounded to fp16 (B-op) ----
#pragma unroll
        for (int nf = 0; nf < 8; nf++) {
            float e0 = fex2(sacc[nf][0]);
            float e1 = fex2(sacc[nf][1]);
            float e2 = fex2(sacc[nf][2]);
            float e3 = fex2(sacc[nf][3]);
            l0 += e0 + e1;
            l1 += e2 + e3;
            int jp = 4 * nf + q;
            sm[OFF_PH + (16 * w + g) * 36 + jp] = pack2h(e0, e1);
            sm[OFF_PH + (16 * w + 8 + g) * 36 + jp] = pack2h(e2, e3);
        }
        __syncwarp();

        // ---- O += Q_j P^T (2-term: Qh·P + Ql·P) ----
        const uint32_t pBase = smb + 4 * (OFF_PH + aRow * 36 + aCol);
        const uint32_t qBase = smb + 4 * (OFF_Q + qb * 9216 + bRow0 * 36 + aCol);
#pragma unroll
        for (int ks = 0; ks < 4; ks++) {
            uint32_t ph0, ph1, ph2, ph3;
            LDSM4(ph0, ph1, ph2, ph3, pBase + 32 * ks);
#pragma unroll
            for (int mf = 0; mf < 8; mf++) {
                uint32_t qh0, qh1, qh2, qh3, ql0, ql1, ql2, ql3;
                uint32_t qa = qBase + 4 * (16 * mf * 36) + 32 * ks;
                LDSM4(qh0, qh1, qh2, qh3, qa);
                LDSM4(ql0, ql1, ql2, ql3, qa + 4 * 4608);
                mma16816(oacc[mf][0], qh0, qh1, qh2, qh3, ph0, ph2);
                mma16816(oacc[mf][0], ql0, ql1, ql2, ql3, ph0, ph2);
                mma16816(oacc[mf][1], qh0, qh1, qh2, qh3, ph1, ph3);
                mma16816(oacc[mf][1], ql0, ql1, ql2, ql3, ph1, ph3);
            }
        }
    }

    l0 += __shfl_xor_sync(0xffffffffu, l0, 1);
    l0 += __shfl_xor_sync(0xffffffffu, l0, 2);
    l1 += __shfl_xor_sync(0xffffffffu, l1, 1);
    l1 += __shfl_xor_sync(0xffffffffu, l1, 2);
    float* lrow = (float*)&sm[OFF_LR];
    if (q == 0) {
        lrow[16 * w + g] = 1.f / l0;
        lrow[16 * w + 8 + g] = 1.f / l1;
    }
    __syncthreads();
#pragma unroll
    for (int nf = 0; nf < 2; nf++) {
        int ic = 16 * w + 8 * nf + 2 * q;
        float il0 = lrow[ic], il1 = lrow[ic + 1];
#pragma unroll
        for (int mf = 0; mf < 8; mf++) {
            int c = h * 128 + 16 * mf + g;
            float* p0 = out + ((size_t)b * COUT + c) * PP + i0 + ic;
            *(float2*)p0 = make_float2(oacc[mf][nf][0] * il0, oacc[mf][nf][1] * il1);
            float* p1 = p0 + 8 * PP;
            *(float2*)p1 = make_float2(oacc[mf][nf][2] * il0, oacc[mf][nf][3] * il1);
        }
    }
}

// ---------------------------------------------------------------------------
extern "C" void kernel_launch(void* const* d_in, const int* in_sizes, int n_in,
                              void* d_out, int out_size)
{
    const float* x  = (const float*)d_in[0];
    const float* Wq = (const float*)d_in[1];
    const float* gq = (const float*)d_in[2];
    const float* bq = (const float*)d_in[3];
    const float* Wk = (const float*)d_in[4];
    const float* gk = (const float*)d_in[5];
    const float* bk = (const float*)d_in[6];
    const float* Wv = (const float*)d_in[7];
    const float* gv = (const float*)d_in[8];
    const float* bv = (const float*)d_in[9];
    float* out = (float*)d_out;

    conv_w_kernel<<<3 * COUT * (CIN / 2) / 256, 256>>>(Wq, Wk, Wv);
    conv_x_kernel<<<dim3(PP / 64, CIN / 64, BB), 256>>>(x);

    cudaFuncSetAttribute(gemm1b_kernel, cudaFuncAttributeMaxDynamicSharedMemorySize, G2_SMEM);
    gemm1b_kernel<<<dim3(PP / 128, COUT / 128, 3 * BB), 256, G2_SMEM>>>();

    stats_kernel<<<dim3(COUT, 3), 256>>>(gq, bq, gk, bk, gv, bv);
    fold_kernel<<<dim3(PP / 64, COUT / 64, 3 * BB), 256>>>();

    cudaFuncSetAttribute(attn5_kernel, cudaFuncAttributeMaxDynamicSharedMemorySize, ATTN5_SMEM);
    attn5_kernel<<<dim3(PP / 128, BB * NH), 256, ATTN5_SMEM>>>(out);
}

// round 11
// speedup vs baseline: 9.2129x; 1.0947x over previous
#include <cuda_runtime.h>
#include <cuda_fp16.h>
#include <math.h>
#include <stdint.h>

#define BB 8
#define CIN 512
#define COUT 1024
#define PP 2048
#define NH 8
#define DH 128

// ---------------- scratch (device globals; no allocations) ----------------
__device__ float    g_y[3][BB][COUT][PP];       // fp32 projections (pre-BN)
__device__ float    g_scale[3][COUT];
__device__ float    g_shift[3][COUT];
__device__ unsigned g_W[3][COUT][CIN/2];        // W rounded fp16 pairs along c
__device__ unsigned g_XT[BB][PP][CIN/2];        // x^T rounded fp16 pairs
__device__ unsigned g_Q[BB][COUT][PP/2];        // Q rounded fp16 pairs along p
__device__ unsigned g_KT[BB][NH][PP][DH/2];     // K^T rounded (pre-scaled)
__device__ unsigned g_VT[BB][NH][PP][DH/2];     // V^T rounded fp16

// log2(e) / sqrt(128): folded into K so softmax is a bare ex2
#define K_ALPHA 0.12751743f

// ---------------- helpers ----------------
__device__ __forceinline__ unsigned pack2h(float x0, float x1) {
    unsigned h;
    asm("cvt.rn.f16x2.f32 %0, %1, %2;" : "=r"(h) : "f"(x1), "f"(x0));
    return h;
}
__device__ __forceinline__ float fex2(float x) {
    float y;
    asm("ex2.approx.ftz.f32 %0, %1;" : "=f"(y) : "f"(x));
    return y;
}
__device__ __forceinline__ void mma16816(float* c,
    unsigned a0, unsigned a1, unsigned a2, unsigned a3, unsigned b0, unsigned b1)
{
    asm volatile(
        "mma.sync.aligned.m16n8k16.row.col.f32.f16.f16.f32 "
        "{%0,%1,%2,%3}, {%4,%5,%6,%7}, {%8,%9}, {%0,%1,%2,%3};\n"
        : "+f"(c[0]), "+f"(c[1]), "+f"(c[2]), "+f"(c[3])
        : "r"(a0), "r"(a1), "r"(a2), "r"(a3), "r"(b0), "r"(b1));
}

#define CP16(d, s) asm volatile("cp.async.cg.shared.global [%0], [%1], 16;" :: "r"(d), "l"(s) : "memory")
#define CP_COMMIT() asm volatile("cp.async.commit_group;" ::: "memory")
#define CP_WAIT(n)  asm volatile("cp.async.wait_group %0;" :: "n"(n) : "memory")
#define LDSM4(r0, r1, r2, r3, a) \
    asm volatile("ldmatrix.sync.aligned.m8n8.x4.shared.b16 {%0,%1,%2,%3}, [%4];" \
        : "=r"(r0), "=r"(r1), "=r"(r2), "=r"(r3) : "r"(a))

// ---------------- conv W -> rounded fp16 pairs ----------------
__global__ __launch_bounds__(256) void conv_w_kernel(
    const float* __restrict__ Wq, const float* __restrict__ Wk, const float* __restrict__ Wv)
{
    int idx = blockIdx.x * 256 + threadIdx.x;
    int proj = idx >> 18;
    int rem = idx & 262143;
    const float* W = (proj == 0) ? Wq : ((proj == 1) ? Wk : Wv);
    float2 v = *(const float2*)(W + (size_t)rem * 2);
    (&g_W[0][0][0])[(size_t)proj * 262144 + rem] = pack2h(v.x, v.y);
}

// ---------------- conv x -> x^T rounded fp16 pairs ----------------
__global__ __launch_bounds__(256) void conv_x_kernel(const float* __restrict__ x)
{
    __shared__ float sm[64][65];
    int p0 = blockIdx.x * 64, c0 = blockIdx.y * 64, b = blockIdx.z;
    int tid = threadIdx.x;
    for (int t = tid; t < 64 * 64; t += 256) {
        int c = t >> 6, p = t & 63;
        sm[c][p] = x[((size_t)b * CIN + c0 + c) * PP + p0 + p];
    }
    __syncthreads();
    for (int t = tid; t < 64 * 32; t += 256) {
        int p = t >> 5, cp = t & 31;
        size_t o = ((size_t)b * PP + p0 + p) * 256 + (c0 >> 1) + cp;
        (&g_XT[0][0][0])[o] = pack2h(sm[2 * cp][p], sm[2 * cp + 1][p]);
    }
}

// ---------------- Stage 1: cp.async + ldmatrix GEMM  y = W * x ---------
// smem per stage (u32): A 128x20=2560, B 2560 => 5120; 2 stages = 40KB
#define G2_STR 20
#define G2_STAGE 5120
#define G2_SMEM (2 * G2_STAGE * 4)

__global__ __launch_bounds__(256, 2) void gemm1b_kernel()
{
    extern __shared__ unsigned su[];
    uint32_t smb = (uint32_t)__cvta_generic_to_shared(su);
    int z = blockIdx.z, proj = z >> 3, b = z & 7;
    int o0 = blockIdx.y * 128, p0 = blockIdx.x * 128;
    const unsigned* gW = &g_W[proj][0][0];
    const unsigned* gX = &g_XT[b][0][0];
    const int tid = threadIdx.x, w = tid >> 5, lane = tid & 31;
    const int g = lane >> 2, q = lane & 3;
    const int tt = lane >> 3, rr = lane & 7;
    const int wo = w >> 2, wp = w & 3;

    float acc[4][4][4];
#pragma unroll
    for (int i = 0; i < 4; i++)
#pragma unroll
        for (int j = 0; j < 4; j++)
#pragma unroll
            for (int e = 0; e < 4; e++) acc[i][j][e] = 0.f;

#define G2_LOAD(c) do { \
        int _s = (c) & 1, _kk = (c) * 16; \
        uint32_t _sb = smb + 4 * (_s * G2_STAGE); \
        for (int t = tid; t < 512; t += 256) { \
            int r = t >> 2, f4 = (t & 3) * 4; \
            uint32_t d = _sb + 4 * (r * G2_STR + f4); \
            CP16(d,            gW + (size_t)(o0 + r) * 256 + _kk + f4); \
            CP16(d + 4 * 2560, gX + (size_t)(p0 + r) * 256 + _kk + f4); \
        } \
    } while (0)

    G2_LOAD(0);
    CP_COMMIT();

    const int fragRow = (tt & 1) * 8 + rr;
    const int fragCol = (tt >> 1) * 4;

    for (int c = 0; c < 16; c++) {
        if (c < 15) {
            G2_LOAD(c + 1);
            CP_COMMIT();
            CP_WAIT(1);
        } else {
            CP_WAIT(0);
        }
        __syncthreads();

        const int s = c & 1;
        const uint32_t aB = smb + 4 * (s * G2_STAGE + (wo * 64 + fragRow) * G2_STR + fragCol);
        const uint32_t bB = smb + 4 * (s * G2_STAGE + 2560 + (wp * 32 + fragRow) * G2_STR + fragCol);
#pragma unroll
        for (int ks = 0; ks < 2; ks++) {
            uint32_t a[4][4];
            uint32_t bh[2][4];
#pragma unroll
            for (int nb = 0; nb < 2; nb++) {
                uint32_t ba = bB + 4 * (16 * nb * G2_STR + 8 * ks);
                LDSM4(bh[nb][0], bh[nb][1], bh[nb][2], bh[nb][3], ba);
            }
#pragma unroll
            for (int mf = 0; mf < 4; mf++) {
                uint32_t aa = aB + 4 * (16 * mf * G2_STR + 8 * ks);
                LDSM4(a[mf][0], a[mf][1], a[mf][2], a[mf][3], aa);
            }
#pragma unroll
            for (int nb = 0; nb < 2; nb++)
#pragma unroll
                for (int mf = 0; mf < 4; mf++) {
                    mma16816(acc[mf][2 * nb],     a[mf][0], a[mf][1], a[mf][2], a[mf][3], bh[nb][0], bh[nb][2]);
                    mma16816(acc[mf][2 * nb + 1], a[mf][0], a[mf][1], a[mf][2], a[mf][3], bh[nb][1], bh[nb][3]);
                }
        }
        __syncthreads();
    }

    float* Y = &g_y[proj][b][0][0];
#pragma unroll
    for (int mf = 0; mf < 4; mf++)
#pragma unroll
        for (int nf = 0; nf < 4; nf++) {
            int oo = o0 + wo * 64 + 16 * mf + g;
            int pp = p0 + wp * 32 + 8 * nf + 2 * q;
            float* r0 = Y + (size_t)oo * PP + pp;
            *(float2*)r0 = make_float2(acc[mf][nf][0], acc[mf][nf][1]);
            *(float2*)(r0 + 8 * PP) = make_float2(acc[mf][nf][2], acc[mf][nf][3]);
        }
}

// ---------------- Stage 2: batch stats -> folded affine ----------------
__global__ __launch_bounds__(256) void stats_kernel(
    const float* __restrict__ gq, const float* __restrict__ bq,
    const float* __restrict__ gk, const float* __restrict__ bk,
    const float* __restrict__ gv, const float* __restrict__ bv)
{
    int o = blockIdx.x, proj = blockIdx.y;
    const float* base = &g_y[proj][0][o][0];
    float s = 0.f, s2 = 0.f;
    for (int t = threadIdx.x; t < BB * PP / 4; t += 256) {
        int b = t >> 9, p4 = (t & 511) * 4;
        float4 v = *(const float4*)&base[(size_t)b * COUT * PP + p4];
        s += v.x + v.y + v.z + v.w;
        s2 += v.x * v.x + v.y * v.y + v.z * v.z + v.w * v.w;
    }
    __shared__ float red0[256], red1[256];
    red0[threadIdx.x] = s; red1[threadIdx.x] = s2;
    __syncthreads();
    for (int st = 128; st > 0; st >>= 1) {
        if (threadIdx.x < st) {
            red0[threadIdx.x] += red0[threadIdx.x + st];
            red1[threadIdx.x] += red1[threadIdx.x + st];
        }
        __syncthreads();
    }
    if (threadIdx.x == 0) {
        const float invn = 1.f / (BB * PP);
        float mean = red0[0] * invn;
        float var = red1[0] * invn - mean * mean;
        const float* gg = (proj == 0) ? gq : ((proj == 1) ? gk : gv);
        const float* be = (proj == 0) ? bq : ((proj == 1) ? bk : bv);
        float sc = gg[o] * rsqrtf(var + 1e-5f);
        g_scale[proj][o] = sc;
        g_shift[proj][o] = be[o] - mean * sc;
    }
}

// ---------------- Stage 3: fold BN+LeakyReLU, emit fp16 operands ----------
__global__ __launch_bounds__(256) void fold_kernel()
{
    __shared__ float sm[64][65];
    int p0 = blockIdx.x * 64, c0 = blockIdx.y * 64;
    int z = blockIdx.z, proj = z >> 3, b = z & 7;
    int tid = threadIdx.x;
    const float post = (proj == 1) ? K_ALPHA : 1.f;
    for (int t = tid; t < 64 * 64; t += 256) {
        int c = t >> 6, p = t & 63;
        float v = g_y[proj][b][c0 + c][p0 + p];
        v = v * g_scale[proj][c0 + c] + g_shift[proj][c0 + c];
        v = (v >= 0.f) ? v : 0.1f * v;
        sm[c][p] = v * post;
    }
    __syncthreads();
    if (proj == 0) {
        for (int t = tid; t < 64 * 32; t += 256) {
            int c = t >> 5, jp = t & 31;
            size_t o = ((size_t)b * COUT + c0 + c) * 1024 + (p0 >> 1) + jp;
            (&g_Q[0][0][0])[o] = pack2h(sm[c][2 * jp], sm[c][2 * jp + 1]);
        }
    } else {
        int h = c0 >> 7, cpo = (c0 & 127) >> 1;
        unsigned* dst = (proj == 1) ? &g_KT[0][0][0][0] : &g_VT[0][0][0][0];
        for (int t = tid; t < 64 * 32; t += 256) {
            int p = t >> 5, cp = t & 31;
            size_t o = ((size_t)(b * NH + h) * PP + p0 + p) * 64 + cpo + cp;
            dst[o] = pack2h(sm[2 * cp][p], sm[2 * cp + 1][p]);
        }
    }
}

// ---------------- Stage 4: pure fp16 flash attention ----------------
// smem (u32): V 0 (2 bufs x 4352)   [prologue stages K (8704 u32) at 0]
//             Q 8704 (2 bufs x 4608)
//             PH 17920 (4608), LR 22528 (128)
#define OFF_V  0
#define OFF_Q  8704
#define OFF_PH 17920
#define OFF_LR 22528
#define ATTN6_SMEM ((22528 + 128) * 4)

__global__ __launch_bounds__(256) void attn6_kernel(float* __restrict__ out)
{
    extern __shared__ unsigned sm[];
    uint32_t smb = (uint32_t)__cvta_generic_to_shared(sm);
    const int tid = threadIdx.x;
    const int w = tid >> 5, lane = tid & 31;
    const int g = lane >> 2, q = lane & 3;
    const int tt = lane >> 3, rr = lane & 7;
    const int bh = blockIdx.y, b = bh >> 3, h = bh & 7;
    const int i0 = blockIdx.x * 128;

    const unsigned* gK = &g_KT[b][h][0][0];
    const unsigned* gV = &g_VT[b][h][0][0];
    const unsigned* gQ = &g_Q[b][h * 128][0];

    const int aRow = 16 * w + (tt & 1) * 8 + rr;
    const int aCol = (tt >> 1) * 4;
    const int bRow0 = (tt & 1) * 8 + rr;

    // ---- prologue: stage K through smem, extract A-fragments to regs ----
    for (int t = tid; t < 2048; t += 256) {
        int r = t >> 4, f4 = (t & 15) * 4;
        CP16(smb + 4 * (r * 68 + f4), gK + (size_t)(i0 + r) * 64 + f4);
    }
    CP_COMMIT();
    CP_WAIT(0);
    __syncthreads();

    unsigned kh[8][4];
    {
        const uint32_t kB = smb + 4 * (aRow * 68 + aCol);
#pragma unroll
        for (int ks = 0; ks < 8; ks++)
            LDSM4(kh[ks][0], kh[ks][1], kh[ks][2], kh[ks][3], kB + 32 * ks);
    }
    __syncthreads();

    // V(0), Q(0)
    for (int t = tid; t < 1024; t += 256) {
        int r = t >> 4, f4 = (t & 15) * 4;
        CP16(smb + 4 * (OFF_V + r * 68 + f4), gV + (size_t)r * 64 + f4);
    }
    for (int t = tid; t < 1024; t += 256) {
        int r = t >> 3, f4 = (t & 7) * 4;
        CP16(smb + 4 * (OFF_Q + r * 36 + f4), gQ + (size_t)r * 1024 + f4);
    }
    CP_COMMIT();

    float oacc[8][2][4];
#pragma unroll
    for (int mf = 0; mf < 8; mf++)
#pragma unroll
        for (int nf = 0; nf < 2; nf++)
#pragma unroll
            for (int e = 0; e < 4; e++) oacc[mf][nf][e] = 0.f;
    float l0 = 0.f, l1 = 0.f;

    for (int jt = 0; jt < 32; jt++) {
        const int qb = jt & 1;
        CP_WAIT(0);
        __syncthreads();                 // V(jt), Q(jt) resident

        // prefetch next tiles into alternate buffers immediately
        if (jt < 31) {
            const int jn = (jt + 1) * 64;
            for (int t = tid; t < 1024; t += 256) {
                int r = t >> 4, f4 = (t & 15) * 4;
                CP16(smb + 4 * (OFF_V + (qb ^ 1) * 4352 + r * 68 + f4),
                     gV + (size_t)(jn + r) * 64 + f4);
            }
            for (int t = tid; t < 1024; t += 256) {
                int r = t >> 3, f4 = (t & 7) * 4;
                CP16(smb + 4 * (OFF_Q + (qb ^ 1) * 4608 + r * 36 + f4),
                     gQ + (size_t)r * 1024 + (jn >> 1) + f4);
            }
            CP_COMMIT();
        }

        // ---- S = K_i^T V_j ----
        float sacc[8][4];
#pragma unroll
        for (int nf = 0; nf < 8; nf++)
#pragma unroll
            for (int e = 0; e < 4; e++) sacc[nf][e] = 0.f;

        const uint32_t vBase = smb + 4 * (OFF_V + qb * 4352 + bRow0 * 68 + aCol);
#pragma unroll
        for (int ks = 0; ks < 8; ks++) {
#pragma unroll
            for (int nb = 0; nb < 4; nb++) {
                uint32_t vh0, vh1, vh2, vh3;
                LDSM4(vh0, vh1, vh2, vh3, vBase + 4 * (nb * 16 * 68) + 32 * ks);
                mma16816(sacc[2 * nb],     kh[ks][0], kh[ks][1], kh[ks][2], kh[ks][3], vh0, vh2);
                mma16816(sacc[2 * nb + 1], kh[ks][0], kh[ks][1], kh[ks][2], kh[ks][3], vh1, vh3);
            }
        }

        // ---- softmax: P = exp2(sacc), rounded to fp16 ----
#pragma unroll
        for (int nf = 0; nf < 8; nf++) {
            float e0 = fex2(sacc[nf][0]);
            float e1 = fex2(sacc[nf][1]);
            float e2 = fex2(sacc[nf][2]);
            float e3 = fex2(sacc[nf][3]);
            l0 += e0 + e1;
            l1 += e2 + e3;
            int jp = 4 * nf + q;
            sm[OFF_PH + (16 * w + g) * 36 + jp] = pack2h(e0, e1);
            sm[OFF_PH + (16 * w + 8 + g) * 36 + jp] = pack2h(e2, e3);
        }
        __syncwarp();

        // ---- O += Q_j P^T ----
        const uint32_t pBase = smb + 4 * (OFF_PH + aRow * 36 + aCol);
        const uint32_t qBase = smb + 4 * (OFF_Q + qb * 4608 + bRow0 * 36 + aCol);
#pragma unroll
        for (int ks = 0; ks < 4; ks++) {
            uint32_t ph0, ph1, ph2, ph3;
            LDSM4(ph0, ph1, ph2, ph3, pBase + 32 * ks);
#pragma unroll
            for (int mf = 0; mf < 8; mf++) {
                uint32_t qh0, qh1, qh2, qh3;
                LDSM4(qh0, qh1, qh2, qh3, qBase + 4 * (16 * mf * 36) + 32 * ks);
                mma16816(oacc[mf][0], qh0, qh1, qh2, qh3, ph0, ph2);
                mma16816(oacc[mf][1], qh0, qh1, qh2, qh3, ph1, ph3);
            }
        }
    }

    l0 += __shfl_xor_sync(0xffffffffu, l0, 1);
    l0 += __shfl_xor_sync(0xffffffffu, l0, 2);
    l1 += __shfl_xor_sync(0xffffffffu, l1, 1);
    l1 += __shfl_xor_sync(0xffffffffu, l1, 2);
    float* lrow = (float*)&sm[OFF_LR];
    if (q == 0) {
        lrow[16 * w + g] = 1.f / l0;
        lrow[16 * w + 8 + g] = 1.f / l1;
    }
    __syncthreads();
#pragma unroll
    for (int nf = 0; nf < 2; nf++) {
        int ic = 16 * w + 8 * nf + 2 * q;
        float il0 = lrow[ic], il1 = lrow[ic + 1];
#pragma unroll
        for (int mf = 0; mf < 8; mf++) {
            int c = h * 128 + 16 * mf + g;
            float* p0 = out + ((size_t)b * COUT + c) * PP + i0 + ic;
            *(float2*)p0 = make_float2(oacc[mf][nf][0] * il0, oacc[mf][nf][1] * il1);
            float* p1 = p0 + 8 * PP;
            *(float2*)p1 = make_float2(oacc[mf][nf][2] * il0, oacc[mf][nf][3] * il1);
        }
    }
}

// ---------------------------------------------------------------------------
extern "C" void kernel_launch(void* const* d_in, const int* in_sizes, int n_in,
                              void* d_out, int out_size)
{
    const float* x  = (const float*)d_in[0];
    const float* Wq = (const float*)d_in[1];
    const float* gq = (const float*)d_in[2];
    const float* bq = (const float*)d_in[3];
    const float* Wk = (const float*)d_in[4];
    const float* gk = (const float*)d_in[5];
    const float* bk = (const float*)d_in[6];
    const float* Wv = (const float*)d_in[7];
    const float* gv = (const float*)d_in[8];
    const float* bv = (const float*)d_in[9];
    float* out = (float*)d_out;

    conv_w_kernel<<<3 * COUT * (CIN / 2) / 256, 256>>>(Wq, Wk, Wv);
    conv_x_kernel<<<dim3(PP / 64, CIN / 64, BB), 256>>>(x);

    cudaFuncSetAttribute(gemm1b_kernel, cudaFuncAttributeMaxDynamicSharedMemorySize, G2_SMEM);
    gemm1b_kernel<<<dim3(PP / 128, COUT / 128, 3 * BB), 256, G2_SMEM>>>();

    stats_kernel<<<dim3(COUT, 3), 256>>>(gq, bq, gk, bk, gv, bv);
    fold_kernel<<<dim3(PP / 64, COUT / 64, 3 * BB), 256>>>();

    cudaFuncSetAttribute(attn6_kernel, cudaFuncAttributeMaxDynamicSharedMemorySize, ATTN6_SMEM);
    attn6_kernel<<<dim3(PP / 128, BB * NH), 256, ATTN6_SMEM>>>(out);
}

// round 12
// speedup vs baseline: 12.9272x; 1.4032x over previous
#include <cuda_runtime.h>
#include <cuda_fp16.h>
#include <math.h>
#include <stdint.h>

#define BB 8
#define CIN 512
#define COUT 1024
#define PP 2048
#define NH 8
#define DH 128

// ---------------- scratch (device globals; no allocations) ----------------
__device__ float    g_y[3][BB][COUT][PP];       // fp32 projections (pre-BN)
__device__ float    g_scale[3][COUT];
__device__ float    g_shift[3][COUT];
__device__ unsigned g_W[3][COUT][CIN/2];        // W rounded fp16 pairs along c
__device__ unsigned g_XT[BB][PP][CIN/2];        // x^T rounded fp16 pairs
__device__ unsigned g_Q[BB][COUT][PP/2];        // Q rounded fp16 pairs along p
__device__ unsigned g_KT[BB][NH][PP][DH/2];     // K^T rounded (pre-scaled)
__device__ unsigned g_VT[BB][NH][PP][DH/2];     // V^T rounded fp16

// log2(e) / sqrt(128): folded into K so softmax is a bare ex2
#define K_ALPHA 0.12751743f

// ---------------- helpers ----------------
__device__ __forceinline__ unsigned pack2h(float x0, float x1) {
    unsigned h;
    asm("cvt.rn.f16x2.f32 %0, %1, %2;" : "=r"(h) : "f"(x1), "f"(x0));
    return h;
}
__device__ __forceinline__ float fex2(float x) {
    float y;
    asm("ex2.approx.ftz.f32 %0, %1;" : "=f"(y) : "f"(x));
    return y;
}
__device__ __forceinline__ void mma16816(float* c,
    unsigned a0, unsigned a1, unsigned a2, unsigned a3, unsigned b0, unsigned b1)
{
    asm volatile(
        "mma.sync.aligned.m16n8k16.row.col.f32.f16.f16.f32 "
        "{%0,%1,%2,%3}, {%4,%5,%6,%7}, {%8,%9}, {%0,%1,%2,%3};\n"
        : "+f"(c[0]), "+f"(c[1]), "+f"(c[2]), "+f"(c[3])
        : "r"(a0), "r"(a1), "r"(a2), "r"(a3), "r"(b0), "r"(b1));
}

#define CP16(d, s) asm volatile("cp.async.cg.shared.global [%0], [%1], 16;" :: "r"(d), "l"(s) : "memory")
#define CP_COMMIT() asm volatile("cp.async.commit_group;" ::: "memory")
#define CP_WAIT(n)  asm volatile("cp.async.wait_group %0;" :: "n"(n) : "memory")
#define LDSM4(r0, r1, r2, r3, a) \
    asm volatile("ldmatrix.sync.aligned.m8n8.x4.shared.b16 {%0,%1,%2,%3}, [%4];" \
        : "=r"(r0), "=r"(r1), "=r"(r2), "=r"(r3) : "r"(a))

// ---------------- conv W -> rounded fp16 pairs ----------------
__global__ __launch_bounds__(256) void conv_w_kernel(
    const float* __restrict__ Wq, const float* __restrict__ Wk, const float* __restrict__ Wv)
{
    int idx = blockIdx.x * 256 + threadIdx.x;
    int proj = idx >> 18;
    int rem = idx & 262143;
    const float* W = (proj == 0) ? Wq : ((proj == 1) ? Wk : Wv);
    float2 v = *(const float2*)(W + (size_t)rem * 2);
    (&g_W[0][0][0])[(size_t)proj * 262144 + rem] = pack2h(v.x, v.y);
}

// ---------------- conv x -> x^T rounded fp16 pairs ----------------
__global__ __launch_bounds__(256) void conv_x_kernel(const float* __restrict__ x)
{
    __shared__ float sm[64][65];
    int p0 = blockIdx.x * 64, c0 = blockIdx.y * 64, b = blockIdx.z;
    int tid = threadIdx.x;
    for (int t = tid; t < 64 * 64; t += 256) {
        int c = t >> 6, p = t & 63;
        sm[c][p] = x[((size_t)b * CIN + c0 + c) * PP + p0 + p];
    }
    __syncthreads();
    for (int t = tid; t < 64 * 32; t += 256) {
        int p = t >> 5, cp = t & 31;
        size_t o = ((size_t)b * PP + p0 + p) * 256 + (c0 >> 1) + cp;
        (&g_XT[0][0][0])[o] = pack2h(sm[2 * cp][p], sm[2 * cp + 1][p]);
    }
}

// ---------------- Stage 1: cp.async + ldmatrix GEMM  y = W * x ---------
#define G2_STR 20
#define G2_STAGE 5120
#define G2_SMEM (2 * G2_STAGE * 4)

__global__ __launch_bounds__(256, 2) void gemm1b_kernel()
{
    extern __shared__ unsigned su[];
    uint32_t smb = (uint32_t)__cvta_generic_to_shared(su);
    int z = blockIdx.z, proj = z >> 3, b = z & 7;
    int o0 = blockIdx.y * 128, p0 = blockIdx.x * 128;
    const unsigned* gW = &g_W[proj][0][0];
    const unsigned* gX = &g_XT[b][0][0];
    const int tid = threadIdx.x, w = tid >> 5, lane = tid & 31;
    const int g = lane >> 2, q = lane & 3;
    const int tt = lane >> 3, rr = lane & 7;
    const int wo = w >> 2, wp = w & 3;

    float acc[4][4][4];
#pragma unroll
    for (int i = 0; i < 4; i++)
#pragma unroll
        for (int j = 0; j < 4; j++)
#pragma unroll
            for (int e = 0; e < 4; e++) acc[i][j][e] = 0.f;

#define G2_LOAD(c) do { \
        int _s = (c) & 1, _kk = (c) * 16; \
        uint32_t _sb = smb + 4 * (_s * G2_STAGE); \
        for (int t = tid; t < 512; t += 256) { \
            int r = t >> 2, f4 = (t & 3) * 4; \
            uint32_t d = _sb + 4 * (r * G2_STR + f4); \
            CP16(d,            gW + (size_t)(o0 + r) * 256 + _kk + f4); \
            CP16(d + 4 * 2560, gX + (size_t)(p0 + r) * 256 + _kk + f4); \
        } \
    } while (0)

    G2_LOAD(0);
    CP_COMMIT();

    const int fragRow = (tt & 1) * 8 + rr;
    const int fragCol = (tt >> 1) * 4;

    for (int c = 0; c < 16; c++) {
        if (c < 15) {
            G2_LOAD(c + 1);
            CP_COMMIT();
            CP_WAIT(1);
        } else {
            CP_WAIT(0);
        }
        __syncthreads();

        const int s = c & 1;
        const uint32_t aB = smb + 4 * (s * G2_STAGE + (wo * 64 + fragRow) * G2_STR + fragCol);
        const uint32_t bB = smb + 4 * (s * G2_STAGE + 2560 + (wp * 32 + fragRow) * G2_STR + fragCol);
#pragma unroll
        for (int ks = 0; ks < 2; ks++) {
            uint32_t a[4][4];
            uint32_t bh[2][4];
#pragma unroll
            for (int nb = 0; nb < 2; nb++) {
                uint32_t ba = bB + 4 * (16 * nb * G2_STR + 8 * ks);
                LDSM4(bh[nb][0], bh[nb][1], bh[nb][2], bh[nb][3], ba);
            }
#pragma unroll
            for (int mf = 0; mf < 4; mf++) {
                uint32_t aa = aB + 4 * (16 * mf * G2_STR + 8 * ks);
                LDSM4(a[mf][0], a[mf][1], a[mf][2], a[mf][3], aa);
            }
#pragma unroll
            for (int nb = 0; nb < 2; nb++)
#pragma unroll
                for (int mf = 0; mf < 4; mf++) {
                    mma16816(acc[mf][2 * nb],     a[mf][0], a[mf][1], a[mf][2], a[mf][3], bh[nb][0], bh[nb][2]);
                    mma16816(acc[mf][2 * nb + 1], a[mf][0], a[mf][1], a[mf][2], a[mf][3], bh[nb][1], bh[nb][3]);
                }
        }
        __syncthreads();
    }

    float* Y = &g_y[proj][b][0][0];
#pragma unroll
    for (int mf = 0; mf < 4; mf++)
#pragma unroll
        for (int nf = 0; nf < 4; nf++) {
            int oo = o0 + wo * 64 + 16 * mf + g;
            int pp = p0 + wp * 32 + 8 * nf + 2 * q;
            float* r0 = Y + (size_t)oo * PP + pp;
            *(float2*)r0 = make_float2(acc[mf][nf][0], acc[mf][nf][1]);
            *(float2*)(r0 + 8 * PP) = make_float2(acc[mf][nf][2], acc[mf][nf][3]);
        }
}

// ---------------- Stage 2: batch stats -> folded affine ----------------
__global__ __launch_bounds__(256) void stats_kernel(
    const float* __restrict__ gq, const float* __restrict__ bq,
    const float* __restrict__ gk, const float* __restrict__ bk,
    const float* __restrict__ gv, const float* __restrict__ bv)
{
    int o = blockIdx.x, proj = blockIdx.y;
    const float* base = &g_y[proj][0][o][0];
    float s = 0.f, s2 = 0.f;
    for (int t = threadIdx.x; t < BB * PP / 4; t += 256) {
        int b = t >> 9, p4 = (t & 511) * 4;
        float4 v = *(const float4*)&base[(size_t)b * COUT * PP + p4];
        s += v.x + v.y + v.z + v.w;
        s2 += v.x * v.x + v.y * v.y + v.z * v.z + v.w * v.w;
    }
    __shared__ float red0[256], red1[256];
    red0[threadIdx.x] = s; red1[threadIdx.x] = s2;
    __syncthreads();
    for (int st = 128; st > 0; st >>= 1) {
        if (threadIdx.x < st) {
            red0[threadIdx.x] += red0[threadIdx.x + st];
            red1[threadIdx.x] += red1[threadIdx.x + st];
        }
        __syncthreads();
    }
    if (threadIdx.x == 0) {
        const float invn = 1.f / (BB * PP);
        float mean = red0[0] * invn;
        float var = red1[0] * invn - mean * mean;
        const float* gg = (proj == 0) ? gq : ((proj == 1) ? gk : gv);
        const float* be = (proj == 0) ? bq : ((proj == 1) ? bk : bv);
        float sc = gg[o] * rsqrtf(var + 1e-5f);
        g_scale[proj][o] = sc;
        g_shift[proj][o] = be[o] - mean * sc;
    }
}

// ---------------- Stage 3: fold BN+LeakyReLU, emit fp16 operands ----------
__global__ __launch_bounds__(256) void fold_kernel()
{
    __shared__ float sm[64][65];
    int p0 = blockIdx.x * 64, c0 = blockIdx.y * 64;
    int z = blockIdx.z, proj = z >> 3, b = z & 7;
    int tid = threadIdx.x;
    const float post = (proj == 1) ? K_ALPHA : 1.f;
    for (int t = tid; t < 64 * 64; t += 256) {
        int c = t >> 6, p = t & 63;
        float v = g_y[proj][b][c0 + c][p0 + p];
        v = v * g_scale[proj][c0 + c] + g_shift[proj][c0 + c];
        v = (v >= 0.f) ? v : 0.1f * v;
        sm[c][p] = v * post;
    }
    __syncthreads();
    if (proj == 0) {
        for (int t = tid; t < 64 * 32; t += 256) {
            int c = t >> 5, jp = t & 31;
            size_t o = ((size_t)b * COUT + c0 + c) * 1024 + (p0 >> 1) + jp;
            (&g_Q[0][0][0])[o] = pack2h(sm[c][2 * jp], sm[c][2 * jp + 1]);
        }
    } else {
        int h = c0 >> 7, cpo = (c0 & 127) >> 1;
        unsigned* dst = (proj == 1) ? &g_KT[0][0][0][0] : &g_VT[0][0][0][0];
        for (int t = tid; t < 64 * 32; t += 256) {
            int p = t >> 5, cp = t & 31;
            size_t o = ((size_t)(b * NH + h) * PP + p0 + p) * 64 + cpo + cp;
            dst[o] = pack2h(sm[2 * cp][p], sm[2 * cp + 1][p]);
        }
    }
}

// ---------------- Stage 4: software-pipelined fp16 flash attention --------
// smem (u32): V 0 (2 bufs x 4352)   [prologue stages K (8704 u32) at 0]
//             Q 8704 (2 bufs x 4608)
//             PH 17920 (4608), LR 22528 (128)
// Pipeline: iter jt does softmax(S(jt)) -> S(jt+1) MMAs -> O(jt) MMAs.
// V(j) lives in buf j&1; Q(j) in qbuf j&1.
#define OFF_V  0
#define OFF_Q  8704
#define OFF_PH 17920
#define OFF_LR 22528
#define ATTN7_SMEM ((22528 + 128) * 4)

__global__ __launch_bounds__(256) void attn7_kernel(float* __restrict__ out)
{
    extern __shared__ unsigned sm[];
    uint32_t smb = (uint32_t)__cvta_generic_to_shared(sm);
    const int tid = threadIdx.x;
    const int w = tid >> 5, lane = tid & 31;
    const int g = lane >> 2, q = lane & 3;
    const int tt = lane >> 3, rr = lane & 7;
    const int bh = blockIdx.y, b = bh >> 3, h = bh & 7;
    const int i0 = blockIdx.x * 128;

    const unsigned* gK = &g_KT[b][h][0][0];
    const unsigned* gV = &g_VT[b][h][0][0];
    const unsigned* gQ = &g_Q[b][h * 128][0];

    const int aRow = 16 * w + (tt & 1) * 8 + rr;
    const int aCol = (tt >> 1) * 4;
    const int bRow0 = (tt & 1) * 8 + rr;

    // ---- prologue: stage K through smem, extract A-fragments to regs ----
    for (int t = tid; t < 2048; t += 256) {
        int r = t >> 4, f4 = (t & 15) * 4;
        CP16(smb + 4 * (r * 68 + f4), gK + (size_t)(i0 + r) * 64 + f4);
    }
    CP_COMMIT();
    CP_WAIT(0);
    __syncthreads();

    unsigned kh[8][4];
    {
        const uint32_t kB = smb + 4 * (aRow * 68 + aCol);
#pragma unroll
        for (int ks = 0; ks < 8; ks++)
            LDSM4(kh[ks][0], kh[ks][1], kh[ks][2], kh[ks][3], kB + 32 * ks);
    }
    __syncthreads();

    // V(0) -> buf0   (group B)
    for (int t = tid; t < 1024; t += 256) {
        int r = t >> 4, f4 = (t & 15) * 4;
        CP16(smb + 4 * (OFF_V + r * 68 + f4), gV + (size_t)r * 64 + f4);
    }
    CP_COMMIT();
    // V(1) -> buf1, Q(0) -> qbuf0   (group C)
    for (int t = tid; t < 1024; t += 256) {
        int r = t >> 4, f4 = (t & 15) * 4;
        CP16(smb + 4 * (OFF_V + 4352 + r * 68 + f4), gV + (size_t)(64 + r) * 64 + f4);
    }
    for (int t = tid; t < 1024; t += 256) {
        int r = t >> 3, f4 = (t & 7) * 4;
        CP16(smb + 4 * (OFF_Q + r * 36 + f4), gQ + (size_t)r * 1024 + f4);
    }
    CP_COMMIT();

    float oacc[8][2][4];
#pragma unroll
    for (int mf = 0; mf < 8; mf++)
#pragma unroll
        for (int nf = 0; nf < 2; nf++)
#pragma unroll
            for (int e = 0; e < 4; e++) oacc[mf][nf][e] = 0.f;
    float l0 = 0.f, l1 = 0.f;
    float sacc[8][4];

    // ---- prologue S(0) (V(0) resident after wait(1)) ----
    CP_WAIT(1);
    __syncthreads();
#pragma unroll
    for (int nf = 0; nf < 8; nf++)
#pragma unroll
        for (int e = 0; e < 4; e++) sacc[nf][e] = 0.f;
    {
        const uint32_t vBase = smb + 4 * (OFF_V + bRow0 * 68 + aCol);
#pragma unroll
        for (int ks = 0; ks < 8; ks++) {
#pragma unroll
            for (int nb = 0; nb < 4; nb++) {
                uint32_t vh0, vh1, vh2, vh3;
                LDSM4(vh0, vh1, vh2, vh3, vBase + 4 * (nb * 16 * 68) + 32 * ks);
                mma16816(sacc[2 * nb],     kh[ks][0], kh[ks][1], kh[ks][2], kh[ks][3], vh0, vh2);
                mma16816(sacc[2 * nb + 1], kh[ks][0], kh[ks][1], kh[ks][2], kh[ks][3], vh1, vh3);
            }
        }
    }

    for (int jt = 0; jt < 32; jt++) {
        const int qb = jt & 1;
        CP_WAIT(0);
        __syncthreads();      // V(jt+1), Q(jt) resident; all warps past iter jt-1

        // prefetch V(jt+2) -> buf jt&1 (V(jt)'s, done), Q(jt+1) -> qbuf (jt+1)&1
        if (jt < 30) {
            const int jn2 = (jt + 2) * 64;
            for (int t = tid; t < 1024; t += 256) {
                int r = t >> 4, f4 = (t & 15) * 4;
                CP16(smb + 4 * (OFF_V + qb * 4352 + r * 68 + f4),
                     gV + (size_t)(jn2 + r) * 64 + f4);
            }
        }
        if (jt < 31) {
            const int jn = (jt + 1) * 64;
            for (int t = tid; t < 1024; t += 256) {
                int r = t >> 3, f4 = (t & 7) * 4;
                CP16(smb + 4 * (OFF_Q + (qb ^ 1) * 4608 + r * 36 + f4),
                     gQ + (size_t)r * 1024 + (jn >> 1) + f4);
            }
            CP_COMMIT();
        }

        // ---- softmax on sacc = S(jt) (produced one iteration ago) ----
#pragma unroll
        for (int nf = 0; nf < 8; nf++) {
            float e0 = fex2(sacc[nf][0]);
            float e1 = fex2(sacc[nf][1]);
            float e2 = fex2(sacc[nf][2]);
            float e3 = fex2(sacc[nf][3]);
            l0 += e0 + e1;
            l1 += e2 + e3;
            int jp = 4 * nf + q;
            sm[OFF_PH + (16 * w + g) * 36 + jp] = pack2h(e0, e1);
            sm[OFF_PH + (16 * w + 8 + g) * 36 + jp] = pack2h(e2, e3);
        }
        __syncwarp();

        // ---- S(jt+1) = K_i^T V(jt+1) ----
        if (jt < 31) {
#pragma unroll
            for (int nf = 0; nf < 8; nf++)
#pragma unroll
                for (int e = 0; e < 4; e++) sacc[nf][e] = 0.f;
            const uint32_t vBase = smb + 4 * (OFF_V + (qb ^ 1) * 4352 + bRow0 * 68 + aCol);
#pragma unroll
            for (int ks = 0; ks < 8; ks++) {
#pragma unroll
                for (int nb = 0; nb < 4; nb++) {
                    uint32_t vh0, vh1, vh2, vh3;
                    LDSM4(vh0, vh1, vh2, vh3, vBase + 4 * (nb * 16 * 68) + 32 * ks);
                    mma16816(sacc[2 * nb],     kh[ks][0], kh[ks][1], kh[ks][2], kh[ks][3], vh0, vh2);
                    mma16816(sacc[2 * nb + 1], kh[ks][0], kh[ks][1], kh[ks][2], kh[ks][3], vh1, vh3);
                }
            }
        }

        // ---- O(jt) += Q(jt) P(jt)^T ----
        const uint32_t pBase = smb + 4 * (OFF_PH + aRow * 36 + aCol);
        const uint32_t qBase = smb + 4 * (OFF_Q + qb * 4608 + bRow0 * 36 + aCol);
#pragma unroll
        for (int ks = 0; ks < 4; ks++) {
            uint32_t ph0, ph1, ph2, ph3;
            LDSM4(ph0, ph1, ph2, ph3, pBase + 32 * ks);
#pragma unroll
            for (int mf = 0; mf < 8; mf++) {
                uint32_t qh0, qh1, qh2, qh3;
                LDSM4(qh0, qh1, qh2, qh3, qBase + 4 * (16 * mf * 36) + 32 * ks);
                mma16816(oacc[mf][0], qh0, qh1, qh2, qh3, ph0, ph2);
                mma16816(oacc[mf][1], qh0, qh1, qh2, qh3, ph1, ph3);
            }
        }
    }

    l0 += __shfl_xor_sync(0xffffffffu, l0, 1);
    l0 += __shfl_xor_sync(0xffffffffu, l0, 2);
    l1 += __shfl_xor_sync(0xffffffffu, l1, 1);
    l1 += __shfl_xor_sync(0xffffffffu, l1, 2);
    float* lrow = (float*)&sm[OFF_LR];
    if (q == 0) {
        lrow[16 * w + g] = 1.f / l0;
        lrow[16 * w + 8 + g] = 1.f / l1;
    }
    __syncthreads();
#pragma unroll
    for (int nf = 0; nf < 2; nf++) {
        int ic = 16 * w + 8 * nf + 2 * q;
        float il0 = lrow[ic], il1 = lrow[ic + 1];
#pragma unroll
        for (int mf = 0; mf < 8; mf++) {
            int c = h * 128 + 16 * mf + g;
            float* p0 = out + ((size_t)b * COUT + c) * PP + i0 + ic;
            *(float2*)p0 = make_float2(oacc[mf][nf][0] * il0, oacc[mf][nf][1] * il1);
            float* p1 = p0 + 8 * PP;
            *(float2*)p1 = make_float2(oacc[mf][nf][2] * il0, oacc[mf][nf][3] * il1);
        }
    }
}

// ---------------------------------------------------------------------------
extern "C" void kernel_launch(void* const* d_in, const int* in_sizes, int n_in,
                              void* d_out, int out_size)
{
    const float* x  = (const float*)d_in[0];
    const float* Wq = (const float*)d_in[1];
    const float* gq = (const float*)d_in[2];
    const float* bq = (const float*)d_in[3];
    const float* Wk = (const float*)d_in[4];
    const float* gk = (const float*)d_in[5];
    const float* bk = (const float*)d_in[6];
    const float* Wv = (const float*)d_in[7];
    const float* gv = (const float*)d_in[8];
    const float* bv = (const float*)d_in[9];
    float* out = (float*)d_out;

    conv_w_kernel<<<3 * COUT * (CIN / 2) / 256, 256>>>(Wq, Wk, Wv);
    conv_x_kernel<<<dim3(PP / 64, CIN / 64, BB), 256>>>(x);

    cudaFuncSetAttribute(gemm1b_kernel, cudaFuncAttributeMaxDynamicSharedMemorySize, G2_SMEM);
    gemm1b_kernel<<<dim3(PP / 128, COUT / 128, 3 * BB), 256, G2_SMEM>>>();

    stats_kernel<<<dim3(COUT, 3), 256>>>(gq, bq, gk, bk, gv, bv);
    fold_kernel<<<dim3(PP / 64, COUT / 64, 3 * BB), 256>>>();

    cudaFuncSetAttribute(attn7_kernel, cudaFuncAttributeMaxDynamicSharedMemorySize, ATTN7_SMEM);
    attn7_kernel<<<dim3(PP / 128, BB * NH), 256, ATTN7_SMEM>>>(out);
}

// round 13
// speedup vs baseline: 13.4880x; 1.0434x over previous
#include <cuda_runtime.h>
#include <cuda_fp16.h>
#include <math.h>
#include <stdint.h>

#define BB 8
#define CIN 512
#define COUT 1024
#define PP 2048
#define NH 8
#define DH 128

// ---------------- scratch (device globals; no allocations) ----------------
__device__ float    g_y[3][BB][COUT][PP];       // fp32 projections (pre-BN)
__device__ float    g_scale[3][COUT];
__device__ float    g_shift[3][COUT];
__device__ unsigned g_W[3][COUT][CIN/2];        // W rounded fp16 pairs along c
__device__ unsigned g_XT[BB][PP][CIN/2];        // x^T rounded fp16 pairs
__device__ unsigned g_Q[BB][COUT][PP/2];        // Q rounded fp16 pairs along p
__device__ unsigned g_KT[BB][NH][PP][DH/2];     // K^T rounded (pre-scaled)
__device__ unsigned g_VT[BB][NH][PP][DH/2];     // V^T rounded fp16

// log2(e) / sqrt(128): folded into K so softmax is a bare ex2
#define K_ALPHA 0.12751743f

// ---------------- helpers ----------------
__device__ __forceinline__ unsigned pack2h(float x0, float x1) {
    unsigned h;
    asm("cvt.rn.f16x2.f32 %0, %1, %2;" : "=r"(h) : "f"(x1), "f"(x0));
    return h;
}
__device__ __forceinline__ float fex2(float x) {
    float y;
    asm("ex2.approx.ftz.f32 %0, %1;" : "=f"(y) : "f"(x));
    return y;
}
__device__ __forceinline__ void mma16816(float* c,
    unsigned a0, unsigned a1, unsigned a2, unsigned a3, unsigned b0, unsigned b1)
{
    asm volatile(
        "mma.sync.aligned.m16n8k16.row.col.f32.f16.f16.f32 "
        "{%0,%1,%2,%3}, {%4,%5,%6,%7}, {%8,%9}, {%0,%1,%2,%3};\n"
        : "+f"(c[0]), "+f"(c[1]), "+f"(c[2]), "+f"(c[3])
        : "r"(a0), "r"(a1), "r"(a2), "r"(a3), "r"(b0), "r"(b1));
}

#define CP16(d, s) asm volatile("cp.async.cg.shared.global [%0], [%1], 16;" :: "r"(d), "l"(s) : "memory")
#define CP_COMMIT() asm volatile("cp.async.commit_group;" ::: "memory")
#define CP_WAIT(n)  asm volatile("cp.async.wait_group %0;" :: "n"(n) : "memory")
#define LDSM4(r0, r1, r2, r3, a) \
    asm volatile("ldmatrix.sync.aligned.m8n8.x4.shared.b16 {%0,%1,%2,%3}, [%4];" \
        : "=r"(r0), "=r"(r1), "=r"(r2), "=r"(r3) : "r"(a))

// ---------------- conv W -> rounded fp16 pairs ----------------
__global__ __launch_bounds__(256) void conv_w_kernel(
    const float* __restrict__ Wq, const float* __restrict__ Wk, const float* __restrict__ Wv)
{
    int idx = blockIdx.x * 256 + threadIdx.x;
    int proj = idx >> 18;
    int rem = idx & 262143;
    const float* W = (proj == 0) ? Wq : ((proj == 1) ? Wk : Wv);
    float2 v = *(const float2*)(W + (size_t)rem * 2);
    (&g_W[0][0][0])[(size_t)proj * 262144 + rem] = pack2h(v.x, v.y);
}

// ---------------- conv x -> x^T rounded fp16 pairs ----------------
__global__ __launch_bounds__(256) void conv_x_kernel(const float* __restrict__ x)
{
    __shared__ float sm[64][65];
    int p0 = blockIdx.x * 64, c0 = blockIdx.y * 64, b = blockIdx.z;
    int tid = threadIdx.x;
    for (int t = tid; t < 64 * 64; t += 256) {
        int c = t >> 6, p = t & 63;
        sm[c][p] = x[((size_t)b * CIN + c0 + c) * PP + p0 + p];
    }
    __syncthreads();
    for (int t = tid; t < 64 * 32; t += 256) {
        int p = t >> 5, cp = t & 31;
        size_t o = ((size_t)b * PP + p0 + p) * 256 + (c0 >> 1) + cp;
        (&g_XT[0][0][0])[o] = pack2h(sm[2 * cp][p], sm[2 * cp + 1][p]);
    }
}

// ---------------- Stage 1: cp.async + ldmatrix GEMM  y = W * x ---------
#define G2_STR 20
#define G2_STAGE 5120
#define G2_SMEM (2 * G2_STAGE * 4)

__global__ __launch_bounds__(256, 2) void gemm1b_kernel()
{
    extern __shared__ unsigned su[];
    uint32_t smb = (uint32_t)__cvta_generic_to_shared(su);
    int z = blockIdx.z, proj = z >> 3, b = z & 7;
    int o0 = blockIdx.y * 128, p0 = blockIdx.x * 128;
    const unsigned* gW = &g_W[proj][0][0];
    const unsigned* gX = &g_XT[b][0][0];
    const int tid = threadIdx.x, w = tid >> 5, lane = tid & 31;
    const int g = lane >> 2, q = lane & 3;
    const int tt = lane >> 3, rr = lane & 7;
    const int wo = w >> 2, wp = w & 3;

    float acc[4][4][4];
#pragma unroll
    for (int i = 0; i < 4; i++)
#pragma unroll
        for (int j = 0; j < 4; j++)
#pragma unroll
            for (int e = 0; e < 4; e++) acc[i][j][e] = 0.f;

#define G2_LOAD(c) do { \
        int _s = (c) & 1, _kk = (c) * 16; \
        uint32_t _sb = smb + 4 * (_s * G2_STAGE); \
        for (int t = tid; t < 512; t += 256) { \
            int r = t >> 2, f4 = (t & 3) * 4; \
            uint32_t d = _sb + 4 * (r * G2_STR + f4); \
            CP16(d,            gW + (size_t)(o0 + r) * 256 + _kk + f4); \
            CP16(d + 4 * 2560, gX + (size_t)(p0 + r) * 256 + _kk + f4); \
        } \
    } while (0)

    G2_LOAD(0);
    CP_COMMIT();

    const int fragRow = (tt & 1) * 8 + rr;
    const int fragCol = (tt >> 1) * 4;

    for (int c = 0; c < 16; c++) {
        if (c < 15) {
            G2_LOAD(c + 1);
            CP_COMMIT();
            CP_WAIT(1);
        } else {
            CP_WAIT(0);
        }
        __syncthreads();

        const int s = c & 1;
        const uint32_t aB = smb + 4 * (s * G2_STAGE + (wo * 64 + fragRow) * G2_STR + fragCol);
        const uint32_t bB = smb + 4 * (s * G2_STAGE + 2560 + (wp * 32 + fragRow) * G2_STR + fragCol);
#pragma unroll
        for (int ks = 0; ks < 2; ks++) {
            uint32_t a[4][4];
            uint32_t bh[2][4];
#pragma unroll
            for (int nb = 0; nb < 2; nb++) {
                uint32_t ba = bB + 4 * (16 * nb * G2_STR + 8 * ks);
                LDSM4(bh[nb][0], bh[nb][1], bh[nb][2], bh[nb][3], ba);
            }
#pragma unroll
            for (int mf = 0; mf < 4; mf++) {
                uint32_t aa = aB + 4 * (16 * mf * G2_STR + 8 * ks);
                LDSM4(a[mf][0], a[mf][1], a[mf][2], a[mf][3], aa);
            }
#pragma unroll
            for (int nb = 0; nb < 2; nb++)
#pragma unroll
                for (int mf = 0; mf < 4; mf++) {
                    mma16816(acc[mf][2 * nb],     a[mf][0], a[mf][1], a[mf][2], a[mf][3], bh[nb][0], bh[nb][2]);
                    mma16816(acc[mf][2 * nb + 1], a[mf][0], a[mf][1], a[mf][2], a[mf][3], bh[nb][1], bh[nb][3]);
                }
        }
        __syncthreads();
    }

    float* Y = &g_y[proj][b][0][0];
#pragma unroll
    for (int mf = 0; mf < 4; mf++)
#pragma unroll
        for (int nf = 0; nf < 4; nf++) {
            int oo = o0 + wo * 64 + 16 * mf + g;
            int pp = p0 + wp * 32 + 8 * nf + 2 * q;
            float* r0 = Y + (size_t)oo * PP + pp;
            *(float2*)r0 = make_float2(acc[mf][nf][0], acc[mf][nf][1]);
            *(float2*)(r0 + 8 * PP) = make_float2(acc[mf][nf][2], acc[mf][nf][3]);
        }
}

// ---------------- Stage 2: batch stats -> folded affine ----------------
__global__ __launch_bounds__(256) void stats_kernel(
    const float* __restrict__ gq, const float* __restrict__ bq,
    const float* __restrict__ gk, const float* __restrict__ bk,
    const float* __restrict__ gv, const float* __restrict__ bv)
{
    int o = blockIdx.x, proj = blockIdx.y;
    const float* base = &g_y[proj][0][o][0];
    float s = 0.f, s2 = 0.f;
    for (int t = threadIdx.x; t < BB * PP / 4; t += 256) {
        int b = t >> 9, p4 = (t & 511) * 4;
        float4 v = *(const float4*)&base[(size_t)b * COUT * PP + p4];
        s += v.x + v.y + v.z + v.w;
        s2 += v.x * v.x + v.y * v.y + v.z * v.z + v.w * v.w;
    }
    __shared__ float red0[256], red1[256];
    red0[threadIdx.x] = s; red1[threadIdx.x] = s2;
    __syncthreads();
    for (int st = 128; st > 0; st >>= 1) {
        if (threadIdx.x < st) {
            red0[threadIdx.x] += red0[threadIdx.x + st];
            red1[threadIdx.x] += red1[threadIdx.x + st];
        }
        __syncthreads();
    }
    if (threadIdx.x == 0) {
        const float invn = 1.f / (BB * PP);
        float mean = red0[0] * invn;
        float var = red1[0] * invn - mean * mean;
        const float* gg = (proj == 0) ? gq : ((proj == 1) ? gk : gv);
        const float* be = (proj == 0) ? bq : ((proj == 1) ? bk : bv);
        float sc = gg[o] * rsqrtf(var + 1e-5f);
        g_scale[proj][o] = sc;
        g_shift[proj][o] = be[o] - mean * sc;
    }
}

// ---------------- Stage 3: fold BN+LeakyReLU, emit fp16 operands ----------
__global__ __launch_bounds__(256) void fold_kernel()
{
    __shared__ float sm[64][65];
    int p0 = blockIdx.x * 64, c0 = blockIdx.y * 64;
    int z = blockIdx.z, proj = z >> 3, b = z & 7;
    int tid = threadIdx.x;
    const float post = (proj == 1) ? K_ALPHA : 1.f;
    for (int t = tid; t < 64 * 64; t += 256) {
        int c = t >> 6, p = t & 63;
        float v = g_y[proj][b][c0 + c][p0 + p];
        v = v * g_scale[proj][c0 + c] + g_shift[proj][c0 + c];
        v = (v >= 0.f) ? v : 0.1f * v;
        sm[c][p] = v * post;
    }
    __syncthreads();
    if (proj == 0) {
        for (int t = tid; t < 64 * 32; t += 256) {
            int c = t >> 5, jp = t & 31;
            size_t o = ((size_t)b * COUT + c0 + c) * 1024 + (p0 >> 1) + jp;
            (&g_Q[0][0][0])[o] = pack2h(sm[c][2 * jp], sm[c][2 * jp + 1]);
        }
    } else {
        int h = c0 >> 7, cpo = (c0 & 127) >> 1;
        unsigned* dst = (proj == 1) ? &g_KT[0][0][0][0] : &g_VT[0][0][0][0];
        for (int t = tid; t < 64 * 32; t += 256) {
            int p = t >> 5, cp = t & 31;
            size_t o = ((size_t)(b * NH + h) * PP + p0 + p) * 64 + cpo + cp;
            dst[o] = pack2h(sm[2 * cp][p], sm[2 * cp + 1][p]);
        }
    }
}

// ---------------- Stage 4: pipelined fp16 flash attention, dual sacc ------
// smem (u32): V 0 (2 bufs x 4352)   [prologue stages K (8704 u32) at 0]
//             Q 8704 (2 bufs x 4608)
//             PH 17920 (4608), LR 22528 (128)
// Iter jt: S(jt+1)->sacc_new (MMA first), softmax(sacc_old) interleaves,
//          then O(jt). V(j) in buf j&1; Q(j) in qbuf j&1.
#define OFF_V  0
#define OFF_Q  8704
#define OFF_PH 17920
#define OFF_LR 22528
#define ATTN8_SMEM ((22528 + 128) * 4)

__global__ __launch_bounds__(256) void attn8_kernel(float* __restrict__ out)
{
    extern __shared__ unsigned sm[];
    uint32_t smb = (uint32_t)__cvta_generic_to_shared(sm);
    const int tid = threadIdx.x;
    const int w = tid >> 5, lane = tid & 31;
    const int g = lane >> 2, q = lane & 3;
    const int tt = lane >> 3, rr = lane & 7;
    const int bh = blockIdx.y, b = bh >> 3, h = bh & 7;
    const int i0 = blockIdx.x * 128;

    const unsigned* gK = &g_KT[b][h][0][0];
    const unsigned* gV = &g_VT[b][h][0][0];
    const unsigned* gQ = &g_Q[b][h * 128][0];

    const int aRow = 16 * w + (tt & 1) * 8 + rr;
    const int aCol = (tt >> 1) * 4;
    const int bRow0 = (tt & 1) * 8 + rr;

    // ---- prologue: stage K through smem, extract A-fragments to regs ----
    for (int t = tid; t < 2048; t += 256) {
        int r = t >> 4, f4 = (t & 15) * 4;
        CP16(smb + 4 * (r * 68 + f4), gK + (size_t)(i0 + r) * 64 + f4);
    }
    CP_COMMIT();
    CP_WAIT(0);
    __syncthreads();

    unsigned kh[8][4];
    {
        const uint32_t kB = smb + 4 * (aRow * 68 + aCol);
#pragma unroll
        for (int ks = 0; ks < 8; ks++)
            LDSM4(kh[ks][0], kh[ks][1], kh[ks][2], kh[ks][3], kB + 32 * ks);
    }
    __syncthreads();

    // V(0) -> buf0
    for (int t = tid; t < 1024; t += 256) {
        int r = t >> 4, f4 = (t & 15) * 4;
        CP16(smb + 4 * (OFF_V + r * 68 + f4), gV + (size_t)r * 64 + f4);
    }
    CP_COMMIT();
    // V(1) -> buf1, Q(0) -> qbuf0
    for (int t = tid; t < 1024; t += 256) {
        int r = t >> 4, f4 = (t & 15) * 4;
        CP16(smb + 4 * (OFF_V + 4352 + r * 68 + f4), gV + (size_t)(64 + r) * 64 + f4);
    }
    for (int t = tid; t < 1024; t += 256) {
        int r = t >> 3, f4 = (t & 7) * 4;
        CP16(smb + 4 * (OFF_Q + r * 36 + f4), gQ + (size_t)r * 1024 + f4);
    }
    CP_COMMIT();

    float oacc[8][2][4];
#pragma unroll
    for (int mf = 0; mf < 8; mf++)
#pragma unroll
        for (int nf = 0; nf < 2; nf++)
#pragma unroll
            for (int e = 0; e < 4; e++) oacc[mf][nf][e] = 0.f;
    float l0 = 0.f, l1 = 0.f;
    float saccA[8][4], saccB[8][4];

    // ---- prologue S(0) -> saccA (V(0) resident after wait(1)) ----
    CP_WAIT(1);
    __syncthreads();
#pragma unroll
    for (int nf = 0; nf < 8; nf++)
#pragma unroll
        for (int e = 0; e < 4; e++) saccA[nf][e] = 0.f;
    {
        const uint32_t vBase = smb + 4 * (OFF_V + bRow0 * 68 + aCol);
#pragma unroll
        for (int ks = 0; ks < 8; ks++) {
#pragma unroll
            for (int nb = 0; nb < 4; nb++) {
                uint32_t vh0, vh1, vh2, vh3;
                LDSM4(vh0, vh1, vh2, vh3, vBase + 4 * (nb * 16 * 68) + 32 * ks);
                mma16816(saccA[2 * nb],     kh[ks][0], kh[ks][1], kh[ks][2], kh[ks][3], vh0, vh2);
                mma16816(saccA[2 * nb + 1], kh[ks][0], kh[ks][1], kh[ks][2], kh[ks][3], vh1, vh3);
            }
        }
    }

    // one iteration: S(jt+1)->sN, softmax(sO), O(jt)
#define ATTN_ITER(jt, sO, sN) do { \
        const int qb = (jt) & 1; \
        CP_WAIT(0); \
        __syncthreads(); \
        if ((jt) < 30) { \
            const int jn2 = ((jt) + 2) * 64; \
            for (int t = tid; t < 1024; t += 256) { \
                int r = t >> 4, f4 = (t & 15) * 4; \
                CP16(smb + 4 * (OFF_V + qb * 4352 + r * 68 + f4), \
                     gV + (size_t)(jn2 + r) * 64 + f4); \
            } \
        } \
        if ((jt) < 31) { \
            const int jn = ((jt) + 1) * 64; \
            for (int t = tid; t < 1024; t += 256) { \
                int r = t >> 3, f4 = (t & 7) * 4; \
                CP16(smb + 4 * (OFF_Q + (qb ^ 1) * 4608 + r * 36 + f4), \
                     gQ + (size_t)r * 1024 + (jn >> 1) + f4); \
            } \
            CP_COMMIT(); \
        } \
        if ((jt) < 31) { \
            _Pragma("unroll") \
            for (int nf = 0; nf < 8; nf++) \
                _Pragma("unroll") \
                for (int e = 0; e < 4; e++) sN[nf][e] = 0.f; \
            const uint32_t vBase = smb + 4 * (OFF_V + (qb ^ 1) * 4352 + bRow0 * 68 + aCol); \
            _Pragma("unroll") \
            for (int ks = 0; ks < 8; ks++) { \
                _Pragma("unroll") \
                for (int nb = 0; nb < 4; nb++) { \
                    uint32_t vh0, vh1, vh2, vh3; \
                    LDSM4(vh0, vh1, vh2, vh3, vBase + 4 * (nb * 16 * 68) + 32 * ks); \
                    mma16816(sN[2 * nb],     kh[ks][0], kh[ks][1], kh[ks][2], kh[ks][3], vh0, vh2); \
                    mma16816(sN[2 * nb + 1], kh[ks][0], kh[ks][1], kh[ks][2], kh[ks][3], vh1, vh3); \
                } \
            } \
        } \
        _Pragma("unroll") \
        for (int nf = 0; nf < 8; nf++) { \
            float e0 = fex2(sO[nf][0]); \
            float e1 = fex2(sO[nf][1]); \
            float e2 = fex2(sO[nf][2]); \
            float e3 = fex2(sO[nf][3]); \
            l0 += e0 + e1; \
            l1 += e2 + e3; \
            int jp = 4 * nf + q; \
            sm[OFF_PH + (16 * w + g) * 36 + jp] = pack2h(e0, e1); \
            sm[OFF_PH + (16 * w + 8 + g) * 36 + jp] = pack2h(e2, e3); \
        } \
        __syncwarp(); \
        const uint32_t pBase = smb + 4 * (OFF_PH + aRow * 36 + aCol); \
        const uint32_t qBase = smb + 4 * (OFF_Q + qb * 4608 + bRow0 * 36 + aCol); \
        _Pragma("unroll") \
        for (int ks = 0; ks < 4; ks++) { \
            uint32_t ph0, ph1, ph2, ph3; \
            LDSM4(ph0, ph1, ph2, ph3, pBase + 32 * ks); \
            _Pragma("unroll") \
            for (int mf = 0; mf < 8; mf++) { \
                uint32_t qh0, qh1, qh2, qh3; \
                LDSM4(qh0, qh1, qh2, qh3, qBase + 4 * (16 * mf * 36) + 32 * ks); \
                mma16816(oacc[mf][0], qh0, qh1, qh2, qh3, ph0, ph2); \
                mma16816(oacc[mf][1], qh0, qh1, qh2, qh3, ph1, ph3); \
            } \
        } \
    } while (0)

    for (int jt = 0; jt < 32; jt += 2) {
        ATTN_ITER(jt,     saccA, saccB);
        ATTN_ITER(jt + 1, saccB, saccA);
    }
#undef ATTN_ITER

    l0 += __shfl_xor_sync(0xffffffffu, l0, 1);
    l0 += __shfl_xor_sync(0xffffffffu, l0, 2);
    l1 += __shfl_xor_sync(0xffffffffu, l1, 1);
    l1 += __shfl_xor_sync(0xffffffffu, l1, 2);
    float* lrow = (float*)&sm[OFF_LR];
    if (q == 0) {
        lrow[16 * w + g] = 1.f / l0;
        lrow[16 * w + 8 + g] = 1.f / l1;
    }
    __syncthreads();
#pragma unroll
    for (int nf = 0; nf < 2; nf++) {
        int ic = 16 * w + 8 * nf + 2 * q;
        float il0 = lrow[ic], il1 = lrow[ic + 1];
#pragma unroll
        for (int mf = 0; mf < 8; mf++) {
            int c = h * 128 + 16 * mf + g;
            float* p0 = out + ((size_t)b * COUT + c) * PP + i0 + ic;
            *(float2*)p0 = make_float2(oacc[mf][nf][0] * il0, oacc[mf][nf][1] * il1);
            float* p1 = p0 + 8 * PP;
            *(float2*)p1 = make_float2(oacc[mf][nf][2] * il0, oacc[mf][nf][3] * il1);
        }
    }
}

// ---------------------------------------------------------------------------
extern "C" void kernel_launch(void* const* d_in, const int* in_sizes, int n_in,
                              void* d_out, int out_size)
{
    const float* x  = (const float*)d_in[0];
    const float* Wq = (const float*)d_in[1];
    const float* gq = (const float*)d_in[2];
    const float* bq = (const float*)d_in[3];
    const float* Wk = (const float*)d_in[4];
    const float* gk = (const float*)d_in[5];
    const float* bk = (const float*)d_in[6];
    const float* Wv = (const float*)d_in[7];
    const float* gv = (const float*)d_in[8];
    const float* bv = (const float*)d_in[9];
    float* out = (float*)d_out;

    conv_w_kernel<<<3 * COUT * (CIN / 2) / 256, 256>>>(Wq, Wk, Wv);
    conv_x_kernel<<<dim3(PP / 64, CIN / 64, BB), 256>>>(x);

    cudaFuncSetAttribute(gemm1b_kernel, cudaFuncAttributeMaxDynamicSharedMemorySize, G2_SMEM);
    gemm1b_kernel<<<dim3(PP / 128, COUT / 128, 3 * BB), 256, G2_SMEM>>>();

    stats_kernel<<<dim3(COUT, 3), 256>>>(gq, bq, gk, bk, gv, bv);
    fold_kernel<<<dim3(PP / 64, COUT / 64, 3 * BB), 256>>>();

    cudaFuncSetAttribute(attn8_kernel, cudaFuncAttributeMaxDynamicSharedMemorySize, ATTN8_SMEM);
    attn8_kernel<<<dim3(PP / 128, BB * NH), 256, ATTN8_SMEM>>>(out);
}

// round 14
// speedup vs baseline: 14.8374x; 1.1000x over previous
#include <cuda_runtime.h>
#include <cuda_fp16.h>
#include <math.h>
#include <stdint.h>

#define BB 8
#define CIN 512
#define COUT 1024
#define PP 2048
#define NH 8
#define DH 128

// ---------------- scratch (device globals; no allocations) ----------------
__device__ unsigned g_yh[3][BB][COUT][PP/2];    // fp16 projections (pre-BN), pairs along p
__device__ float    g_sum[3][COUT];             // batch stats accumulators
__device__ float    g_sumsq[3][COUT];
__device__ float    g_scale[3][COUT];
__device__ float    g_shift[3][COUT];
__device__ unsigned g_W[3][COUT][CIN/2];        // W rounded fp16 pairs along c
__device__ unsigned g_XT[BB][PP][CIN/2];        // x^T rounded fp16 pairs
__device__ unsigned g_Q[BB][COUT][PP/2];        // Q rounded fp16 pairs along p
__device__ unsigned g_KT[BB][NH][PP][DH/2];     // K^T rounded (pre-scaled)
__device__ unsigned g_VT[BB][NH][PP][DH/2];     // V^T rounded fp16

// log2(e) / sqrt(128): folded into K so softmax is a bare ex2
#define K_ALPHA 0.12751743f

// ---------------- helpers ----------------
__device__ __forceinline__ unsigned pack2h(float x0, float x1) {
    unsigned h;
    asm("cvt.rn.f16x2.f32 %0, %1, %2;" : "=r"(h) : "f"(x1), "f"(x0));
    return h;
}
__device__ __forceinline__ float2 unpack2h(unsigned u) {
    __half2 h = *(__half2*)&u;
    return make_float2(__half2float(__low2half(h)), __half2float(__high2half(h)));
}
__device__ __forceinline__ float fex2(float x) {
    float y;
    asm("ex2.approx.ftz.f32 %0, %1;" : "=f"(y) : "f"(x));
    return y;
}
__device__ __forceinline__ void mma16816(float* c,
    unsigned a0, unsigned a1, unsigned a2, unsigned a3, unsigned b0, unsigned b1)
{
    asm volatile(
        "mma.sync.aligned.m16n8k16.row.col.f32.f16.f16.f32 "
        "{%0,%1,%2,%3}, {%4,%5,%6,%7}, {%8,%9}, {%0,%1,%2,%3};\n"
        : "+f"(c[0]), "+f"(c[1]), "+f"(c[2]), "+f"(c[3])
        : "r"(a0), "r"(a1), "r"(a2), "r"(a3), "r"(b0), "r"(b1));
}

#define CP16(d, s) asm volatile("cp.async.cg.shared.global [%0], [%1], 16;" :: "r"(d), "l"(s) : "memory")
#define CP_COMMIT() asm volatile("cp.async.commit_group;" ::: "memory")
#define CP_WAIT(n)  asm volatile("cp.async.wait_group %0;" :: "n"(n) : "memory")
#define LDSM4(r0, r1, r2, r3, a) \
    asm volatile("ldmatrix.sync.aligned.m8n8.x4.shared.b16 {%0,%1,%2,%3}, [%4];" \
        : "=r"(r0), "=r"(r1), "=r"(r2), "=r"(r3) : "r"(a))

// ---------------- conv W -> fp16 pairs; zero stats accumulators ------------
__global__ __launch_bounds__(256) void conv_w_kernel(
    const float* __restrict__ Wq, const float* __restrict__ Wk, const float* __restrict__ Wv)
{
    int idx = blockIdx.x * 256 + threadIdx.x;
    if (idx < 3 * COUT) {
        (&g_sum[0][0])[idx] = 0.f;
        (&g_sumsq[0][0])[idx] = 0.f;
    }
    int proj = idx >> 18;
    int rem = idx & 262143;
    const float* W = (proj == 0) ? Wq : ((proj == 1) ? Wk : Wv);
    float2 v = *(const float2*)(W + (size_t)rem * 2);
    (&g_W[0][0][0])[(size_t)proj * 262144 + rem] = pack2h(v.x, v.y);
}

// ---------------- conv x -> x^T rounded fp16 pairs ----------------
__global__ __launch_bounds__(256) void conv_x_kernel(const float* __restrict__ x)
{
    __shared__ float sm[64][65];
    int p0 = blockIdx.x * 64, c0 = blockIdx.y * 64, b = blockIdx.z;
    int tid = threadIdx.x;
    for (int t = tid; t < 64 * 64; t += 256) {
        int c = t >> 6, p = t & 63;
        sm[c][p] = x[((size_t)b * CIN + c0 + c) * PP + p0 + p];
    }
    __syncthreads();
    for (int t = tid; t < 64 * 32; t += 256) {
        int p = t >> 5, cp = t & 31;
        size_t o = ((size_t)b * PP + p0 + p) * 256 + (c0 >> 1) + cp;
        (&g_XT[0][0][0])[o] = pack2h(sm[2 * cp][p], sm[2 * cp + 1][p]);
    }
}

// ---------------- Stage 1: GEMM y = W*x, fp16 store + fused stats ---------
#define G2_STR 20
#define G2_STAGE 5120
#define G2_SMEM (2 * G2_STAGE * 4)

__global__ __launch_bounds__(256, 2) void gemm1c_kernel()
{
    extern __shared__ unsigned su[];
    uint32_t smb = (uint32_t)__cvta_generic_to_shared(su);
    int z = blockIdx.z, proj = z >> 3, b = z & 7;
    int o0 = blockIdx.y * 128, p0 = blockIdx.x * 128;
    const unsigned* gW = &g_W[proj][0][0];
    const unsigned* gX = &g_XT[b][0][0];
    const int tid = threadIdx.x, w = tid >> 5, lane = tid & 31;
    const int g = lane >> 2, q = lane & 3;
    const int tt = lane >> 3, rr = lane & 7;
    const int wo = w >> 2, wp = w & 3;

    float acc[4][4][4];
#pragma unroll
    for (int i = 0; i < 4; i++)
#pragma unroll
        for (int j = 0; j < 4; j++)
#pragma unroll
            for (int e = 0; e < 4; e++) acc[i][j][e] = 0.f;

#define G2_LOAD(c) do { \
        int _s = (c) & 1, _kk = (c) * 16; \
        uint32_t _sb = smb + 4 * (_s * G2_STAGE); \
        for (int t = tid; t < 512; t += 256) { \
            int r = t >> 2, f4 = (t & 3) * 4; \
            uint32_t d = _sb + 4 * (r * G2_STR + f4); \
            CP16(d,            gW + (size_t)(o0 + r) * 256 + _kk + f4); \
            CP16(d + 4 * 2560, gX + (size_t)(p0 + r) * 256 + _kk + f4); \
        } \
    } while (0)

    G2_LOAD(0);
    CP_COMMIT();

    const int fragRow = (tt & 1) * 8 + rr;
    const int fragCol = (tt >> 1) * 4;

    for (int c = 0; c < 16; c++) {
        if (c < 15) {
            G2_LOAD(c + 1);
            CP_COMMIT();
            CP_WAIT(1);
        } else {
            CP_WAIT(0);
        }
        __syncthreads();

        const int s = c & 1;
        const uint32_t aB = smb + 4 * (s * G2_STAGE + (wo * 64 + fragRow) * G2_STR + fragCol);
        const uint32_t bB = smb + 4 * (s * G2_STAGE + 2560 + (wp * 32 + fragRow) * G2_STR + fragCol);
#pragma unroll
        for (int ks = 0; ks < 2; ks++) {
            uint32_t a[4][4];
            uint32_t bh[2][4];
#pragma unroll
            for (int nb = 0; nb < 2; nb++) {
                uint32_t ba = bB + 4 * (16 * nb * G2_STR + 8 * ks);
                LDSM4(bh[nb][0], bh[nb][1], bh[nb][2], bh[nb][3], ba);
            }
#pragma unroll
            for (int mf = 0; mf < 4; mf++) {
                uint32_t aa = aB + 4 * (16 * mf * G2_STR + 8 * ks);
                LDSM4(a[mf][0], a[mf][1], a[mf][2], a[mf][3], aa);
            }
#pragma unroll
            for (int nb = 0; nb < 2; nb++)
#pragma unroll
                for (int mf = 0; mf < 4; mf++) {
                    mma16816(acc[mf][2 * nb],     a[mf][0], a[mf][1], a[mf][2], a[mf][3], bh[nb][0], bh[nb][2]);
                    mma16816(acc[mf][2 * nb + 1], a[mf][0], a[mf][1], a[mf][2], a[mf][3], bh[nb][1], bh[nb][3]);
                }
        }
        __syncthreads();
    }

    // ---- store y as fp16 pairs + fused per-channel stats ----
    unsigned* Yh = &g_yh[proj][b][0][0];
    const int pp2 = (p0 >> 1) + wp * 16 + q;     // u32 column
#pragma unroll
    for (int mf = 0; mf < 4; mf++) {
        int oo = o0 + wo * 64 + 16 * mf + g;
#pragma unroll
        for (int nf = 0; nf < 4; nf++) {
            Yh[(size_t)oo * 1024 + pp2 + 4 * nf] = pack2h(acc[mf][nf][0], acc[mf][nf][1]);
            Yh[(size_t)(oo + 8) * 1024 + pp2 + 4 * nf] = pack2h(acc[mf][nf][2], acc[mf][nf][3]);
        }
    }
#pragma unroll
    for (int mf = 0; mf < 4; mf++) {
#pragma unroll
        for (int half = 0; half < 2; half++) {
            float s = 0.f, s2 = 0.f;
#pragma unroll
            for (int nf = 0; nf < 4; nf++) {
                float v0 = acc[mf][nf][2 * half], v1 = acc[mf][nf][2 * half + 1];
                s += v0 + v1;
                s2 += v0 * v0 + v1 * v1;
            }
            s += __shfl_xor_sync(0xffffffffu, s, 1);
            s += __shfl_xor_sync(0xffffffffu, s, 2);
            s2 += __shfl_xor_sync(0xffffffffu, s2, 1);
            s2 += __shfl_xor_sync(0xffffffffu, s2, 2);
            if (q == 0) {
                int o = o0 + wo * 64 + 16 * mf + g + 8 * half;
                atomicAdd(&g_sum[proj][o], s);
                atomicAdd(&g_sumsq[proj][o], s2);
            }
        }
    }
}

// ---------------- Stage 2: finalize stats -> folded affine ----------------
__global__ __launch_bounds__(256) void finalize_stats_kernel(
    const float* __restrict__ gq, const float* __restrict__ bq,
    const float* __restrict__ gk, const float* __restrict__ bk,
    const float* __restrict__ gv, const float* __restrict__ bv)
{
    int idx = blockIdx.x * 256 + threadIdx.x;   // 3*1024
    int proj = idx >> 10, o = idx & 1023;
    const float invn = 1.f / (BB * PP);
    float mean = g_sum[proj][o] * invn;
    float var = g_sumsq[proj][o] * invn - mean * mean;
    const float* gg = (proj == 0) ? gq : ((proj == 1) ? gk : gv);
    const float* be = (proj == 0) ? bq : ((proj == 1) ? bk : bv);
    float sc = gg[o] * rsqrtf(var + 1e-5f);
    g_scale[proj][o] = sc;
    g_shift[proj][o] = be[o] - mean * sc;
}

// ---------------- Stage 3: fold BN+LeakyReLU from fp16 y ----------------
__global__ __launch_bounds__(256) void fold2_kernel()
{
    int p0 = blockIdx.x * 64, c0 = blockIdx.y * 64;
    int z = blockIdx.z, proj = z >> 3, b = z & 7;
    int tid = threadIdx.x;

    if (proj == 0) {
        // Q: elementwise on u32 pairs (same layout in and out)
        for (int t = tid; t < 64 * 32; t += 256) {
            int c = c0 + (t >> 5), jp = (p0 >> 1) + (t & 31);
            float2 v = unpack2h(g_yh[0][b][c][jp]);
            float sc = g_scale[0][c], sh = g_shift[0][c];
            float v0 = v.x * sc + sh, v1 = v.y * sc + sh;
            v0 = (v0 >= 0.f) ? v0 : 0.1f * v0;
            v1 = (v1 >= 0.f) ? v1 : 0.1f * v1;
            g_Q[b][c][jp] = pack2h(v0, v1);
        }
        return;
    }

    __shared__ float sm[64][65];
    const float post = (proj == 1) ? K_ALPHA : 1.f;
    for (int t = tid; t < 64 * 32; t += 256) {
        int c = t >> 5, jp = t & 31;
        float2 v = unpack2h(g_yh[proj][b][c0 + c][(p0 >> 1) + jp]);
        float sc = g_scale[proj][c0 + c], sh = g_shift[proj][c0 + c];
        float v0 = v.x * sc + sh, v1 = v.y * sc + sh;
        v0 = ((v0 >= 0.f) ? v0 : 0.1f * v0) * post;
        v1 = ((v1 >= 0.f) ? v1 : 0.1f * v1) * post;
        sm[c][2 * jp] = v0;
        sm[c][2 * jp + 1] = v1;
    }
    __syncthreads();
    int h = c0 >> 7, cpo = (c0 & 127) >> 1;
    unsigned* dst = (proj == 1) ? &g_KT[0][0][0][0] : &g_VT[0][0][0][0];
    for (int t = tid; t < 64 * 32; t += 256) {
        int p = t >> 5, cp = t & 31;
        size_t o = ((size_t)(b * NH + h) * PP + p0 + p) * 64 + cpo + cp;
        dst[o] = pack2h(sm[2 * cp][p], sm[2 * cp + 1][p]);
    }
}

// ---------------- Stage 4: pipelined fp16 flash attention, dual sacc ------
#define OFF_V  0
#define OFF_Q  8704
#define OFF_PH 17920
#define OFF_LR 22528
#define ATTN8_SMEM ((22528 + 128) * 4)

__global__ __launch_bounds__(256) void attn8_kernel(float* __restrict__ out)
{
    extern __shared__ unsigned sm[];
    uint32_t smb = (uint32_t)__cvta_generic_to_shared(sm);
    const int tid = threadIdx.x;
    const int w = tid >> 5, lane = tid & 31;
    const int g = lane >> 2, q = lane & 3;
    const int tt = lane >> 3, rr = lane & 7;
    const int bh = blockIdx.y, b = bh >> 3, h = bh & 7;
    const int i0 = blockIdx.x * 128;

    const unsigned* gK = &g_KT[b][h][0][0];
    const unsigned* gV = &g_VT[b][h][0][0];
    const unsigned* gQ = &g_Q[b][h * 128][0];

    const int aRow = 16 * w + (tt & 1) * 8 + rr;
    const int aCol = (tt >> 1) * 4;
    const int bRow0 = (tt & 1) * 8 + rr;

    // ---- prologue: stage K through smem, extract A-fragments to regs ----
    for (int t = tid; t < 2048; t += 256) {
        int r = t >> 4, f4 = (t & 15) * 4;
        CP16(smb + 4 * (r * 68 + f4), gK + (size_t)(i0 + r) * 64 + f4);
    }
    CP_COMMIT();
    CP_WAIT(0);
    __syncthreads();

    unsigned kh[8][4];
    {
        const uint32_t kB = smb + 4 * (aRow * 68 + aCol);
#pragma unroll
        for (int ks = 0; ks < 8; ks++)
            LDSM4(kh[ks][0], kh[ks][1], kh[ks][2], kh[ks][3], kB + 32 * ks);
    }
    __syncthreads();

    // V(0) -> buf0
    for (int t = tid; t < 1024; t += 256) {
        int r = t >> 4, f4 = (t & 15) * 4;
        CP16(smb + 4 * (OFF_V + r * 68 + f4), gV + (size_t)r * 64 + f4);
    }
    CP_COMMIT();
    // V(1) -> buf1, Q(0) -> qbuf0
    for (int t = tid; t < 1024; t += 256) {
        int r = t >> 4, f4 = (t & 15) * 4;
        CP16(smb + 4 * (OFF_V + 4352 + r * 68 + f4), gV + (size_t)(64 + r) * 64 + f4);
    }
    for (int t = tid; t < 1024; t += 256) {
        int r = t >> 3, f4 = (t & 7) * 4;
        CP16(smb + 4 * (OFF_Q + r * 36 + f4), gQ + (size_t)r * 1024 + f4);
    }
    CP_COMMIT();

    float oacc[8][2][4];
#pragma unroll
    for (int mf = 0; mf < 8; mf++)
#pragma unroll
        for (int nf = 0; nf < 2; nf++)
#pragma unroll
            for (int e = 0; e < 4; e++) oacc[mf][nf][e] = 0.f;
    float l0 = 0.f, l1 = 0.f;
    float saccA[8][4], saccB[8][4];

    // ---- prologue S(0) -> saccA (V(0) resident after wait(1)) ----
    CP_WAIT(1);
    __syncthreads();
#pragma unroll
    for (int nf = 0; nf < 8; nf++)
#pragma unroll
        for (int e = 0; e < 4; e++) saccA[nf][e] = 0.f;
    {
        const uint32_t vBase = smb + 4 * (OFF_V + bRow0 * 68 + aCol);
#pragma unroll
        for (int ks = 0; ks < 8; ks++) {
#pragma unroll
            for (int nb = 0; nb < 4; nb++) {
                uint32_t vh0, vh1, vh2, vh3;
                LDSM4(vh0, vh1, vh2, vh3, vBase + 4 * (nb * 16 * 68) + 32 * ks);
                mma16816(saccA[2 * nb],     kh[ks][0], kh[ks][1], kh[ks][2], kh[ks][3], vh0, vh2);
                mma16816(saccA[2 * nb + 1], kh[ks][0], kh[ks][1], kh[ks][2], kh[ks][3], vh1, vh3);
            }
        }
    }

#define ATTN_ITER(jt, sO, sN) do { \
        const int qb = (jt) & 1; \
        CP_WAIT(0); \
        __syncthreads(); \
        if ((jt) < 30) { \
            const int jn2 = ((jt) + 2) * 64; \
            for (int t = tid; t < 1024; t += 256) { \
                int r = t >> 4, f4 = (t & 15) * 4; \
                CP16(smb + 4 * (OFF_V + qb * 4352 + r * 68 + f4), \
                     gV + (size_t)(jn2 + r) * 64 + f4); \
            } \
        } \
        if ((jt) < 31) { \
            const int jn = ((jt) + 1) * 64; \
            for (int t = tid; t < 1024; t += 256) { \
                int r = t >> 3, f4 = (t & 7) * 4; \
                CP16(smb + 4 * (OFF_Q + (qb ^ 1) * 4608 + r * 36 + f4), \
                     gQ + (size_t)r * 1024 + (jn >> 1) + f4); \
            } \
            CP_COMMIT(); \
        } \
        if ((jt) < 31) { \
            _Pragma("unroll") \
            for (int nf = 0; nf < 8; nf++) \
                _Pragma("unroll") \
                for (int e = 0; e < 4; e++) sN[nf][e] = 0.f; \
            const uint32_t vBase = smb + 4 * (OFF_V + (qb ^ 1) * 4352 + bRow0 * 68 + aCol); \
            _Pragma("unroll") \
            for (int ks = 0; ks < 8; ks++) { \
                _Pragma("unroll") \
                for (int nb = 0; nb < 4; nb++) { \
                    uint32_t vh0, vh1, vh2, vh3; \
                    LDSM4(vh0, vh1, vh2, vh3, vBase + 4 * (nb * 16 * 68) + 32 * ks); \
                    mma16816(sN[2 * nb],     kh[ks][0], kh[ks][1], kh[ks][2], kh[ks][3], vh0, vh2); \
                    mma16816(sN[2 * nb + 1], kh[ks][0], kh[ks][1], kh[ks][2], kh[ks][3], vh1, vh3); \
                } \
            } \
        } \
        _Pragma("unroll") \
        for (int nf = 0; nf < 8; nf++) { \
            float e0 = fex2(sO[nf][0]); \
            float e1 = fex2(sO[nf][1]); \
            float e2 = fex2(sO[nf][2]); \
            float e3 = fex2(sO[nf][3]); \
            l0 += e0 + e1; \
            l1 += e2 + e3; \
            int jp = 4 * nf + q; \
            sm[OFF_PH + (16 * w + g) * 36 + jp] = pack2h(e0, e1); \
            sm[OFF_PH + (16 * w + 8 + g) * 36 + jp] = pack2h(e2, e3); \
        } \
        __syncwarp(); \
        const uint32_t pBase = smb + 4 * (OFF_PH + aRow * 36 + aCol); \
        const uint32_t qBase = smb + 4 * (OFF_Q + qb * 4608 + bRow0 * 36 + aCol); \
        _Pragma("unroll") \
        for (int ks = 0; ks < 4; ks++) { \
            uint32_t ph0, ph1, ph2, ph3; \
            LDSM4(ph0, ph1, ph2, ph3, pBase + 32 * ks); \
            _Pragma("unroll") \
            for (int mf = 0; mf < 8; mf++) { \
                uint32_t qh0, qh1, qh2, qh3; \
                LDSM4(qh0, qh1, qh2, qh3, qBase + 4 * (16 * mf * 36) + 32 * ks); \
                mma16816(oacc[mf][0], qh0, qh1, qh2, qh3, ph0, ph2); \
                mma16816(oacc[mf][1], qh0, qh1, qh2, qh3, ph1, ph3); \
            } \
        } \
    } while (0)

    for (int jt = 0; jt < 32; jt += 2) {
        ATTN_ITER(jt,     saccA, saccB);
        ATTN_ITER(jt + 1, saccB, saccA);
    }
#undef ATTN_ITER

    l0 += __shfl_xor_sync(0xffffffffu, l0, 1);
    l0 += __shfl_xor_sync(0xffffffffu, l0, 2);
    l1 += __shfl_xor_sync(0xffffffffu, l1, 1);
    l1 += __shfl_xor_sync(0xffffffffu, l1, 2);
    float* lrow = (float*)&sm[OFF_LR];
    if (q == 0) {
        lrow[16 * w + g] = 1.f / l0;
        lrow[16 * w + 8 + g] = 1.f / l1;
    }
    __syncthreads();
#pragma unroll
    for (int nf = 0; nf < 2; nf++) {
        int ic = 16 * w + 8 * nf + 2 * q;
        float il0 = lrow[ic], il1 = lrow[ic + 1];
#pragma unroll
        for (int mf = 0; mf < 8; mf++) {
            int c = h * 128 + 16 * mf + g;
            float* p0 = out + ((size_t)b * COUT + c) * PP + i0 + ic;
            *(float2*)p0 = make_float2(oacc[mf][nf][0] * il0, oacc[mf][nf][1] * il1);
            float* p1 = p0 + 8 * PP;
            *(float2*)p1 = make_float2(oacc[mf][nf][2] * il0, oacc[mf][nf][3] * il1);
        }
    }
}

// ---------------------------------------------------------------------------
extern "C" void kernel_launch(void* const* d_in, const int* in_sizes, int n_in,
                              void* d_out, int out_size)
{
    const float* x  = (const float*)d_in[0];
    const float* Wq = (const float*)d_in[1];
    const float* gq = (const float*)d_in[2];
    const float* bq = (const float*)d_in[3];
    const float* Wk = (const float*)d_in[4];
    const float* gk = (const float*)d_in[5];
    const float* bk = (const float*)d_in[6];
    const float* Wv = (const float*)d_in[7];
    const float* gv = (const float*)d_in[8];
    const float* bv = (const float*)d_in[9];
    float* out = (float*)d_out;

    conv_w_kernel<<<3 * COUT * (CIN / 2) / 256, 256>>>(Wq, Wk, Wv);
    conv_x_kernel<<<dim3(PP / 64, CIN / 64, BB), 256>>>(x);

    cudaFuncSetAttribute(gemm1c_kernel, cudaFuncAttributeMaxDynamicSharedMemorySize, G2_SMEM);
    gemm1c_kernel<<<dim3(PP / 128, COUT / 128, 3 * BB), 256, G2_SMEM>>>();

    finalize_stats_kernel<<<12, 256>>>(gq, bq, gk, bk, gv, bv);
    fold2_kernel<<<dim3(PP / 64, COUT / 64, 3 * BB), 256>>>();

    cudaFuncSetAttribute(attn8_kernel, cudaFuncAttributeMaxDynamicSharedMemorySize, ATTN8_SMEM);
    attn8_kernel<<<dim3(PP / 128, BB * NH), 256, ATTN8_SMEM>>>(out);
}

// round 15
// speedup vs baseline: 15.4258x; 1.0397x over previous
#include <cuda_runtime.h>
#include <cuda_fp16.h>
#include <math.h>
#include <stdint.h>

#define BB 8
#define CIN 512
#define COUT 1024
#define PP 2048
#define NH 8
#define DH 128

// ---------------- scratch (device globals; no allocations) ----------------
__device__ unsigned g_yh[3][BB][COUT][PP/2];    // fp16 projections (pre-BN), pairs along p
__device__ float    g_sum[3][COUT];             // batch stats accumulators
__device__ float    g_sumsq[3][COUT];
__device__ float    g_scale[3][COUT];
__device__ float    g_shift[3][COUT];
__device__ unsigned g_W[3][COUT][CIN/2];        // W rounded fp16 pairs along c
__device__ unsigned g_XT[BB][PP][CIN/2];        // x^T rounded fp16 pairs
__device__ unsigned g_Q[BB][COUT][PP/2];        // Q rounded fp16 pairs along p
__device__ unsigned g_KT[BB][NH][PP][DH/2];     // K^T rounded (pre-scaled)
__device__ unsigned g_VT[BB][NH][PP][DH/2];     // V^T rounded fp16

// log2(e) / sqrt(128): folded into K so softmax is a bare ex2
#define K_ALPHA 0.12751743f

// ---------------- helpers ----------------
__device__ __forceinline__ unsigned pack2h(float x0, float x1) {
    unsigned h;
    asm("cvt.rn.f16x2.f32 %0, %1, %2;" : "=r"(h) : "f"(x1), "f"(x0));
    return h;
}
__device__ __forceinline__ float2 unpack2h(unsigned u) {
    __half2 h = *(__half2*)&u;
    return make_float2(__half2float(__low2half(h)), __half2float(__high2half(h)));
}
__device__ __forceinline__ float fex2(float x) {
    float y;
    asm("ex2.approx.ftz.f32 %0, %1;" : "=f"(y) : "f"(x));
    return y;
}
__device__ __forceinline__ void mma16816(float* c,
    unsigned a0, unsigned a1, unsigned a2, unsigned a3, unsigned b0, unsigned b1)
{
    asm volatile(
        "mma.sync.aligned.m16n8k16.row.col.f32.f16.f16.f32 "
        "{%0,%1,%2,%3}, {%4,%5,%6,%7}, {%8,%9}, {%0,%1,%2,%3};\n"
        : "+f"(c[0]), "+f"(c[1]), "+f"(c[2]), "+f"(c[3])
        : "r"(a0), "r"(a1), "r"(a2), "r"(a3), "r"(b0), "r"(b1));
}

#define CP16(d, s) asm volatile("cp.async.cg.shared.global [%0], [%1], 16;" :: "r"(d), "l"(s) : "memory")
#define CP_COMMIT() asm volatile("cp.async.commit_group;" ::: "memory")
#define CP_WAIT(n)  asm volatile("cp.async.wait_group %0;" :: "n"(n) : "memory")
#define LDSM4(r0, r1, r2, r3, a) \
    asm volatile("ldmatrix.sync.aligned.m8n8.x4.shared.b16 {%0,%1,%2,%3}, [%4];" \
        : "=r"(r0), "=r"(r1), "=r"(r2), "=r"(r3) : "r"(a))

// ---------------- conv W -> fp16 pairs; zero stats accumulators ------------
__global__ __launch_bounds__(256) void conv_w_kernel(
    const float* __restrict__ Wq, const float* __restrict__ Wk, const float* __restrict__ Wv)
{
    int idx = blockIdx.x * 256 + threadIdx.x;
    if (idx < 3 * COUT) {
        (&g_sum[0][0])[idx] = 0.f;
        (&g_sumsq[0][0])[idx] = 0.f;
    }
    int proj = idx >> 18;
    int rem = idx & 262143;
    const float* W = (proj == 0) ? Wq : ((proj == 1) ? Wk : Wv);
    float2 v = *(const float2*)(W + (size_t)rem * 2);
    (&g_W[0][0][0])[(size_t)proj * 262144 + rem] = pack2h(v.x, v.y);
}

// ---------------- conv x -> x^T rounded fp16 pairs ----------------
__global__ __launch_bounds__(256) void conv_x_kernel(const float* __restrict__ x)
{
    __shared__ float sm[64][65];
    int p0 = blockIdx.x * 64, c0 = blockIdx.y * 64, b = blockIdx.z;
    int tid = threadIdx.x;
    for (int t = tid; t < 64 * 64; t += 256) {
        int c = t >> 6, p = t & 63;
        sm[c][p] = x[((size_t)b * CIN + c0 + c) * PP + p0 + p];
    }
    __syncthreads();
    for (int t = tid; t < 64 * 32; t += 256) {
        int p = t >> 5, cp = t & 31;
        size_t o = ((size_t)b * PP + p0 + p) * 256 + (c0 >> 1) + cp;
        (&g_XT[0][0][0])[o] = pack2h(sm[2 * cp][p], sm[2 * cp + 1][p]);
    }
}

// ---------------- Stage 1: GEMM y = W*x, fp16 store + fused stats ---------
#define G2_STR 20
#define G2_STAGE 5120
#define G2_SMEM (2 * G2_STAGE * 4)

__global__ __launch_bounds__(256, 2) void gemm1c_kernel()
{
    extern __shared__ unsigned su[];
    uint32_t smb = (uint32_t)__cvta_generic_to_shared(su);
    int z = blockIdx.z, proj = z >> 3, b = z & 7;
    int o0 = blockIdx.y * 128, p0 = blockIdx.x * 128;
    const unsigned* gW = &g_W[proj][0][0];
    const unsigned* gX = &g_XT[b][0][0];
    const int tid = threadIdx.x, w = tid >> 5, lane = tid & 31;
    const int g = lane >> 2, q = lane & 3;
    const int tt = lane >> 3, rr = lane & 7;
    const int wo = w >> 2, wp = w & 3;

    float acc[4][4][4];
#pragma unroll
    for (int i = 0; i < 4; i++)
#pragma unroll
        for (int j = 0; j < 4; j++)
#pragma unroll
            for (int e = 0; e < 4; e++) acc[i][j][e] = 0.f;

#define G2_LOAD(c) do { \
        int _s = (c) & 1, _kk = (c) * 16; \
        uint32_t _sb = smb + 4 * (_s * G2_STAGE); \
        for (int t = tid; t < 512; t += 256) { \
            int r = t >> 2, f4 = (t & 3) * 4; \
            uint32_t d = _sb + 4 * (r * G2_STR + f4); \
            CP16(d,            gW + (size_t)(o0 + r) * 256 + _kk + f4); \
            CP16(d + 4 * 2560, gX + (size_t)(p0 + r) * 256 + _kk + f4); \
        } \
    } while (0)

    G2_LOAD(0);
    CP_COMMIT();

    const int fragRow = (tt & 1) * 8 + rr;
    const int fragCol = (tt >> 1) * 4;

    for (int c = 0; c < 16; c++) {
        if (c < 15) {
            G2_LOAD(c + 1);
            CP_COMMIT();
            CP_WAIT(1);
        } else {
            CP_WAIT(0);
        }
        __syncthreads();

        const int s = c & 1;
        const uint32_t aB = smb + 4 * (s * G2_STAGE + (wo * 64 + fragRow) * G2_STR + fragCol);
        const uint32_t bB = smb + 4 * (s * G2_STAGE + 2560 + (wp * 32 + fragRow) * G2_STR + fragCol);
#pragma unroll
        for (int ks = 0; ks < 2; ks++) {
            uint32_t a[4][4];
            uint32_t bh[2][4];
#pragma unroll
            for (int nb = 0; nb < 2; nb++) {
                uint32_t ba = bB + 4 * (16 * nb * G2_STR + 8 * ks);
                LDSM4(bh[nb][0], bh[nb][1], bh[nb][2], bh[nb][3], ba);
            }
#pragma unroll
            for (int mf = 0; mf < 4; mf++) {
                uint32_t aa = aB + 4 * (16 * mf * G2_STR + 8 * ks);
                LDSM4(a[mf][0], a[mf][1], a[mf][2], a[mf][3], aa);
            }
#pragma unroll
            for (int nb = 0; nb < 2; nb++)
#pragma unroll
                for (int mf = 0; mf < 4; mf++) {
                    mma16816(acc[mf][2 * nb],     a[mf][0], a[mf][1], a[mf][2], a[mf][3], bh[nb][0], bh[nb][2]);
                    mma16816(acc[mf][2 * nb + 1], a[mf][0], a[mf][1], a[mf][2], a[mf][3], bh[nb][1], bh[nb][3]);
                }
        }
        __syncthreads();
    }

    // ---- store y as fp16 pairs + fused per-channel stats ----
    unsigned* Yh = &g_yh[proj][b][0][0];
    const int pp2 = (p0 >> 1) + wp * 16 + q;
#pragma unroll
    for (int mf = 0; mf < 4; mf++) {
        int oo = o0 + wo * 64 + 16 * mf + g;
#pragma unroll
        for (int nf = 0; nf < 4; nf++) {
            Yh[(size_t)oo * 1024 + pp2 + 4 * nf] = pack2h(acc[mf][nf][0], acc[mf][nf][1]);
            Yh[(size_t)(oo + 8) * 1024 + pp2 + 4 * nf] = pack2h(acc[mf][nf][2], acc[mf][nf][3]);
        }
    }
#pragma unroll
    for (int mf = 0; mf < 4; mf++) {
#pragma unroll
        for (int half = 0; half < 2; half++) {
            float s = 0.f, s2 = 0.f;
#pragma unroll
            for (int nf = 0; nf < 4; nf++) {
                float v0 = acc[mf][nf][2 * half], v1 = acc[mf][nf][2 * half + 1];
                s += v0 + v1;
                s2 += v0 * v0 + v1 * v1;
            }
            s += __shfl_xor_sync(0xffffffffu, s, 1);
            s += __shfl_xor_sync(0xffffffffu, s, 2);
            s2 += __shfl_xor_sync(0xffffffffu, s2, 1);
            s2 += __shfl_xor_sync(0xffffffffu, s2, 2);
            if (q == 0) {
                int o = o0 + wo * 64 + 16 * mf + g + 8 * half;
                atomicAdd(&g_sum[proj][o], s);
                atomicAdd(&g_sumsq[proj][o], s2);
            }
        }
    }
}

// ---------------- Stage 2: finalize stats -> folded affine ----------------
__global__ __launch_bounds__(256) void finalize_stats_kernel(
    const float* __restrict__ gq, const float* __restrict__ bq,
    const float* __restrict__ gk, const float* __restrict__ bk,
    const float* __restrict__ gv, const float* __restrict__ bv)
{
    int idx = blockIdx.x * 256 + threadIdx.x;
    int proj = idx >> 10, o = idx & 1023;
    const float invn = 1.f / (BB * PP);
    float mean = g_sum[proj][o] * invn;
    float var = g_sumsq[proj][o] * invn - mean * mean;
    const float* gg = (proj == 0) ? gq : ((proj == 1) ? gk : gv);
    const float* be = (proj == 0) ? bq : ((proj == 1) ? bk : bv);
    float sc = gg[o] * rsqrtf(var + 1e-5f);
    g_scale[proj][o] = sc;
    g_shift[proj][o] = be[o] - mean * sc;
}

// ---------------- Stage 3: fold BN+LeakyReLU from fp16 y ----------------
__global__ __launch_bounds__(256) void fold2_kernel()
{
    int p0 = blockIdx.x * 64, c0 = blockIdx.y * 64;
    int z = blockIdx.z, proj = z >> 3, b = z & 7;
    int tid = threadIdx.x;

    if (proj == 0) {
        for (int t = tid; t < 64 * 32; t += 256) {
            int c = c0 + (t >> 5), jp = (p0 >> 1) + (t & 31);
            float2 v = unpack2h(g_yh[0][b][c][jp]);
            float sc = g_scale[0][c], sh = g_shift[0][c];
            float v0 = v.x * sc + sh, v1 = v.y * sc + sh;
            v0 = (v0 >= 0.f) ? v0 : 0.1f * v0;
            v1 = (v1 >= 0.f) ? v1 : 0.1f * v1;
            g_Q[b][c][jp] = pack2h(v0, v1);
        }
        return;
    }

    __shared__ float sm[64][65];
    const float post = (proj == 1) ? K_ALPHA : 1.f;
    for (int t = tid; t < 64 * 32; t += 256) {
        int c = t >> 5, jp = t & 31;
        float2 v = unpack2h(g_yh[proj][b][c0 + c][(p0 >> 1) + jp]);
        float sc = g_scale[proj][c0 + c], sh = g_shift[proj][c0 + c];
        float v0 = v.x * sc + sh, v1 = v.y * sc + sh;
        v0 = ((v0 >= 0.f) ? v0 : 0.1f * v0) * post;
        v1 = ((v1 >= 0.f) ? v1 : 0.1f * v1) * post;
        sm[c][2 * jp] = v0;
        sm[c][2 * jp + 1] = v1;
    }
    __syncthreads();
    int h = c0 >> 7, cpo = (c0 & 127) >> 1;
    unsigned* dst = (proj == 1) ? &g_KT[0][0][0][0] : &g_VT[0][0][0][0];
    for (int t = tid; t < 64 * 32; t += 256) {
        int p = t >> 5, cp = t & 31;
        size_t o = ((size_t)(b * NH + h) * PP + p0 + p) * 64 + cpo + cp;
        dst[o] = pack2h(sm[2 * cp][p], sm[2 * cp + 1][p]);
    }
}

// ---------------- Stage 4: fp16 flash attention, P-in-registers -----------
// smem (u32): V 0 (2 bufs x 4352)   [prologue stages K (8704 u32) at 0]
//             Q 8704 (2 bufs x 4608)
// Iter jt: S(jt+1)->sacc_new, softmax(sacc_old)->P regs, O^T(jt) += P * Q.
// O^T[i][c]: warp w owns i rows 16w..16w+15; P is the MMA A-operand (regs).
#define OFF_V  0
#define OFF_Q  8704
#define ATTN9_SMEM ((8704 + 2 * 4608) * 4)

__global__ __launch_bounds__(256) void attn9_kernel(float* __restrict__ out)
{
    extern __shared__ unsigned sm[];
    uint32_t smb = (uint32_t)__cvta_generic_to_shared(sm);
    const int tid = threadIdx.x;
    const int w = tid >> 5, lane = tid & 31;
    const int g = lane >> 2, q = lane & 3;
    const int tt = lane >> 3, rr = lane & 7;
    const int bh = blockIdx.y, b = bh >> 3, h = bh & 7;
    const int i0 = blockIdx.x * 128;

    const unsigned* gK = &g_KT[b][h][0][0];
    const unsigned* gV = &g_VT[b][h][0][0];
    const unsigned* gQ = &g_Q[b][h * 128][0];

    const int aRow = 16 * w + (tt & 1) * 8 + rr;
    const int aCol = (tt >> 1) * 4;
    const int bRow0 = (tt & 1) * 8 + rr;

    // ---- prologue: stage K through smem, extract A-fragments to regs ----
    for (int t = tid; t < 2048; t += 256) {
        int r = t >> 4, f4 = (t & 15) * 4;
        CP16(smb + 4 * (r * 68 + f4), gK + (size_t)(i0 + r) * 64 + f4);
    }
    CP_COMMIT();
    CP_WAIT(0);
    __syncthreads();

    unsigned kh[8][4];
    {
        const uint32_t kB = smb + 4 * (aRow * 68 + aCol);
#pragma unroll
        for (int ks = 0; ks < 8; ks++)
            LDSM4(kh[ks][0], kh[ks][1], kh[ks][2], kh[ks][3], kB + 32 * ks);
    }
    __syncthreads();

    // V(0) -> buf0
    for (int t = tid; t < 1024; t += 256) {
        int r = t >> 4, f4 = (t & 15) * 4;
        CP16(smb + 4 * (OFF_V + r * 68 + f4), gV + (size_t)r * 64 + f4);
    }
    CP_COMMIT();
    // V(1) -> buf1, Q(0) -> qbuf0
    for (int t = tid; t < 1024; t += 256) {
        int r = t >> 4, f4 = (t & 15) * 4;
        CP16(smb + 4 * (OFF_V + 4352 + r * 68 + f4), gV + (size_t)(64 + r) * 64 + f4);
    }
    for (int t = tid; t < 1024; t += 256) {
        int r = t >> 3, f4 = (t & 7) * 4;
        CP16(smb + 4 * (OFF_Q + r * 36 + f4), gQ + (size_t)r * 1024 + f4);
    }
    CP_COMMIT();

    // O^T accumulators: oacc[nf] covers c = 8nf + {2q, 2q+1}, rows g / g+8
    float oacc[16][4];
#pragma unroll
    for (int nf = 0; nf < 16; nf++)
#pragma unroll
        for (int e = 0; e < 4; e++) oacc[nf][e] = 0.f;
    float l0 = 0.f, l1 = 0.f;
    float saccA[8][4], saccB[8][4];

    // ---- prologue S(0) -> saccA ----
    CP_WAIT(1);
    __syncthreads();
#pragma unroll
    for (int nf = 0; nf < 8; nf++)
#pragma unroll
        for (int e = 0; e < 4; e++) saccA[nf][e] = 0.f;
    {
        const uint32_t vBase = smb + 4 * (OFF_V + bRow0 * 68 + aCol);
#pragma unroll
        for (int ks = 0; ks < 8; ks++) {
#pragma unroll
            for (int nb = 0; nb < 4; nb++) {
                uint32_t vh0, vh1, vh2, vh3;
                LDSM4(vh0, vh1, vh2, vh3, vBase + 4 * (nb * 16 * 68) + 32 * ks);
                mma16816(saccA[2 * nb],     kh[ks][0], kh[ks][1], kh[ks][2], kh[ks][3], vh0, vh2);
                mma16816(saccA[2 * nb + 1], kh[ks][0], kh[ks][1], kh[ks][2], kh[ks][3], vh1, vh3);
            }
        }
    }

#define ATTN_ITER(jt, sO, sN) do { \
        const int qb = (jt) & 1; \
        CP_WAIT(0); \
        __syncthreads(); \
        if ((jt) < 30) { \
            const int jn2 = ((jt) + 2) * 64; \
            for (int t = tid; t < 1024; t += 256) { \
                int r = t >> 4, f4 = (t & 15) * 4; \
                CP16(smb + 4 * (OFF_V + qb * 4352 + r * 68 + f4), \
                     gV + (size_t)(jn2 + r) * 64 + f4); \
            } \
        } \
        if ((jt) < 31) { \
            const int jn = ((jt) + 1) * 64; \
            for (int t = tid; t < 1024; t += 256) { \
                int r = t >> 3, f4 = (t & 7) * 4; \
                CP16(smb + 4 * (OFF_Q + (qb ^ 1) * 4608 + r * 36 + f4), \
                     gQ + (size_t)r * 1024 + (jn >> 1) + f4); \
            } \
            CP_COMMIT(); \
        } \
        if ((jt) < 31) { \
            _Pragma("unroll") \
            for (int nf = 0; nf < 8; nf++) \
                _Pragma("unroll") \
                for (int e = 0; e < 4; e++) sN[nf][e] = 0.f; \
            const uint32_t vBase = smb + 4 * (OFF_V + (qb ^ 1) * 4352 + bRow0 * 68 + aCol); \
            _Pragma("unroll") \
            for (int ks = 0; ks < 8; ks++) { \
                _Pragma("unroll") \
                for (int nb = 0; nb < 4; nb++) { \
                    uint32_t vh0, vh1, vh2, vh3; \
                    LDSM4(vh0, vh1, vh2, vh3, vBase + 4 * (nb * 16 * 68) + 32 * ks); \
                    mma16816(sN[2 * nb],     kh[ks][0], kh[ks][1], kh[ks][2], kh[ks][3], vh0, vh2); \
                    mma16816(sN[2 * nb + 1], kh[ks][0], kh[ks][1], kh[ks][2], kh[ks][3], vh1, vh3); \
                } \
            } \
        } \
        unsigned pa[8], pb[8]; \
        _Pragma("unroll") \
        for (int nf = 0; nf < 8; nf++) { \
            float e0 = fex2(sO[nf][0]); \
            float e1 = fex2(sO[nf][1]); \
            float e2 = fex2(sO[nf][2]); \
            float e3 = fex2(sO[nf][3]); \
            l0 += e0 + e1; \
            l1 += e2 + e3; \
            pa[nf] = pack2h(e0, e1); \
            pb[nf] = pack2h(e2, e3); \
        } \
        const uint32_t qBase = smb + 4 * (OFF_Q + qb * 4608 + bRow0 * 36 + aCol); \
        _Pragma("unroll") \
        for (int ks = 0; ks < 4; ks++) { \
            _Pragma("unroll") \
            for (int cb = 0; cb < 8; cb++) { \
                uint32_t qh0, qh1, qh2, qh3; \
                LDSM4(qh0, qh1, qh2, qh3, qBase + 4 * (16 * cb * 36) + 32 * ks); \
                mma16816(oacc[2 * cb],     pa[2 * ks], pb[2 * ks], pa[2 * ks + 1], pb[2 * ks + 1], qh0, qh2); \
                mma16816(oacc[2 * cb + 1], pa[2 * ks], pb[2 * ks], pa[2 * ks + 1], pb[2 * ks + 1], qh1, qh3); \
            } \
        } \
    } while (0)

    for (int jt = 0; jt < 32; jt += 2) {
        ATTN_ITER(jt,     saccA, saccB);
        ATTN_ITER(jt + 1, saccB, saccA);
    }
#undef ATTN_ITER

    // ---- finalize: thread owns exactly rows i = 16w+g (l0), 16w+g+8 (l1) ----
    l0 += __shfl_xor_sync(0xffffffffu, l0, 1);
    l0 += __shfl_xor_sync(0xffffffffu, l0, 2);
    l1 += __shfl_xor_sync(0xffffffffu, l1, 1);
    l1 += __shfl_xor_sync(0xffffffffu, l1, 2);
    float il0 = 1.f / l0, il1 = 1.f / l1;
    const int iA = i0 + 16 * w + g;
#pragma unroll
    for (int nf = 0; nf < 16; nf++) {
        int c = h * 128 + 8 * nf + 2 * q;
        float* r0 = out + ((size_t)b * COUT + c) * PP;
        float* r1 = out + ((size_t)b * COUT + c + 1) * PP;
        r0[iA] = oacc[nf][0] * il0;
        r1[iA] = oacc[nf][1] * il0;
        r0[iA + 8] = oacc[nf][2] * il1;
        r1[iA + 8] = oacc[nf][3] * il1;
    }
}

// ---------------------------------------------------------------------------
extern "C" void kernel_launch(void* const* d_in, const int* in_sizes, int n_in,
                              void* d_out, int out_size)
{
    const float* x  = (const float*)d_in[0];
    const float* Wq = (const float*)d_in[1];
    const float* gq = (const float*)d_in[2];
    const float* bq = (const float*)d_in[3];
    const float* Wk = (const float*)d_in[4];
    const float* gk = (const float*)d_in[5];
    const float* bk = (const float*)d_in[6];
    const float* Wv = (const float*)d_in[7];
    const float* gv = (const float*)d_in[8];
    const float* bv = (const float*)d_in[9];
    float* out = (float*)d_out;

    conv_w_kernel<<<3 * COUT * (CIN / 2) / 256, 256>>>(Wq, Wk, Wv);
    conv_x_kernel<<<dim3(PP / 64, CIN / 64, BB), 256>>>(x);

    cudaFuncSetAttribute(gemm1c_kernel, cudaFuncAttributeMaxDynamicSharedMemorySize, G2_SMEM);
    gemm1c_kernel<<<dim3(PP / 128, COUT / 128, 3 * BB), 256, G2_SMEM>>>();

    finalize_stats_kernel<<<12, 256>>>(gq, bq, gk, bk, gv, bv);
    fold2_kernel<<<dim3(PP / 64, COUT / 64, 3 * BB), 256>>>();

    cudaFuncSetAttribute(attn9_kernel, cudaFuncAttributeMaxDynamicSharedMemorySize, ATTN9_SMEM);
    attn9_kernel<<<dim3(PP / 128, BB * NH), 256, ATTN9_SMEM>>>(out);
}